// round 9
// baseline (speedup 1.0000x reference)
#include <cuda_runtime.h>
#include <cuda_bf16.h>
#include <cuda_fp16.h>
#include <math.h>
#include <stdint.h>

#define B_   8192
#define DIN  1024
#define HID  2048
#define LAT  256
#define KC   4096

typedef unsigned long long ull;

// ---------------- scratch (device globals; no allocation allowed) ----------
__device__ __align__(128) float g_h1[(size_t)B_ * HID];   // enc h1 splits / dec h1 splits
__device__ __align__(128) float g_h2[(size_t)B_ * HID];   // enc h2 splits / dec h2 splits
__device__ __align__(128) float g_ze[(size_t)B_ * LAT];
__device__ float g_zsq[B_];
__device__ float g_esq[KC];
__device__ float g_rowloss[B_];
__device__ int   g_idx[B_];
// decoder presplit (bf16x2 k-pairs)
__device__ __align__(128) uint32_t g_zqh[(size_t)B_ * (LAT/2)];
__device__ __align__(128) uint32_t g_zql[(size_t)B_ * (LAT/2)];
__device__ __align__(128) uint32_t g_d1h[(size_t)HID * (LAT/2)];
__device__ __align__(128) uint32_t g_d1l[(size_t)HID * (LAT/2)];
__device__ __align__(128) uint32_t g_d2h[(size_t)HID * (HID/2)];
__device__ __align__(128) uint32_t g_d2l[(size_t)HID * (HID/2)];
__device__ __align__(128) uint32_t g_d3h[(size_t)DIN * (HID/2)];
__device__ __align__(128) uint32_t g_d3l[(size_t)DIN * (HID/2)];
// encoder presplit (fp16x2 k-pairs)
__device__ __align__(128) uint32_t g_xh[(size_t)B_ * (DIN/2)];
__device__ __align__(128) uint32_t g_xl[(size_t)B_ * (DIN/2)];
__device__ __align__(128) uint32_t g_w1h[(size_t)HID * (DIN/2)];
__device__ __align__(128) uint32_t g_w1l[(size_t)HID * (DIN/2)];
__device__ __align__(128) uint32_t g_w2h[(size_t)HID * (HID/2)];
__device__ __align__(128) uint32_t g_w2l[(size_t)HID * (HID/2)];
__device__ __align__(128) uint32_t g_w3h[(size_t)LAT * (HID/2)];
__device__ __align__(128) uint32_t g_w3l[(size_t)LAT * (HID/2)];

__device__ __forceinline__ float gelu_exact(float x) {
    return 0.5f * x * (1.0f + erff(x * 0.7071067811865476f));
}

// packed fp32x2 FMA (dist kernel)
__device__ __forceinline__ void fma2(ull& d, ull a, ull b, ull c) {
    asm("fma.rn.f32x2 %0, %1, %2, %3;" : "=l"(d) : "l"(a), "l"(b), "l"(c));
}
__device__ __forceinline__ ull pack2(float lo, float hi) {
    ull r;
    asm("mov.b64 %0, {%1, %2};" : "=l"(r) : "f"(lo), "f"(hi));
    return r;
}
__device__ __forceinline__ void unpack2(ull v, float& lo, float& hi) {
    asm("mov.b64 {%0, %1}, %2;" : "=f"(lo), "=f"(hi) : "l"(v));
}

// ---- bf16 split (decoder path; unchanged values) ----
__device__ __forceinline__ uint32_t pack2bf(__nv_bfloat16 a, __nv_bfloat16 b) {
    __nv_bfloat162 v(a, b);
    return *reinterpret_cast<uint32_t*>(&v);
}
__device__ __forceinline__ void split_bf(float x, __nv_bfloat16& h, __nv_bfloat16& l) {
    h = __float2bfloat16_rn(x);
    l = __float2bfloat16_rn(x - __bfloat162float(h));
}
__device__ __forceinline__ uint32_t split_pair_hi(float x0, float x1) {
    __nv_bfloat16 h0, l0, h1, l1;
    split_bf(x0, h0, l0); split_bf(x1, h1, l1);
    return pack2bf(h0, h1);
}
__device__ __forceinline__ uint32_t split_pair_lo(float x0, float x1) {
    __nv_bfloat16 h0, l0, h1, l1;
    split_bf(x0, h0, l0); split_bf(x1, h1, l1);
    return pack2bf(l0, l1);
}

// ---- fp16 split (encoder path; residual ~2^-22) ----
__device__ __forceinline__ uint32_t pack2hf(__half a, __half b) {
    __half2 v = __halves2half2(a, b);
    return *reinterpret_cast<uint32_t*>(&v);
}
__device__ __forceinline__ void split_hf(float x, __half& h, __half& l) {
    h = __float2half_rn(x);
    l = __float2half_rn(x - __half2float(h));
}
__device__ __forceinline__ uint32_t split_pair_hi_hf(float x0, float x1) {
    __half h0, l0, h1, l1;
    split_hf(x0, h0, l0); split_hf(x1, h1, l1);
    return pack2hf(h0, h1);
}
__device__ __forceinline__ uint32_t split_pair_lo_hf(float x0, float x1) {
    __half h0, l0, h1, l1;
    split_hf(x0, h0, l0); split_hf(x1, h1, l1);
    return pack2hf(l0, l1);
}

// ---- warp MMAs ----
__device__ __forceinline__ void mma16b(float* d, const uint32_t* a, const uint32_t* b) {
    asm("mma.sync.aligned.m16n8k16.row.col.f32.bf16.bf16.f32 "
        "{%0,%1,%2,%3}, {%4,%5,%6,%7}, {%8,%9}, {%0,%1,%2,%3};"
        : "+f"(d[0]), "+f"(d[1]), "+f"(d[2]), "+f"(d[3])
        : "r"(a[0]), "r"(a[1]), "r"(a[2]), "r"(a[3]), "r"(b[0]), "r"(b[1]));
}
__device__ __forceinline__ void mma16h(float* d, const uint32_t* a, const uint32_t* b) {
    asm("mma.sync.aligned.m16n8k16.row.col.f32.f16.f16.f32 "
        "{%0,%1,%2,%3}, {%4,%5,%6,%7}, {%8,%9}, {%0,%1,%2,%3};"
        : "+f"(d[0]), "+f"(d[1]), "+f"(d[2]), "+f"(d[3])
        : "r"(a[0]), "r"(a[1]), "r"(a[2]), "r"(a[3]), "r"(b[0]), "r"(b[1]));
}

// ================= presplit 3-term MMA GEMM =================================
// A: [M][K/2] u32 hi/lo k-pairs, B: [N][K/2] u32 hi/lo.
// BF=1: bf16 MMA + bf16 split output. BF=0: fp16 MMA + fp16 split output.
// MODE 0: fp32 out (bias, no gelu). MODE 1: bias+gelu, split out [M][N/2].
#define LDA 20   // u32 row stride (16 kp + 4 pad)

template<int MODE, int BF>
__global__ void __launch_bounds__(256) mmaps_gemm(
    const uint32_t* __restrict__ Ah_g, const uint32_t* __restrict__ Al_g,
    const uint32_t* __restrict__ Bh_g, const uint32_t* __restrict__ Bl_g,
    const float* __restrict__ bias, float* __restrict__ C,
    uint32_t* __restrict__ Oh, uint32_t* __restrict__ Ol,
    int M, int N, int K)
{
    __shared__ uint32_t Ah[128 * LDA], Al[128 * LDA];
    __shared__ uint32_t Bh[128 * LDA], Bl[128 * LDA];

    const int tid  = threadIdx.x;
    const int wid  = tid >> 5;
    const int lane = tid & 31;
    const int g = lane >> 2;
    const int t = lane & 3;
    const int warp_m = wid & 1;
    const int warp_n = wid >> 1;
    const int bm = blockIdx.y * 128;
    const int bn = blockIdx.x * 128;
    const int Kp = K >> 1;

    float acc[4][4][4];
#pragma unroll
    for (int i = 0; i < 4; i++)
#pragma unroll
        for (int j = 0; j < 4; j++)
#pragma unroll
            for (int r = 0; r < 4; r++) acc[i][j][r] = 0.0f;

    const int fr = tid >> 1;
    const int fo = (tid & 1) * 8;
    const uint32_t* pAh = Ah_g + (size_t)(bm + fr) * Kp + fo;
    const uint32_t* pAl = Al_g + (size_t)(bm + fr) * Kp + fo;
    const uint32_t* pBh = Bh_g + (size_t)(bn + fr) * Kp + fo;
    const uint32_t* pBl = Bl_g + (size_t)(bn + fr) * Kp + fo;

    uint4 vah[2], val_[2], vbh[2], vbl[2];
#pragma unroll
    for (int q = 0; q < 2; q++) {
        vah[q]  = *(const uint4*)(pAh + q * 4);
        val_[q] = *(const uint4*)(pAl + q * 4);
        vbh[q]  = *(const uint4*)(pBh + q * 4);
        vbl[q]  = *(const uint4*)(pBl + q * 4);
    }

    const int nt = K / 32;
    for (int kt = 0; kt < nt; kt++) {
#pragma unroll
        for (int q = 0; q < 2; q++) {
            *(uint4*)&Ah[fr * LDA + fo + q * 4] = vah[q];
            *(uint4*)&Al[fr * LDA + fo + q * 4] = val_[q];
            *(uint4*)&Bh[fr * LDA + fo + q * 4] = vbh[q];
            *(uint4*)&Bl[fr * LDA + fo + q * 4] = vbl[q];
        }
        __syncthreads();

        if (kt + 1 < nt) {
            const int off = (kt + 1) * 16;
#pragma unroll
            for (int q = 0; q < 2; q++) {
                vah[q]  = *(const uint4*)(pAh + off + q * 4);
                val_[q] = *(const uint4*)(pAl + off + q * 4);
                vbh[q]  = *(const uint4*)(pBh + off + q * 4);
                vbl[q]  = *(const uint4*)(pBl + off + q * 4);
            }
        }

#pragma unroll
        for (int kk = 0; kk < 2; kk++) {
            const int ko = kk * 8;
            uint32_t ah[4][4], al[4][4], bh[4][2], bl[4][2];
#pragma unroll
            for (int im = 0; im < 4; im++) {
                int row = warp_m * 64 + im * 16 + g;
                int base = row * LDA + ko;
                ah[im][0] = Ah[base + t];
                ah[im][1] = Ah[base + 8 * LDA + t];
                ah[im][2] = Ah[base + t + 4];
                ah[im][3] = Ah[base + 8 * LDA + t + 4];
                al[im][0] = Al[base + t];
                al[im][1] = Al[base + 8 * LDA + t];
                al[im][2] = Al[base + t + 4];
                al[im][3] = Al[base + 8 * LDA + t + 4];
            }
#pragma unroll
            for (int jn = 0; jn < 4; jn++) {
                int n = warp_n * 32 + jn * 8 + g;
                int base = n * LDA + ko;
                bh[jn][0] = Bh[base + t];
                bh[jn][1] = Bh[base + t + 4];
                bl[jn][0] = Bl[base + t];
                bl[jn][1] = Bl[base + t + 4];
            }
#pragma unroll
            for (int im = 0; im < 4; im++)
#pragma unroll
                for (int jn = 0; jn < 4; jn++) {
                    if (BF) {
                        mma16b(acc[im][jn], al[im], bh[jn]);
                        mma16b(acc[im][jn], ah[im], bl[jn]);
                        mma16b(acc[im][jn], ah[im], bh[jn]);
                    } else {
                        mma16h(acc[im][jn], al[im], bh[jn]);
                        mma16h(acc[im][jn], ah[im], bl[jn]);
                        mma16h(acc[im][jn], ah[im], bh[jn]);
                    }
                }
        }
        __syncthreads();
    }

    // epilogue
#pragma unroll
    for (int im = 0; im < 4; im++) {
#pragma unroll
        for (int jn = 0; jn < 4; jn++) {
            int row = bm + warp_m * 64 + im * 16 + g;
            int col = bn + warp_n * 32 + jn * 8 + 2 * t;
            float bx = bias[col], by = bias[col + 1];
            float2 v0, v1;
            v0.x = acc[im][jn][0] + bx;
            v0.y = acc[im][jn][1] + by;
            v1.x = acc[im][jn][2] + bx;
            v1.y = acc[im][jn][3] + by;
            if (MODE == 1) {
                v0.x = gelu_exact(v0.x); v0.y = gelu_exact(v0.y);
                v1.x = gelu_exact(v1.x); v1.y = gelu_exact(v1.y);
                size_t o0 = (size_t)row * (N >> 1) + (col >> 1);
                size_t o1 = (size_t)(row + 8) * (N >> 1) + (col >> 1);
                if (BF) {
                    Oh[o0] = split_pair_hi(v0.x, v0.y);
                    Ol[o0] = split_pair_lo(v0.x, v0.y);
                    Oh[o1] = split_pair_hi(v1.x, v1.y);
                    Ol[o1] = split_pair_lo(v1.x, v1.y);
                } else {
                    Oh[o0] = split_pair_hi_hf(v0.x, v0.y);
                    Ol[o0] = split_pair_lo_hf(v0.x, v0.y);
                    Oh[o1] = split_pair_hi_hf(v1.x, v1.y);
                    Ol[o1] = split_pair_lo_hf(v1.x, v1.y);
                }
            } else {
                *(float2*)&C[(size_t)row * N + col] = v0;
                *(float2*)&C[(size_t)(row + 8) * N + col] = v1;
            }
        }
    }
}

// ================= weight transpose-split prep (bf16 & fp16) ================
__global__ void wsplit_kernel(const float* __restrict__ B, int K, int N,
                              uint32_t* __restrict__ Oh, uint32_t* __restrict__ Ol)
{
    __shared__ float t[64][33];
    const int n0 = blockIdx.x * 32;
    const int k0 = blockIdx.y * 64;
    const int tid = threadIdx.x;
#pragma unroll
    for (int i = 0; i < 8; i++) {
        int idx = tid + i * 256;
        int kk = idx >> 5, nn = idx & 31;
        t[kk][nn] = B[(size_t)(k0 + kk) * N + n0 + nn];
    }
    __syncthreads();
    const int Kp = K >> 1;
#pragma unroll
    for (int i = 0; i < 4; i++) {
        int idx = tid + i * 256;
        int nn = idx >> 5, kp = idx & 31;
        float x0 = t[2 * kp][nn], x1 = t[2 * kp + 1][nn];
        size_t o = (size_t)(n0 + nn) * Kp + (k0 >> 1) + kp;
        Oh[o] = split_pair_hi(x0, x1);
        Ol[o] = split_pair_lo(x0, x1);
    }
}

__global__ void wsplit_h_kernel(const float* __restrict__ B, int K, int N,
                                uint32_t* __restrict__ Oh, uint32_t* __restrict__ Ol)
{
    __shared__ float t[64][33];
    const int n0 = blockIdx.x * 32;
    const int k0 = blockIdx.y * 64;
    const int tid = threadIdx.x;
#pragma unroll
    for (int i = 0; i < 8; i++) {
        int idx = tid + i * 256;
        int kk = idx >> 5, nn = idx & 31;
        t[kk][nn] = B[(size_t)(k0 + kk) * N + n0 + nn];
    }
    __syncthreads();
    const int Kp = K >> 1;
#pragma unroll
    for (int i = 0; i < 4; i++) {
        int idx = tid + i * 256;
        int nn = idx >> 5, kp = idx & 31;
        float x0 = t[2 * kp][nn], x1 = t[2 * kp + 1][nn];
        size_t o = (size_t)(n0 + nn) * Kp + (k0 >> 1) + kp;
        Oh[o] = split_pair_hi_hf(x0, x1);
        Ol[o] = split_pair_lo_hf(x0, x1);
    }
}

// x row-major elementwise fp16 split
__global__ void xsplit_kernel(const float* __restrict__ X,
                              uint32_t* __restrict__ Oh, uint32_t* __restrict__ Ol,
                              int total_pairs)
{
    int idx = blockIdx.x * blockDim.x + threadIdx.x;
    if (idx >= total_pairs) return;
    float2 v = *(const float2*)(X + 2 * (size_t)idx);
    Oh[idx] = split_pair_hi_hf(v.x, v.y);
    Ol[idx] = split_pair_lo_hf(v.x, v.y);
}

// ---------------- per-row sum of squares (one warp per row) ----------------
__global__ void rowsumsq_kernel(const float* __restrict__ src,
                                float* __restrict__ out, int rows)
{
    int warp = (blockIdx.x * blockDim.x + threadIdx.x) >> 5;
    int lane = threadIdx.x & 31;
    if (warp >= rows) return;
    const float* p = src + (size_t)warp * LAT;
    float s = 0.0f;
#pragma unroll
    for (int i = 0; i < LAT; i += 32) {
        float v = p[i + lane];
        s = fmaf(v, v, s);
    }
#pragma unroll
    for (int o = 16; o; o >>= 1) s += __shfl_down_sync(0xffffffffu, s, o);
    if (lane == 0) out[warp] = s;
}

// ---------------- distance + argmin (unchanged structure) ------------------
__global__ void __launch_bounds__(256) dist_argmin_kernel(
    const float* __restrict__ embed)
{
    extern __shared__ float sm[];
    float* Es = sm;
    float* Zs = sm + 64 * 256;

    const int tid = threadIdx.x;
    const int tx = tid & 31;
    const int ty = tid >> 5;
    const int row0 = blockIdx.x * 64;

    float bestv[8];
    int   besti[8];
#pragma unroll
    for (int i = 0; i < 8; i++) { bestv[i] = INFINITY; besti[i] = 0; }

    float zs[8];
#pragma unroll
    for (int i = 0; i < 8; i++) zs[i] = g_zsq[row0 + ty * 8 + i];

    const int zr = tid & 63;
    const int zq = tid >> 6;

    for (int c0 = 0; c0 < KC; c0 += 256) {
        ull acc2[8][4];
#pragma unroll
        for (int i = 0; i < 8; i++)
#pragma unroll
            for (int j = 0; j < 4; j++) acc2[i][j] = 0ull;

        for (int ks = 0; ks < 256; ks += 64) {
            __syncthreads();
            {
                const float4* ep = (const float4*)(embed + (size_t)(c0 + tid) * LAT + ks);
#pragma unroll
                for (int q = 0; q < 16; q++) {
                    float4 v = ep[q];
                    Es[(4 * q + 0) * 256 + tid] = v.x;
                    Es[(4 * q + 1) * 256 + tid] = v.y;
                    Es[(4 * q + 2) * 256 + tid] = v.z;
                    Es[(4 * q + 3) * 256 + tid] = v.w;
                }
            }
            {
                const float4* zp = (const float4*)(g_ze + (size_t)(row0 + zr) * LAT + ks + zq * 16);
#pragma unroll
                for (int q = 0; q < 4; q++) {
                    float4 v = zp[q];
                    int kb = zq * 16 + 4 * q;
                    Zs[(kb + 0) * 64 + zr] = v.x;
                    Zs[(kb + 1) * 64 + zr] = v.y;
                    Zs[(kb + 2) * 64 + zr] = v.z;
                    Zs[(kb + 3) * 64 + zr] = v.w;
                }
            }
            __syncthreads();

            for (int k = 0; k < 64; k++) {
                float rz[8];
                *(float4*)(rz)     = *(const float4*)&Zs[k * 64 + ty * 8];
                *(float4*)(rz + 4) = *(const float4*)&Zs[k * 64 + ty * 8 + 4];
                ull re2[4];
                *(uint4*)&re2[0] = *(const uint4*)&Es[k * 256 + tx * 8];
                *(uint4*)&re2[2] = *(const uint4*)&Es[k * 256 + tx * 8 + 4];
#pragma unroll
                for (int i = 0; i < 8; i++) {
                    ull z2 = pack2(rz[i], rz[i]);
#pragma unroll
                    for (int j = 0; j < 4; j++)
                        fma2(acc2[i][j], z2, re2[j], acc2[i][j]);
                }
            }
        }

#pragma unroll
        for (int i = 0; i < 8; i++) {
            float dot[8];
            unpack2(acc2[i][0], dot[0], dot[1]);
            unpack2(acc2[i][1], dot[2], dot[3]);
            unpack2(acc2[i][2], dot[4], dot[5]);
            unpack2(acc2[i][3], dot[6], dot[7]);
#pragma unroll
            for (int j = 0; j < 8; j++) {
                int c = c0 + tx * 8 + j;
                float t1 = zs[i] + g_esq[c];
                float v  = fmaf(-2.0f, dot[j], t1);
                if (v < bestv[i] || (v == bestv[i] && c < besti[i])) {
                    bestv[i] = v; besti[i] = c;
                }
            }
        }
    }

    __syncthreads();
    float* sval = sm;
    int*   sidx = (int*)(sm + 64 * 32);
#pragma unroll
    for (int i = 0; i < 8; i++) {
        sval[(ty * 8 + i) * 32 + tx] = bestv[i];
        sidx[(ty * 8 + i) * 32 + tx] = besti[i];
    }
    __syncthreads();
    if (tid < 64) {
        float bv = INFINITY; int bi = 0x7fffffff;
        for (int tt = 0; tt < 32; tt++) {
            float v = sval[tid * 32 + tt];
            int   c = sidx[tid * 32 + tt];
            if (v < bv || (v == bv && c < bi)) { bv = v; bi = c; }
        }
        g_idx[row0 + tid] = bi;
    }
}

// ---------------- gather z_q (bf16 split), per-row loss, indices out -------
__global__ void gather_loss_kernel(const float* __restrict__ embed,
                                   float* __restrict__ out_f, int write_extra)
{
    int warp = (blockIdx.x * blockDim.x + threadIdx.x) >> 5;
    int lane = threadIdx.x & 31;
    if (warp >= B_) return;
    int idx = g_idx[warp];
    const float* ze = g_ze + (size_t)warp * LAT;
    const float* eq = embed + (size_t)idx * LAT;
    float s = 0.0f;
#pragma unroll
    for (int i = 0; i < LAT; i += 32) {
        float q = eq[i + lane];
        float z = ze[i + lane];
        float d = z - q;
        s = fmaf(d, d, s);
    }
#pragma unroll
    for (int o = 16; o; o >>= 1) s += __shfl_down_sync(0xffffffffu, s, o);
#pragma unroll
    for (int m = 0; m < LAT / 2; m += 32) {
        int kp = m + lane;
        float q0 = eq[2 * kp], q1 = eq[2 * kp + 1];
        g_zqh[(size_t)warp * (LAT / 2) + kp] = split_pair_hi(q0, q1);
        g_zql[(size_t)warp * (LAT / 2) + kp] = split_pair_lo(q0, q1);
    }
    if (lane == 0) {
        g_rowloss[warp] = s;
        if (write_extra)
            out_f[(size_t)B_ * DIN + 1 + warp] = (float)idx;
    }
}

// ---------------- final loss reduction --------------------------------------
__global__ void loss_final_kernel(float* __restrict__ out_f, int write_extra)
{
    __shared__ float sh[256];
    float s = 0.0f;
    for (int i = threadIdx.x; i < B_; i += 256) s += g_rowloss[i];
    sh[threadIdx.x] = s;
    __syncthreads();
    for (int o = 128; o; o >>= 1) {
        if (threadIdx.x < o) sh[threadIdx.x] += sh[threadIdx.x + o];
        __syncthreads();
    }
    if (threadIdx.x == 0 && write_extra) {
        out_f[(size_t)B_ * DIN] = 1.25f * sh[0] / (float)((size_t)B_ * LAT);
    }
}

// ---------------- launch ----------------------------------------------------
extern "C" void kernel_launch(void* const* d_in, const int* in_sizes, int n_in,
                              void* d_out, int out_size)
{
    const float* x     = (const float*)d_in[0];
    const float* W1    = (const float*)d_in[1];
    const float* b1    = (const float*)d_in[2];
    const float* W2    = (const float*)d_in[3];
    const float* b2    = (const float*)d_in[4];
    const float* W3    = (const float*)d_in[5];
    const float* b3    = (const float*)d_in[6];
    const float* embed = (const float*)d_in[7];
    const float* D1    = (const float*)d_in[8];
    const float* d1    = (const float*)d_in[9];
    const float* D2    = (const float*)d_in[10];
    const float* d2    = (const float*)d_in[11];
    const float* D3    = (const float*)d_in[12];
    const float* d3    = (const float*)d_in[13];
    float* out = (float*)d_out;

    float *h1, *h2, *ze, *zsq, *esq;
    uint32_t *zqh, *zql, *d1h, *d1l, *d2h, *d2l, *d3h, *d3l;
    uint32_t *xh, *xl, *w1h, *w1l, *w2h, *w2l, *w3h, *w3l;
    cudaGetSymbolAddress((void**)&h1,  g_h1);
    cudaGetSymbolAddress((void**)&h2,  g_h2);
    cudaGetSymbolAddress((void**)&ze,  g_ze);
    cudaGetSymbolAddress((void**)&zsq, g_zsq);
    cudaGetSymbolAddress((void**)&esq, g_esq);
    cudaGetSymbolAddress((void**)&zqh, g_zqh);
    cudaGetSymbolAddress((void**)&zql, g_zql);
    cudaGetSymbolAddress((void**)&d1h, g_d1h);
    cudaGetSymbolAddress((void**)&d1l, g_d1l);
    cudaGetSymbolAddress((void**)&d2h, g_d2h);
    cudaGetSymbolAddress((void**)&d2l, g_d2l);
    cudaGetSymbolAddress((void**)&d3h, g_d3h);
    cudaGetSymbolAddress((void**)&d3l, g_d3l);
    cudaGetSymbolAddress((void**)&xh,  g_xh);
    cudaGetSymbolAddress((void**)&xl,  g_xl);
    cudaGetSymbolAddress((void**)&w1h, g_w1h);
    cudaGetSymbolAddress((void**)&w1l, g_w1l);
    cudaGetSymbolAddress((void**)&w2h, g_w2h);
    cudaGetSymbolAddress((void**)&w2l, g_w2l);
    cudaGetSymbolAddress((void**)&w3h, g_w3h);
    cudaGetSymbolAddress((void**)&w3l, g_w3l);

    // encoder h splits (fp16) and decoder h splits (bf16) share scratch
    uint32_t* h1h = (uint32_t*)h1;
    uint32_t* h1l = h1h + (size_t)B_ * (HID / 2);
    uint32_t* h2h = (uint32_t*)h2;
    uint32_t* h2l = h2h + (size_t)B_ * (HID / 2);

    const int write_extra =
        ((size_t)out_size >= (size_t)B_ * DIN + 1 + B_) ? 1 : 0;

    // presplit: x and encoder weights (fp16), decoder weights (bf16)
    xsplit_kernel<<<(B_ * (DIN / 2)) / 256, 256>>>(x, xh, xl, B_ * (DIN / 2));
    wsplit_h_kernel<<<dim3(HID / 32, DIN / 64), 256>>>(W1, DIN, HID, w1h, w1l);
    wsplit_h_kernel<<<dim3(HID / 32, HID / 64), 256>>>(W2, HID, HID, w2h, w2l);
    wsplit_h_kernel<<<dim3(LAT / 32, HID / 64), 256>>>(W3, HID, LAT, w3h, w3l);
    wsplit_kernel<<<dim3(HID / 32, LAT / 64), 256>>>(D1, LAT, HID, d1h, d1l);
    wsplit_kernel<<<dim3(HID / 32, HID / 64), 256>>>(D2, HID, HID, d2h, d2l);
    wsplit_kernel<<<dim3(DIN / 32, HID / 64), 256>>>(D3, HID, DIN, d3h, d3l);

    // encoder — fp16 2-way-split 3-term MMA (error ~5e-7, below fp32 reorder noise)
    {
        dim3 g(HID / 128, B_ / 128);
        mmaps_gemm<1, 0><<<g, 256>>>(xh, xl, w1h, w1l, b1, nullptr,
                                     h1h, h1l, B_, HID, DIN);
    }
    {
        dim3 g(HID / 128, B_ / 128);
        mmaps_gemm<1, 0><<<g, 256>>>(h1h, h1l, w2h, w2l, b2, nullptr,
                                     h2h, h2l, B_, HID, HID);
    }
    {
        dim3 g(LAT / 128, B_ / 128);
        mmaps_gemm<0, 0><<<g, 256>>>(h2h, h2l, w3h, w3l, b3, ze,
                                     nullptr, nullptr, B_, LAT, HID);
    }

    // norms
    rowsumsq_kernel<<<(B_ * 32) / 256, 256>>>(ze, zsq, B_);
    rowsumsq_kernel<<<(KC * 32) / 256, 256>>>(embed, esq, KC);

    // distance + argmin
    {
        int smem = (64 * 256 + 64 * 64) * (int)sizeof(float);  // 80 KB
        cudaFuncSetAttribute(dist_argmin_kernel,
                             cudaFuncAttributeMaxDynamicSharedMemorySize, smem);
        dist_argmin_kernel<<<B_ / 64, 256, smem>>>(embed);
    }

    // gather (+ zq bf16 split) + loss
    gather_loss_kernel<<<(B_ * 32) / 256, 256>>>(embed, out, write_extra);
    loss_final_kernel<<<1, 256>>>(out, write_extra);

    // decoder — bf16 3-term MMA (unchanged from Round 7)
    {
        dim3 g(HID / 128, B_ / 128);
        mmaps_gemm<1, 1><<<g, 256>>>(zqh, zql, d1h, d1l, d1, nullptr,
                                     h1h, h1l, B_, HID, LAT);
    }
    {
        dim3 g(HID / 128, B_ / 128);
        mmaps_gemm<1, 1><<<g, 256>>>(h1h, h1l, d2h, d2l, d2, nullptr,
                                     h2h, h2l, B_, HID, HID);
    }
    {
        dim3 g(DIN / 128, B_ / 128);
        mmaps_gemm<0, 1><<<g, 256>>>(h2h, h2l, d3h, d3l, d3, out,
                                     nullptr, nullptr, B_, DIN, HID);
    }
}

// round 10
// speedup vs baseline: 1.5321x; 1.5321x over previous
#include <cuda_runtime.h>
#include <cuda_bf16.h>
#include <cuda_fp16.h>
#include <math.h>
#include <stdint.h>

#define B_   8192
#define DIN  1024
#define HID  2048
#define LAT  256
#define KC   4096

typedef unsigned long long ull;

// ---------------- scratch (device globals; no allocation allowed) ----------
__device__ __align__(128) float g_h1[(size_t)B_ * HID];
__device__ __align__(128) float g_h2[(size_t)B_ * HID];
__device__ __align__(128) float g_ze[(size_t)B_ * LAT];
__device__ float g_zsq[B_];
__device__ float g_esq[KC];
__device__ float g_rowloss[B_];
__device__ int   g_idx[B_];
// decoder presplit (bf16x2 k-pairs)
__device__ __align__(128) uint32_t g_zqh[(size_t)B_ * (LAT/2)];
__device__ __align__(128) uint32_t g_zql[(size_t)B_ * (LAT/2)];
__device__ __align__(128) uint32_t g_d1h[(size_t)HID * (LAT/2)];
__device__ __align__(128) uint32_t g_d1l[(size_t)HID * (LAT/2)];
__device__ __align__(128) uint32_t g_d2h[(size_t)HID * (HID/2)];
__device__ __align__(128) uint32_t g_d2l[(size_t)HID * (HID/2)];
__device__ __align__(128) uint32_t g_d3h[(size_t)DIN * (HID/2)];
__device__ __align__(128) uint32_t g_d3l[(size_t)DIN * (HID/2)];
// encoder presplit (fp16x2 k-pairs)
__device__ __align__(128) uint32_t g_xh[(size_t)B_ * (DIN/2)];
__device__ __align__(128) uint32_t g_xl[(size_t)B_ * (DIN/2)];
__device__ __align__(128) uint32_t g_w1h[(size_t)HID * (DIN/2)];
__device__ __align__(128) uint32_t g_w1l[(size_t)HID * (DIN/2)];
__device__ __align__(128) uint32_t g_w2h[(size_t)HID * (HID/2)];
__device__ __align__(128) uint32_t g_w2l[(size_t)HID * (HID/2)];
__device__ __align__(128) uint32_t g_w3h[(size_t)LAT * (HID/2)];
__device__ __align__(128) uint32_t g_w3l[(size_t)LAT * (HID/2)];

__device__ __forceinline__ float gelu_exact(float x) {
    return 0.5f * x * (1.0f + erff(x * 0.7071067811865476f));
}

// packed fp32x2 FMA (dist kernel)
__device__ __forceinline__ void fma2(ull& d, ull a, ull b, ull c) {
    asm("fma.rn.f32x2 %0, %1, %2, %3;" : "=l"(d) : "l"(a), "l"(b), "l"(c));
}
__device__ __forceinline__ ull pack2(float lo, float hi) {
    ull r;
    asm("mov.b64 %0, {%1, %2};" : "=l"(r) : "f"(lo), "f"(hi));
    return r;
}
__device__ __forceinline__ void unpack2(ull v, float& lo, float& hi) {
    asm("mov.b64 {%0, %1}, %2;" : "=f"(lo), "=f"(hi) : "l"(v));
}

// ---- bf16 split ----
__device__ __forceinline__ uint32_t pack2bf(__nv_bfloat16 a, __nv_bfloat16 b) {
    __nv_bfloat162 v(a, b);
    return *reinterpret_cast<uint32_t*>(&v);
}
__device__ __forceinline__ void split_bf(float x, __nv_bfloat16& h, __nv_bfloat16& l) {
    h = __float2bfloat16_rn(x);
    l = __float2bfloat16_rn(x - __bfloat162float(h));
}
__device__ __forceinline__ uint32_t split_pair_hi(float x0, float x1) {
    __nv_bfloat16 h0, l0, h1, l1;
    split_bf(x0, h0, l0); split_bf(x1, h1, l1);
    return pack2bf(h0, h1);
}
__device__ __forceinline__ uint32_t split_pair_lo(float x0, float x1) {
    __nv_bfloat16 h0, l0, h1, l1;
    split_bf(x0, h0, l0); split_bf(x1, h1, l1);
    return pack2bf(l0, l1);
}

// ---- fp16 split ----
__device__ __forceinline__ uint32_t pack2hf(__half a, __half b) {
    __half2 v = __halves2half2(a, b);
    return *reinterpret_cast<uint32_t*>(&v);
}
__device__ __forceinline__ void split_hf(float x, __half& h, __half& l) {
    h = __float2half_rn(x);
    l = __float2half_rn(x - __half2float(h));
}
__device__ __forceinline__ uint32_t split_pair_hi_hf(float x0, float x1) {
    __half h0, l0, h1, l1;
    split_hf(x0, h0, l0); split_hf(x1, h1, l1);
    return pack2hf(h0, h1);
}
__device__ __forceinline__ uint32_t split_pair_lo_hf(float x0, float x1) {
    __half h0, l0, h1, l1;
    split_hf(x0, h0, l0); split_hf(x1, h1, l1);
    return pack2hf(l0, l1);
}

// ---- warp MMAs ----
__device__ __forceinline__ void mma16b(float* d, const uint32_t* a, const uint32_t* b) {
    asm("mma.sync.aligned.m16n8k16.row.col.f32.bf16.bf16.f32 "
        "{%0,%1,%2,%3}, {%4,%5,%6,%7}, {%8,%9}, {%0,%1,%2,%3};"
        : "+f"(d[0]), "+f"(d[1]), "+f"(d[2]), "+f"(d[3])
        : "r"(a[0]), "r"(a[1]), "r"(a[2]), "r"(a[3]), "r"(b[0]), "r"(b[1]));
}
__device__ __forceinline__ void mma16h(float* d, const uint32_t* a, const uint32_t* b) {
    asm("mma.sync.aligned.m16n8k16.row.col.f32.f16.f16.f32 "
        "{%0,%1,%2,%3}, {%4,%5,%6,%7}, {%8,%9}, {%0,%1,%2,%3};"
        : "+f"(d[0]), "+f"(d[1]), "+f"(d[2]), "+f"(d[3])
        : "r"(a[0]), "r"(a[1]), "r"(a[2]), "r"(a[3]), "r"(b[0]), "r"(b[1]));
}

// ================= presplit 3-term MMA GEMM (2 CTAs/SM) =====================
// A: [M][K/2] u32 hi/lo k-pairs, B: [N][K/2] u32 hi/lo.
// BF=1: bf16 MMA + bf16 split output. BF=0: fp16 MMA + fp16 split output.
// MODE 0: fp32 out (bias). MODE 1: bias+gelu, split out [M][N/2].
// 2 CTAs/SM: each CTA's load/sync phase overlaps the other CTA's MMA phase.
#define LDA 20   // u32 row stride (16 kp + 4 pad)

template<int MODE, int BF>
__global__ void __launch_bounds__(256, 2) mmaps_gemm(
    const uint32_t* __restrict__ Ah_g, const uint32_t* __restrict__ Al_g,
    const uint32_t* __restrict__ Bh_g, const uint32_t* __restrict__ Bl_g,
    const float* __restrict__ bias, float* __restrict__ C,
    uint32_t* __restrict__ Oh, uint32_t* __restrict__ Ol,
    int M, int N, int K)
{
    __shared__ uint32_t Ah[128 * LDA], Al[128 * LDA];
    __shared__ uint32_t Bh[128 * LDA], Bl[128 * LDA];

    const int tid  = threadIdx.x;
    const int wid  = tid >> 5;
    const int lane = tid & 31;
    const int g = lane >> 2;
    const int t = lane & 3;
    const int warp_m = wid & 1;
    const int warp_n = wid >> 1;
    const int bm = blockIdx.y * 128;
    const int bn = blockIdx.x * 128;
    const int Kp = K >> 1;

    float acc[4][4][4];
#pragma unroll
    for (int i = 0; i < 4; i++)
#pragma unroll
        for (int j = 0; j < 4; j++)
#pragma unroll
            for (int r = 0; r < 4; r++) acc[i][j][r] = 0.0f;

    const int fr = tid >> 1;
    const int fo = (tid & 1) * 8;
    const uint32_t* pAh = Ah_g + (size_t)(bm + fr) * Kp + fo;
    const uint32_t* pAl = Al_g + (size_t)(bm + fr) * Kp + fo;
    const uint32_t* pBh = Bh_g + (size_t)(bn + fr) * Kp + fo;
    const uint32_t* pBl = Bl_g + (size_t)(bn + fr) * Kp + fo;
    uint32_t* sAh = &Ah[fr * LDA + fo];
    uint32_t* sAl = &Al[fr * LDA + fo];
    uint32_t* sBh = &Bh[fr * LDA + fo];
    uint32_t* sBl = &Bl[fr * LDA + fo];

    const int nt = K / 32;
    for (int kt = 0; kt < nt; kt++) {
        const int off = kt * 16;
        // direct LDG->STS (latency covered by the co-resident CTA's MMA phase)
#pragma unroll
        for (int q = 0; q < 2; q++) {
            *(uint4*)(sAh + q * 4) = *(const uint4*)(pAh + off + q * 4);
            *(uint4*)(sAl + q * 4) = *(const uint4*)(pAl + off + q * 4);
            *(uint4*)(sBh + q * 4) = *(const uint4*)(pBh + off + q * 4);
            *(uint4*)(sBl + q * 4) = *(const uint4*)(pBl + off + q * 4);
        }
        __syncthreads();

#pragma unroll
        for (int kk = 0; kk < 2; kk++) {
            const int ko = kk * 8;
            uint32_t ah[4][4], al[4][4], bh[4][2], bl[4][2];
#pragma unroll
            for (int im = 0; im < 4; im++) {
                int row = warp_m * 64 + im * 16 + g;
                int base = row * LDA + ko;
                ah[im][0] = Ah[base + t];
                ah[im][1] = Ah[base + 8 * LDA + t];
                ah[im][2] = Ah[base + t + 4];
                ah[im][3] = Ah[base + 8 * LDA + t + 4];
                al[im][0] = Al[base + t];
                al[im][1] = Al[base + 8 * LDA + t];
                al[im][2] = Al[base + t + 4];
                al[im][3] = Al[base + 8 * LDA + t + 4];
            }
#pragma unroll
            for (int jn = 0; jn < 4; jn++) {
                int n = warp_n * 32 + jn * 8 + g;
                int base = n * LDA + ko;
                bh[jn][0] = Bh[base + t];
                bh[jn][1] = Bh[base + t + 4];
                bl[jn][0] = Bl[base + t];
                bl[jn][1] = Bl[base + t + 4];
            }
#pragma unroll
            for (int im = 0; im < 4; im++)
#pragma unroll
                for (int jn = 0; jn < 4; jn++) {
                    if (BF) {
                        mma16b(acc[im][jn], al[im], bh[jn]);
                        mma16b(acc[im][jn], ah[im], bl[jn]);
                        mma16b(acc[im][jn], ah[im], bh[jn]);
                    } else {
                        mma16h(acc[im][jn], al[im], bh[jn]);
                        mma16h(acc[im][jn], ah[im], bl[jn]);
                        mma16h(acc[im][jn], ah[im], bh[jn]);
                    }
                }
        }
        __syncthreads();
    }

    // epilogue
#pragma unroll
    for (int im = 0; im < 4; im++) {
#pragma unroll
        for (int jn = 0; jn < 4; jn++) {
            int row = bm + warp_m * 64 + im * 16 + g;
            int col = bn + warp_n * 32 + jn * 8 + 2 * t;
            float bx = bias[col], by = bias[col + 1];
            float2 v0, v1;
            v0.x = acc[im][jn][0] + bx;
            v0.y = acc[im][jn][1] + by;
            v1.x = acc[im][jn][2] + bx;
            v1.y = acc[im][jn][3] + by;
            if (MODE == 1) {
                v0.x = gelu_exact(v0.x); v0.y = gelu_exact(v0.y);
                v1.x = gelu_exact(v1.x); v1.y = gelu_exact(v1.y);
                size_t o0 = (size_t)row * (N >> 1) + (col >> 1);
                size_t o1 = (size_t)(row + 8) * (N >> 1) + (col >> 1);
                if (BF) {
                    Oh[o0] = split_pair_hi(v0.x, v0.y);
                    Ol[o0] = split_pair_lo(v0.x, v0.y);
                    Oh[o1] = split_pair_hi(v1.x, v1.y);
                    Ol[o1] = split_pair_lo(v1.x, v1.y);
                } else {
                    Oh[o0] = split_pair_hi_hf(v0.x, v0.y);
                    Ol[o0] = split_pair_lo_hf(v0.x, v0.y);
                    Oh[o1] = split_pair_hi_hf(v1.x, v1.y);
                    Ol[o1] = split_pair_lo_hf(v1.x, v1.y);
                }
            } else {
                *(float2*)&C[(size_t)row * N + col] = v0;
                *(float2*)&C[(size_t)(row + 8) * N + col] = v1;
            }
        }
    }
}

// ================= weight transpose-split prep (bf16 & fp16) ================
__global__ void wsplit_kernel(const float* __restrict__ B, int K, int N,
                              uint32_t* __restrict__ Oh, uint32_t* __restrict__ Ol)
{
    __shared__ float t[64][33];
    const int n0 = blockIdx.x * 32;
    const int k0 = blockIdx.y * 64;
    const int tid = threadIdx.x;
#pragma unroll
    for (int i = 0; i < 8; i++) {
        int idx = tid + i * 256;
        int kk = idx >> 5, nn = idx & 31;
        t[kk][nn] = B[(size_t)(k0 + kk) * N + n0 + nn];
    }
    __syncthreads();
    const int Kp = K >> 1;
#pragma unroll
    for (int i = 0; i < 4; i++) {
        int idx = tid + i * 256;
        int nn = idx >> 5, kp = idx & 31;
        float x0 = t[2 * kp][nn], x1 = t[2 * kp + 1][nn];
        size_t o = (size_t)(n0 + nn) * Kp + (k0 >> 1) + kp;
        Oh[o] = split_pair_hi(x0, x1);
        Ol[o] = split_pair_lo(x0, x1);
    }
}

__global__ void wsplit_h_kernel(const float* __restrict__ B, int K, int N,
                                uint32_t* __restrict__ Oh, uint32_t* __restrict__ Ol)
{
    __shared__ float t[64][33];
    const int n0 = blockIdx.x * 32;
    const int k0 = blockIdx.y * 64;
    const int tid = threadIdx.x;
#pragma unroll
    for (int i = 0; i < 8; i++) {
        int idx = tid + i * 256;
        int kk = idx >> 5, nn = idx & 31;
        t[kk][nn] = B[(size_t)(k0 + kk) * N + n0 + nn];
    }
    __syncthreads();
    const int Kp = K >> 1;
#pragma unroll
    for (int i = 0; i < 4; i++) {
        int idx = tid + i * 256;
        int nn = idx >> 5, kp = idx & 31;
        float x0 = t[2 * kp][nn], x1 = t[2 * kp + 1][nn];
        size_t o = (size_t)(n0 + nn) * Kp + (k0 >> 1) + kp;
        Oh[o] = split_pair_hi_hf(x0, x1);
        Ol[o] = split_pair_lo_hf(x0, x1);
    }
}

__global__ void xsplit_kernel(const float* __restrict__ X,
                              uint32_t* __restrict__ Oh, uint32_t* __restrict__ Ol,
                              int total_pairs)
{
    int idx = blockIdx.x * blockDim.x + threadIdx.x;
    if (idx >= total_pairs) return;
    float2 v = *(const float2*)(X + 2 * (size_t)idx);
    Oh[idx] = split_pair_hi_hf(v.x, v.y);
    Ol[idx] = split_pair_lo_hf(v.x, v.y);
}

// ---------------- per-row sum of squares (one warp per row) ----------------
__global__ void rowsumsq_kernel(const float* __restrict__ src,
                                float* __restrict__ out, int rows)
{
    int warp = (blockIdx.x * blockDim.x + threadIdx.x) >> 5;
    int lane = threadIdx.x & 31;
    if (warp >= rows) return;
    const float* p = src + (size_t)warp * LAT;
    float s = 0.0f;
#pragma unroll
    for (int i = 0; i < LAT; i += 32) {
        float v = p[i + lane];
        s = fmaf(v, v, s);
    }
#pragma unroll
    for (int o = 16; o; o >>= 1) s += __shfl_down_sync(0xffffffffu, s, o);
    if (lane == 0) out[warp] = s;
}

// ---------------- distance + argmin (unchanged) -----------------------------
__global__ void __launch_bounds__(256) dist_argmin_kernel(
    const float* __restrict__ embed)
{
    extern __shared__ float sm[];
    float* Es = sm;
    float* Zs = sm + 64 * 256;

    const int tid = threadIdx.x;
    const int tx = tid & 31;
    const int ty = tid >> 5;
    const int row0 = blockIdx.x * 64;

    float bestv[8];
    int   besti[8];
#pragma unroll
    for (int i = 0; i < 8; i++) { bestv[i] = INFINITY; besti[i] = 0; }

    float zs[8];
#pragma unroll
    for (int i = 0; i < 8; i++) zs[i] = g_zsq[row0 + ty * 8 + i];

    const int zr = tid & 63;
    const int zq = tid >> 6;

    for (int c0 = 0; c0 < KC; c0 += 256) {
        ull acc2[8][4];
#pragma unroll
        for (int i = 0; i < 8; i++)
#pragma unroll
            for (int j = 0; j < 4; j++) acc2[i][j] = 0ull;

        for (int ks = 0; ks < 256; ks += 64) {
            __syncthreads();
            {
                const float4* ep = (const float4*)(embed + (size_t)(c0 + tid) * LAT + ks);
#pragma unroll
                for (int q = 0; q < 16; q++) {
                    float4 v = ep[q];
                    Es[(4 * q + 0) * 256 + tid] = v.x;
                    Es[(4 * q + 1) * 256 + tid] = v.y;
                    Es[(4 * q + 2) * 256 + tid] = v.z;
                    Es[(4 * q + 3) * 256 + tid] = v.w;
                }
            }
            {
                const float4* zp = (const float4*)(g_ze + (size_t)(row0 + zr) * LAT + ks + zq * 16);
#pragma unroll
                for (int q = 0; q < 4; q++) {
                    float4 v = zp[q];
                    int kb = zq * 16 + 4 * q;
                    Zs[(kb + 0) * 64 + zr] = v.x;
                    Zs[(kb + 1) * 64 + zr] = v.y;
                    Zs[(kb + 2) * 64 + zr] = v.z;
                    Zs[(kb + 3) * 64 + zr] = v.w;
                }
            }
            __syncthreads();

            for (int k = 0; k < 64; k++) {
                float rz[8];
                *(float4*)(rz)     = *(const float4*)&Zs[k * 64 + ty * 8];
                *(float4*)(rz + 4) = *(const float4*)&Zs[k * 64 + ty * 8 + 4];
                ull re2[4];
                *(uint4*)&re2[0] = *(const uint4*)&Es[k * 256 + tx * 8];
                *(uint4*)&re2[2] = *(const uint4*)&Es[k * 256 + tx * 8 + 4];
#pragma unroll
                for (int i = 0; i < 8; i++) {
                    ull z2 = pack2(rz[i], rz[i]);
#pragma unroll
                    for (int j = 0; j < 4; j++)
                        fma2(acc2[i][j], z2, re2[j], acc2[i][j]);
                }
            }
        }

#pragma unroll
        for (int i = 0; i < 8; i++) {
            float dot[8];
            unpack2(acc2[i][0], dot[0], dot[1]);
            unpack2(acc2[i][1], dot[2], dot[3]);
            unpack2(acc2[i][2], dot[4], dot[5]);
            unpack2(acc2[i][3], dot[6], dot[7]);
#pragma unroll
            for (int j = 0; j < 8; j++) {
                int c = c0 + tx * 8 + j;
                float t1 = zs[i] + g_esq[c];
                float v  = fmaf(-2.0f, dot[j], t1);
                if (v < bestv[i] || (v == bestv[i] && c < besti[i])) {
                    bestv[i] = v; besti[i] = c;
                }
            }
        }
    }

    __syncthreads();
    float* sval = sm;
    int*   sidx = (int*)(sm + 64 * 32);
#pragma unroll
    for (int i = 0; i < 8; i++) {
        sval[(ty * 8 + i) * 32 + tx] = bestv[i];
        sidx[(ty * 8 + i) * 32 + tx] = besti[i];
    }
    __syncthreads();
    if (tid < 64) {
        float bv = INFINITY; int bi = 0x7fffffff;
        for (int tt = 0; tt < 32; tt++) {
            float v = sval[tid * 32 + tt];
            int   c = sidx[tid * 32 + tt];
            if (v < bv || (v == bv && c < bi)) { bv = v; bi = c; }
        }
        g_idx[row0 + tid] = bi;
    }
}

// ---------------- gather z_q (bf16 split), per-row loss, indices out -------
__global__ void gather_loss_kernel(const float* __restrict__ embed,
                                   float* __restrict__ out_f, int write_extra)
{
    int warp = (blockIdx.x * blockDim.x + threadIdx.x) >> 5;
    int lane = threadIdx.x & 31;
    if (warp >= B_) return;
    int idx = g_idx[warp];
    const float* ze = g_ze + (size_t)warp * LAT;
    const float* eq = embed + (size_t)idx * LAT;
    float s = 0.0f;
#pragma unroll
    for (int i = 0; i < LAT; i += 32) {
        float q = eq[i + lane];
        float z = ze[i + lane];
        float d = z - q;
        s = fmaf(d, d, s);
    }
#pragma unroll
    for (int o = 16; o; o >>= 1) s += __shfl_down_sync(0xffffffffu, s, o);
#pragma unroll
    for (int m = 0; m < LAT / 2; m += 32) {
        int kp = m + lane;
        float q0 = eq[2 * kp], q1 = eq[2 * kp + 1];
        g_zqh[(size_t)warp * (LAT / 2) + kp] = split_pair_hi(q0, q1);
        g_zql[(size_t)warp * (LAT / 2) + kp] = split_pair_lo(q0, q1);
    }
    if (lane == 0) {
        g_rowloss[warp] = s;
        if (write_extra)
            out_f[(size_t)B_ * DIN + 1 + warp] = (float)idx;
    }
}

// ---------------- final loss reduction --------------------------------------
__global__ void loss_final_kernel(float* __restrict__ out_f, int write_extra)
{
    __shared__ float sh[256];
    float s = 0.0f;
    for (int i = threadIdx.x; i < B_; i += 256) s += g_rowloss[i];
    sh[threadIdx.x] = s;
    __syncthreads();
    for (int o = 128; o; o >>= 1) {
        if (threadIdx.x < o) sh[threadIdx.x] += sh[threadIdx.x + o];
        __syncthreads();
    }
    if (threadIdx.x == 0 && write_extra) {
        out_f[(size_t)B_ * DIN] = 1.25f * sh[0] / (float)((size_t)B_ * LAT);
    }
}

// ---------------- launch ----------------------------------------------------
extern "C" void kernel_launch(void* const* d_in, const int* in_sizes, int n_in,
                              void* d_out, int out_size)
{
    const float* x     = (const float*)d_in[0];
    const float* W1    = (const float*)d_in[1];
    const float* b1    = (const float*)d_in[2];
    const float* W2    = (const float*)d_in[3];
    const float* b2    = (const float*)d_in[4];
    const float* W3    = (const float*)d_in[5];
    const float* b3    = (const float*)d_in[6];
    const float* embed = (const float*)d_in[7];
    const float* D1    = (const float*)d_in[8];
    const float* d1    = (const float*)d_in[9];
    const float* D2    = (const float*)d_in[10];
    const float* d2    = (const float*)d_in[11];
    const float* D3    = (const float*)d_in[12];
    const float* d3    = (const float*)d_in[13];
    float* out = (float*)d_out;

    float *h1, *h2, *ze, *zsq, *esq;
    uint32_t *zqh, *zql, *d1h, *d1l, *d2h, *d2l, *d3h, *d3l;
    uint32_t *xh, *xl, *w1h, *w1l, *w2h, *w2l, *w3h, *w3l;
    cudaGetSymbolAddress((void**)&h1,  g_h1);
    cudaGetSymbolAddress((void**)&h2,  g_h2);
    cudaGetSymbolAddress((void**)&ze,  g_ze);
    cudaGetSymbolAddress((void**)&zsq, g_zsq);
    cudaGetSymbolAddress((void**)&esq, g_esq);
    cudaGetSymbolAddress((void**)&zqh, g_zqh);
    cudaGetSymbolAddress((void**)&zql, g_zql);
    cudaGetSymbolAddress((void**)&d1h, g_d1h);
    cudaGetSymbolAddress((void**)&d1l, g_d1l);
    cudaGetSymbolAddress((void**)&d2h, g_d2h);
    cudaGetSymbolAddress((void**)&d2l, g_d2l);
    cudaGetSymbolAddress((void**)&d3h, g_d3h);
    cudaGetSymbolAddress((void**)&d3l, g_d3l);
    cudaGetSymbolAddress((void**)&xh,  g_xh);
    cudaGetSymbolAddress((void**)&xl,  g_xl);
    cudaGetSymbolAddress((void**)&w1h, g_w1h);
    cudaGetSymbolAddress((void**)&w1l, g_w1l);
    cudaGetSymbolAddress((void**)&w2h, g_w2h);
    cudaGetSymbolAddress((void**)&w2l, g_w2l);
    cudaGetSymbolAddress((void**)&w3h, g_w3h);
    cudaGetSymbolAddress((void**)&w3l, g_w3l);

    uint32_t* h1h = (uint32_t*)h1;
    uint32_t* h1l = h1h + (size_t)B_ * (HID / 2);
    uint32_t* h2h = (uint32_t*)h2;
    uint32_t* h2l = h2h + (size_t)B_ * (HID / 2);

    const int write_extra =
        ((size_t)out_size >= (size_t)B_ * DIN + 1 + B_) ? 1 : 0;

    // presplit
    xsplit_kernel<<<(B_ * (DIN / 2)) / 256, 256>>>(x, xh, xl, B_ * (DIN / 2));
    wsplit_h_kernel<<<dim3(HID / 32, DIN / 64), 256>>>(W1, DIN, HID, w1h, w1l);
    wsplit_h_kernel<<<dim3(HID / 32, HID / 64), 256>>>(W2, HID, HID, w2h, w2l);
    wsplit_h_kernel<<<dim3(LAT / 32, HID / 64), 256>>>(W3, HID, LAT, w3h, w3l);
    wsplit_kernel<<<dim3(HID / 32, LAT / 64), 256>>>(D1, LAT, HID, d1h, d1l);
    wsplit_kernel<<<dim3(HID / 32, HID / 64), 256>>>(D2, HID, HID, d2h, d2l);
    wsplit_kernel<<<dim3(DIN / 32, HID / 64), 256>>>(D3, HID, DIN, d3h, d3l);

    // encoder — fp16 2-way-split 3-term MMA (zero index flips, proven R9)
    {
        dim3 g(HID / 128, B_ / 128);
        mmaps_gemm<1, 0><<<g, 256>>>(xh, xl, w1h, w1l, b1, nullptr,
                                     h1h, h1l, B_, HID, DIN);
    }
    {
        dim3 g(HID / 128, B_ / 128);
        mmaps_gemm<1, 0><<<g, 256>>>(h1h, h1l, w2h, w2l, b2, nullptr,
                                     h2h, h2l, B_, HID, HID);
    }
    {
        dim3 g(LAT / 128, B_ / 128);
        mmaps_gemm<0, 0><<<g, 256>>>(h2h, h2l, w3h, w3l, b3, ze,
                                     nullptr, nullptr, B_, LAT, HID);
    }

    // norms
    rowsumsq_kernel<<<(B_ * 32) / 256, 256>>>(ze, zsq, B_);
    rowsumsq_kernel<<<(KC * 32) / 256, 256>>>(embed, esq, KC);

    // distance + argmin
    {
        int smem = (64 * 256 + 64 * 64) * (int)sizeof(float);  // 80 KB
        cudaFuncSetAttribute(dist_argmin_kernel,
                             cudaFuncAttributeMaxDynamicSharedMemorySize, smem);
        dist_argmin_kernel<<<B_ / 64, 256, smem>>>(embed);
    }

    // gather (+ zq bf16 split) + loss
    gather_loss_kernel<<<(B_ * 32) / 256, 256>>>(embed, out, write_extra);
    loss_final_kernel<<<1, 256>>>(out, write_extra);

    // decoder — bf16 3-term MMA
    {
        dim3 g(HID / 128, B_ / 128);
        mmaps_gemm<1, 1><<<g, 256>>>(zqh, zql, d1h, d1l, d1, nullptr,
                                     h1h, h1l, B_, HID, LAT);
    }
    {
        dim3 g(HID / 128, B_ / 128);
        mmaps_gemm<1, 1><<<g, 256>>>(h1h, h1l, d2h, d2l, d2, nullptr,
                                     h2h, h2l, B_, HID, HID);
    }
    {
        dim3 g(DIN / 128, B_ / 128);
        mmaps_gemm<0, 1><<<g, 256>>>(h2h, h2l, d3h, d3l, d3, out,
                                     nullptr, nullptr, B_, DIN, HID);
    }
}

// round 12
// speedup vs baseline: 1.7171x; 1.1208x over previous
#include <cuda_runtime.h>
#include <cuda_bf16.h>
#include <cuda_fp16.h>
#include <math.h>
#include <stdint.h>

#define B_   8192
#define DIN  1024
#define HID  2048
#define LAT  256
#define KC   4096

typedef unsigned long long ull;

// ---------------- scratch (device globals; no allocation allowed) ----------
__device__ __align__(128) float g_h1[(size_t)B_ * HID];
__device__ __align__(128) float g_h2[(size_t)B_ * HID];
__device__ __align__(128) float g_ze[(size_t)B_ * LAT];
__device__ float g_zsq[B_];
__device__ float g_esq[KC];
__device__ float g_rowloss[B_];
__device__ int   g_idx[B_];
// decoder presplit (bf16x2 k-pairs)
__device__ __align__(128) uint32_t g_zqh[(size_t)B_ * (LAT/2)];
__device__ __align__(128) uint32_t g_zql[(size_t)B_ * (LAT/2)];
__device__ __align__(128) uint32_t g_d1h[(size_t)HID * (LAT/2)];
__device__ __align__(128) uint32_t g_d1l[(size_t)HID * (LAT/2)];
__device__ __align__(128) uint32_t g_d2h[(size_t)HID * (HID/2)];
__device__ __align__(128) uint32_t g_d2l[(size_t)HID * (HID/2)];
__device__ __align__(128) uint32_t g_d3h[(size_t)DIN * (HID/2)];
__device__ __align__(128) uint32_t g_d3l[(size_t)DIN * (HID/2)];
// encoder presplit (fp16x2 k-pairs)
__device__ __align__(128) uint32_t g_xh[(size_t)B_ * (DIN/2)];
__device__ __align__(128) uint32_t g_xl[(size_t)B_ * (DIN/2)];
__device__ __align__(128) uint32_t g_w1h[(size_t)HID * (DIN/2)];
__device__ __align__(128) uint32_t g_w1l[(size_t)HID * (DIN/2)];
__device__ __align__(128) uint32_t g_w2h[(size_t)HID * (HID/2)];
__device__ __align__(128) uint32_t g_w2l[(size_t)HID * (HID/2)];
__device__ __align__(128) uint32_t g_w3h[(size_t)LAT * (HID/2)];
__device__ __align__(128) uint32_t g_w3l[(size_t)LAT * (HID/2)];
// dist path (fp16 splits; embed scaled by 4096)
__device__ __align__(128) uint32_t g_zeh[(size_t)B_ * (LAT/2)];
__device__ __align__(128) uint32_t g_zel[(size_t)B_ * (LAT/2)];
__device__ __align__(128) uint32_t g_eh[(size_t)KC * (LAT/2)];
__device__ __align__(128) uint32_t g_el[(size_t)KC * (LAT/2)];
__device__ float g_pv[(size_t)B_ * 32];
__device__ int   g_pi[(size_t)B_ * 32];

__device__ __forceinline__ float gelu_exact(float x) {
    return 0.5f * x * (1.0f + erff(x * 0.7071067811865476f));
}

// ---- bf16 split ----
__device__ __forceinline__ uint32_t pack2bf(__nv_bfloat16 a, __nv_bfloat16 b) {
    __nv_bfloat162 v(a, b);
    return *reinterpret_cast<uint32_t*>(&v);
}
__device__ __forceinline__ void split_bf(float x, __nv_bfloat16& h, __nv_bfloat16& l) {
    h = __float2bfloat16_rn(x);
    l = __float2bfloat16_rn(x - __bfloat162float(h));
}
__device__ __forceinline__ uint32_t split_pair_hi(float x0, float x1) {
    __nv_bfloat16 h0, l0, h1, l1;
    split_bf(x0, h0, l0); split_bf(x1, h1, l1);
    return pack2bf(h0, h1);
}
__device__ __forceinline__ uint32_t split_pair_lo(float x0, float x1) {
    __nv_bfloat16 h0, l0, h1, l1;
    split_bf(x0, h0, l0); split_bf(x1, h1, l1);
    return pack2bf(l0, l1);
}

// ---- fp16 split ----
__device__ __forceinline__ uint32_t pack2hf(__half a, __half b) {
    __half2 v = __halves2half2(a, b);
    return *reinterpret_cast<uint32_t*>(&v);
}
__device__ __forceinline__ void split_hf(float x, __half& h, __half& l) {
    h = __float2half_rn(x);
    l = __float2half_rn(x - __half2float(h));
}
__device__ __forceinline__ uint32_t split_pair_hi_hf(float x0, float x1) {
    __half h0, l0, h1, l1;
    split_hf(x0, h0, l0); split_hf(x1, h1, l1);
    return pack2hf(h0, h1);
}
__device__ __forceinline__ uint32_t split_pair_lo_hf(float x0, float x1) {
    __half h0, l0, h1, l1;
    split_hf(x0, h0, l0); split_hf(x1, h1, l1);
    return pack2hf(l0, l1);
}

// ---- warp MMAs ----
__device__ __forceinline__ void mma16b(float* d, const uint32_t* a, const uint32_t* b) {
    asm("mma.sync.aligned.m16n8k16.row.col.f32.bf16.bf16.f32 "
        "{%0,%1,%2,%3}, {%4,%5,%6,%7}, {%8,%9}, {%0,%1,%2,%3};"
        : "+f"(d[0]), "+f"(d[1]), "+f"(d[2]), "+f"(d[3])
        : "r"(a[0]), "r"(a[1]), "r"(a[2]), "r"(a[3]), "r"(b[0]), "r"(b[1]));
}
__device__ __forceinline__ void mma16h(float* d, const uint32_t* a, const uint32_t* b) {
    asm("mma.sync.aligned.m16n8k16.row.col.f32.f16.f16.f32 "
        "{%0,%1,%2,%3}, {%4,%5,%6,%7}, {%8,%9}, {%0,%1,%2,%3};"
        : "+f"(d[0]), "+f"(d[1]), "+f"(d[2]), "+f"(d[3])
        : "r"(a[0]), "r"(a[1]), "r"(a[2]), "r"(a[3]), "r"(b[0]), "r"(b[1]));
}

__device__ __forceinline__ void upd_best(float& bv, int& bi, float v, int c) {
    if (v < bv || (v == bv && c < bi)) { bv = v; bi = c; }
}

// ================= presplit 3-term MMA GEMM (2 CTAs/SM) =====================
// MODE 0: fp32 out. MODE 1: gelu + split out. MODE 2: fp32 out + fp16 split out.
#define LDA 20

template<int MODE, int BF>
__global__ void __launch_bounds__(256, 2) mmaps_gemm(
    const uint32_t* __restrict__ Ah_g, const uint32_t* __restrict__ Al_g,
    const uint32_t* __restrict__ Bh_g, const uint32_t* __restrict__ Bl_g,
    const float* __restrict__ bias, float* __restrict__ C,
    uint32_t* __restrict__ Oh, uint32_t* __restrict__ Ol,
    int M, int N, int K)
{
    __shared__ uint32_t Ah[128 * LDA], Al[128 * LDA];
    __shared__ uint32_t Bh[128 * LDA], Bl[128 * LDA];

    const int tid  = threadIdx.x;
    const int wid  = tid >> 5;
    const int lane = tid & 31;
    const int g = lane >> 2;
    const int t = lane & 3;
    const int warp_m = wid & 1;
    const int warp_n = wid >> 1;
    const int bm = blockIdx.y * 128;
    const int bn = blockIdx.x * 128;
    const int Kp = K >> 1;

    float acc[4][4][4];
#pragma unroll
    for (int i = 0; i < 4; i++)
#pragma unroll
        for (int j = 0; j < 4; j++)
#pragma unroll
            for (int r = 0; r < 4; r++) acc[i][j][r] = 0.0f;

    const int fr = tid >> 1;
    const int fo = (tid & 1) * 8;
    const uint32_t* pAh = Ah_g + (size_t)(bm + fr) * Kp + fo;
    const uint32_t* pAl = Al_g + (size_t)(bm + fr) * Kp + fo;
    const uint32_t* pBh = Bh_g + (size_t)(bn + fr) * Kp + fo;
    const uint32_t* pBl = Bl_g + (size_t)(bn + fr) * Kp + fo;
    uint32_t* sAh = &Ah[fr * LDA + fo];
    uint32_t* sAl = &Al[fr * LDA + fo];
    uint32_t* sBh = &Bh[fr * LDA + fo];
    uint32_t* sBl = &Bl[fr * LDA + fo];

    const int nt = K / 32;
    for (int kt = 0; kt < nt; kt++) {
        const int off = kt * 16;
#pragma unroll
        for (int q = 0; q < 2; q++) {
            *(uint4*)(sAh + q * 4) = *(const uint4*)(pAh + off + q * 4);
            *(uint4*)(sAl + q * 4) = *(const uint4*)(pAl + off + q * 4);
            *(uint4*)(sBh + q * 4) = *(const uint4*)(pBh + off + q * 4);
            *(uint4*)(sBl + q * 4) = *(const uint4*)(pBl + off + q * 4);
        }
        __syncthreads();

#pragma unroll
        for (int kk = 0; kk < 2; kk++) {
            const int ko = kk * 8;
            uint32_t ah[4][4], al[4][4], bh[4][2], bl[4][2];
#pragma unroll
            for (int im = 0; im < 4; im++) {
                int row = warp_m * 64 + im * 16 + g;
                int base = row * LDA + ko;
                ah[im][0] = Ah[base + t];
                ah[im][1] = Ah[base + 8 * LDA + t];
                ah[im][2] = Ah[base + t + 4];
                ah[im][3] = Ah[base + 8 * LDA + t + 4];
                al[im][0] = Al[base + t];
                al[im][1] = Al[base + 8 * LDA + t];
                al[im][2] = Al[base + t + 4];
                al[im][3] = Al[base + 8 * LDA + t + 4];
            }
#pragma unroll
            for (int jn = 0; jn < 4; jn++) {
                int n = warp_n * 32 + jn * 8 + g;
                int base = n * LDA + ko;
                bh[jn][0] = Bh[base + t];
                bh[jn][1] = Bh[base + t + 4];
                bl[jn][0] = Bl[base + t];
                bl[jn][1] = Bl[base + t + 4];
            }
#pragma unroll
            for (int im = 0; im < 4; im++)
#pragma unroll
                for (int jn = 0; jn < 4; jn++) {
                    if (BF) {
                        mma16b(acc[im][jn], al[im], bh[jn]);
                        mma16b(acc[im][jn], ah[im], bl[jn]);
                        mma16b(acc[im][jn], ah[im], bh[jn]);
                    } else {
                        mma16h(acc[im][jn], al[im], bh[jn]);
                        mma16h(acc[im][jn], ah[im], bl[jn]);
                        mma16h(acc[im][jn], ah[im], bh[jn]);
                    }
                }
        }
        __syncthreads();
    }

    // epilogue
#pragma unroll
    for (int im = 0; im < 4; im++) {
#pragma unroll
        for (int jn = 0; jn < 4; jn++) {
            int row = bm + warp_m * 64 + im * 16 + g;
            int col = bn + warp_n * 32 + jn * 8 + 2 * t;
            float bx = bias[col], by = bias[col + 1];
            float2 v0, v1;
            v0.x = acc[im][jn][0] + bx;
            v0.y = acc[im][jn][1] + by;
            v1.x = acc[im][jn][2] + bx;
            v1.y = acc[im][jn][3] + by;
            if (MODE == 1) {
                v0.x = gelu_exact(v0.x); v0.y = gelu_exact(v0.y);
                v1.x = gelu_exact(v1.x); v1.y = gelu_exact(v1.y);
                size_t o0 = (size_t)row * (N >> 1) + (col >> 1);
                size_t o1 = (size_t)(row + 8) * (N >> 1) + (col >> 1);
                if (BF) {
                    Oh[o0] = split_pair_hi(v0.x, v0.y);
                    Ol[o0] = split_pair_lo(v0.x, v0.y);
                    Oh[o1] = split_pair_hi(v1.x, v1.y);
                    Ol[o1] = split_pair_lo(v1.x, v1.y);
                } else {
                    Oh[o0] = split_pair_hi_hf(v0.x, v0.y);
                    Ol[o0] = split_pair_lo_hf(v0.x, v0.y);
                    Oh[o1] = split_pair_hi_hf(v1.x, v1.y);
                    Ol[o1] = split_pair_lo_hf(v1.x, v1.y);
                }
            } else if (MODE == 2) {
                *(float2*)&C[(size_t)row * N + col] = v0;
                *(float2*)&C[(size_t)(row + 8) * N + col] = v1;
                size_t o0 = (size_t)row * (N >> 1) + (col >> 1);
                size_t o1 = (size_t)(row + 8) * (N >> 1) + (col >> 1);
                Oh[o0] = split_pair_hi_hf(v0.x, v0.y);
                Ol[o0] = split_pair_lo_hf(v0.x, v0.y);
                Oh[o1] = split_pair_hi_hf(v1.x, v1.y);
                Ol[o1] = split_pair_lo_hf(v1.x, v1.y);
            } else {
                *(float2*)&C[(size_t)row * N + col] = v0;
                *(float2*)&C[(size_t)(row + 8) * N + col] = v1;
            }
        }
    }
}

// ================= dist MMA + fused argmin ==================================
// dot' = z.(e*4096); dot = dot' * 2^-12 (EXACT). Criterion matches reference:
// v = fl( fl(zsq+esq) - 2*dot ) — the ~3e-5 quantization at |v|~256 masks the
// MMA dot deviation (~5e-9) exactly like it masked the FFMA2 path's (~2e-9).
__global__ void __launch_bounds__(256, 2) dist_mma_kernel(
    const uint32_t* __restrict__ Zh, const uint32_t* __restrict__ Zl,
    const uint32_t* __restrict__ Eh, const uint32_t* __restrict__ El,
    const float* __restrict__ zsq, const float* __restrict__ esq,
    float* __restrict__ pv, int* __restrict__ pi)
{
    __shared__ uint32_t Ah[128 * LDA], Al[128 * LDA];
    __shared__ uint32_t Bh[128 * LDA], Bl[128 * LDA];
    __shared__ float sval[4 * 128];
    __shared__ int   sidx[4 * 128];

    const int tid  = threadIdx.x;
    const int wid  = tid >> 5;
    const int lane = tid & 31;
    const int g = lane >> 2;
    const int t = lane & 3;
    const int warp_m = wid & 1;
    const int warp_n = wid >> 1;
    const int bm = blockIdx.y * 128;   // z rows
    const int bn = blockIdx.x * 128;   // codes
    const int Kp = LAT >> 1;           // 128

    float acc[4][4][4];
#pragma unroll
    for (int i = 0; i < 4; i++)
#pragma unroll
        for (int j = 0; j < 4; j++)
#pragma unroll
            for (int r = 0; r < 4; r++) acc[i][j][r] = 0.0f;

    const int fr = tid >> 1;
    const int fo = (tid & 1) * 8;
    const uint32_t* pAh = Zh + (size_t)(bm + fr) * Kp + fo;
    const uint32_t* pAl = Zl + (size_t)(bm + fr) * Kp + fo;
    const uint32_t* pBh = Eh + (size_t)(bn + fr) * Kp + fo;
    const uint32_t* pBl = El + (size_t)(bn + fr) * Kp + fo;
    uint32_t* sAh = &Ah[fr * LDA + fo];
    uint32_t* sAl = &Al[fr * LDA + fo];
    uint32_t* sBh = &Bh[fr * LDA + fo];
    uint32_t* sBl = &Bl[fr * LDA + fo];

    const int nt = LAT / 32;           // 8
    for (int kt = 0; kt < nt; kt++) {
        const int off = kt * 16;
#pragma unroll
        for (int q = 0; q < 2; q++) {
            *(uint4*)(sAh + q * 4) = *(const uint4*)(pAh + off + q * 4);
            *(uint4*)(sAl + q * 4) = *(const uint4*)(pAl + off + q * 4);
            *(uint4*)(sBh + q * 4) = *(const uint4*)(pBh + off + q * 4);
            *(uint4*)(sBl + q * 4) = *(const uint4*)(pBl + off + q * 4);
        }
        __syncthreads();

#pragma unroll
        for (int kk = 0; kk < 2; kk++) {
            const int ko = kk * 8;
            uint32_t ah[4][4], al[4][4], bh[4][2], bl[4][2];
#pragma unroll
            for (int im = 0; im < 4; im++) {
                int row = warp_m * 64 + im * 16 + g;
                int base = row * LDA + ko;
                ah[im][0] = Ah[base + t];
                ah[im][1] = Ah[base + 8 * LDA + t];
                ah[im][2] = Ah[base + t + 4];
                ah[im][3] = Ah[base + 8 * LDA + t + 4];
                al[im][0] = Al[base + t];
                al[im][1] = Al[base + 8 * LDA + t];
                al[im][2] = Al[base + t + 4];
                al[im][3] = Al[base + 8 * LDA + t + 4];
            }
#pragma unroll
            for (int jn = 0; jn < 4; jn++) {
                int n = warp_n * 32 + jn * 8 + g;
                int base = n * LDA + ko;
                bh[jn][0] = Bh[base + t];
                bh[jn][1] = Bh[base + t + 4];
                bl[jn][0] = Bl[base + t];
                bl[jn][1] = Bl[base + t + 4];
            }
#pragma unroll
            for (int im = 0; im < 4; im++)
#pragma unroll
                for (int jn = 0; jn < 4; jn++) {
                    mma16h(acc[im][jn], al[im], bh[jn]);
                    mma16h(acc[im][jn], ah[im], bl[jn]);
                    mma16h(acc[im][jn], ah[im], bh[jn]);
                }
        }
        __syncthreads();
    }

    // fused argmin epilogue — reference criterion with exact 2^-12 rescale
    const float inv = 0.000244140625f;   // 2^-12, exact scale
    float bv[4][2];
    int   bi[4][2];
    float zs0[4], zs1[4];
#pragma unroll
    for (int im = 0; im < 4; im++) {
        int r0 = bm + warp_m * 64 + im * 16 + g;
        zs0[im] = zsq[r0];
        zs1[im] = zsq[r0 + 8];
        bv[im][0] = INFINITY; bi[im][0] = 0x7fffffff;
        bv[im][1] = INFINITY; bi[im][1] = 0x7fffffff;
    }

#pragma unroll
    for (int im = 0; im < 4; im++) {
#pragma unroll
        for (int jn = 0; jn < 4; jn++) {
            int c0 = bn + warp_n * 32 + jn * 8 + 2 * t;
            float e0 = esq[c0], e1 = esq[c0 + 1];
            float t00 = zs0[im] + e0, t01 = zs0[im] + e1;
            float t10 = zs1[im] + e0, t11 = zs1[im] + e1;
            float d00 = fmaf(-2.0f, acc[im][jn][0] * inv, t00);
            float d01 = fmaf(-2.0f, acc[im][jn][1] * inv, t01);
            float d10 = fmaf(-2.0f, acc[im][jn][2] * inv, t10);
            float d11 = fmaf(-2.0f, acc[im][jn][3] * inv, t11);
            upd_best(bv[im][0], bi[im][0], d00, c0);
            upd_best(bv[im][0], bi[im][0], d01, c0 + 1);
            upd_best(bv[im][1], bi[im][1], d10, c0);
            upd_best(bv[im][1], bi[im][1], d11, c0 + 1);
        }
    }
#pragma unroll
    for (int im = 0; im < 4; im++)
#pragma unroll
        for (int h = 0; h < 2; h++) {
#pragma unroll
            for (int o = 2; o; o >>= 1) {
                float vv = __shfl_down_sync(0xffffffffu, bv[im][h], o, 4);
                int   cc = __shfl_down_sync(0xffffffffu, bi[im][h], o, 4);
                upd_best(bv[im][h], bi[im][h], vv, cc);
            }
        }
    if (t == 0) {
#pragma unroll
        for (int im = 0; im < 4; im++)
#pragma unroll
            for (int h = 0; h < 2; h++) {
                int r = warp_m * 64 + im * 16 + g + h * 8;
                sval[warp_n * 128 + r] = bv[im][h];
                sidx[warp_n * 128 + r] = bi[im][h];
            }
    }
    __syncthreads();
    if (tid < 128) {
        float v = sval[tid];
        int   c = sidx[tid];
        for (int wn = 1; wn < 4; wn++)
            upd_best(v, c, sval[wn * 128 + tid], sidx[wn * 128 + tid]);
        size_t o = (size_t)(bm + tid) * 32 + blockIdx.x;
        pv[o] = v;
        pi[o] = c;
    }
}

__global__ void argmin_final_kernel(const float* __restrict__ pv,
                                    const int* __restrict__ pi)
{
    int r = blockIdx.x * blockDim.x + threadIdx.x;
    if (r >= B_) return;
    float bv = INFINITY;
    int   bi = 0x7fffffff;
    for (int cb = 0; cb < 32; cb++)
        upd_best(bv, bi, pv[(size_t)r * 32 + cb], pi[(size_t)r * 32 + cb]);
    g_idx[r] = bi;
}

// ================= prep kernels =============================================
__global__ void wsplit_kernel(const float* __restrict__ B, int K, int N,
                              uint32_t* __restrict__ Oh, uint32_t* __restrict__ Ol)
{
    __shared__ float t[64][33];
    const int n0 = blockIdx.x * 32;
    const int k0 = blockIdx.y * 64;
    const int tid = threadIdx.x;
#pragma unroll
    for (int i = 0; i < 8; i++) {
        int idx = tid + i * 256;
        int kk = idx >> 5, nn = idx & 31;
        t[kk][nn] = B[(size_t)(k0 + kk) * N + n0 + nn];
    }
    __syncthreads();
    const int Kp = K >> 1;
#pragma unroll
    for (int i = 0; i < 4; i++) {
        int idx = tid + i * 256;
        int nn = idx >> 5, kp = idx & 31;
        float x0 = t[2 * kp][nn], x1 = t[2 * kp + 1][nn];
        size_t o = (size_t)(n0 + nn) * Kp + (k0 >> 1) + kp;
        Oh[o] = split_pair_hi(x0, x1);
        Ol[o] = split_pair_lo(x0, x1);
    }
}

__global__ void wsplit_h_kernel(const float* __restrict__ B, int K, int N,
                                uint32_t* __restrict__ Oh, uint32_t* __restrict__ Ol)
{
    __shared__ float t[64][33];
    const int n0 = blockIdx.x * 32;
    const int k0 = blockIdx.y * 64;
    const int tid = threadIdx.x;
#pragma unroll
    for (int i = 0; i < 8; i++) {
        int idx = tid + i * 256;
        int kk = idx >> 5, nn = idx & 31;
        t[kk][nn] = B[(size_t)(k0 + kk) * N + n0 + nn];
    }
    __syncthreads();
    const int Kp = K >> 1;
#pragma unroll
    for (int i = 0; i < 4; i++) {
        int idx = tid + i * 256;
        int nn = idx >> 5, kp = idx & 31;
        float x0 = t[2 * kp][nn], x1 = t[2 * kp + 1][nn];
        size_t o = (size_t)(n0 + nn) * Kp + (k0 >> 1) + kp;
        Oh[o] = split_pair_hi_hf(x0, x1);
        Ol[o] = split_pair_lo_hf(x0, x1);
    }
}

__global__ void xsplit_kernel(const float* __restrict__ X,
                              uint32_t* __restrict__ Oh, uint32_t* __restrict__ Ol,
                              int total_pairs)
{
    int idx = blockIdx.x * blockDim.x + threadIdx.x;
    if (idx >= total_pairs) return;
    float2 v = *(const float2*)(X + 2 * (size_t)idx);
    Oh[idx] = split_pair_hi_hf(v.x, v.y);
    Ol[idx] = split_pair_lo_hf(v.x, v.y);
}

// embed fp16 split, pre-scaled by 4096 (exact) to dodge fp16 subnormals
__global__ void esplit_kernel(const float* __restrict__ E,
                              uint32_t* __restrict__ Oh, uint32_t* __restrict__ Ol,
                              int total_pairs)
{
    int idx = blockIdx.x * blockDim.x + threadIdx.x;
    if (idx >= total_pairs) return;
    float2 v = *(const float2*)(E + 2 * (size_t)idx);
    float x0 = v.x * 4096.0f, x1 = v.y * 4096.0f;
    Oh[idx] = split_pair_hi_hf(x0, x1);
    Ol[idx] = split_pair_lo_hf(x0, x1);
}

// ---------------- per-row sum of squares (one warp per row) ----------------
__global__ void rowsumsq_kernel(const float* __restrict__ src,
                                float* __restrict__ out, int rows)
{
    int warp = (blockIdx.x * blockDim.x + threadIdx.x) >> 5;
    int lane = threadIdx.x & 31;
    if (warp >= rows) return;
    const float* p = src + (size_t)warp * LAT;
    float s = 0.0f;
#pragma unroll
    for (int i = 0; i < LAT; i += 32) {
        float v = p[i + lane];
        s = fmaf(v, v, s);
    }
#pragma unroll
    for (int o = 16; o; o >>= 1) s += __shfl_down_sync(0xffffffffu, s, o);
    if (lane == 0) out[warp] = s;
}

// ---------------- gather z_q (bf16 split), per-row loss, indices out -------
__global__ void gather_loss_kernel(const float* __restrict__ embed,
                                   float* __restrict__ out_f, int write_extra)
{
    int warp = (blockIdx.x * blockDim.x + threadIdx.x) >> 5;
    int lane = threadIdx.x & 31;
    if (warp >= B_) return;
    int idx = g_idx[warp];
    const float* ze = g_ze + (size_t)warp * LAT;
    const float* eq = embed + (size_t)idx * LAT;
    float s = 0.0f;
#pragma unroll
    for (int i = 0; i < LAT; i += 32) {
        float q = eq[i + lane];
        float z = ze[i + lane];
        float d = z - q;
        s = fmaf(d, d, s);
    }
#pragma unroll
    for (int o = 16; o; o >>= 1) s += __shfl_down_sync(0xffffffffu, s, o);
#pragma unroll
    for (int m = 0; m < LAT / 2; m += 32) {
        int kp = m + lane;
        float q0 = eq[2 * kp], q1 = eq[2 * kp + 1];
        g_zqh[(size_t)warp * (LAT / 2) + kp] = split_pair_hi(q0, q1);
        g_zql[(size_t)warp * (LAT / 2) + kp] = split_pair_lo(q0, q1);
    }
    if (lane == 0) {
        g_rowloss[warp] = s;
        if (write_extra)
            out_f[(size_t)B_ * DIN + 1 + warp] = (float)idx;
    }
}

// ---------------- final loss reduction --------------------------------------
__global__ void loss_final_kernel(float* __restrict__ out_f, int write_extra)
{
    __shared__ float sh[256];
    float s = 0.0f;
    for (int i = threadIdx.x; i < B_; i += 256) s += g_rowloss[i];
    sh[threadIdx.x] = s;
    __syncthreads();
    for (int o = 128; o; o >>= 1) {
        if (threadIdx.x < o) sh[threadIdx.x] += sh[threadIdx.x + o];
        __syncthreads();
    }
    if (threadIdx.x == 0 && write_extra) {
        out_f[(size_t)B_ * DIN] = 1.25f * sh[0] / (float)((size_t)B_ * LAT);
    }
}

// ---------------- launch ----------------------------------------------------
extern "C" void kernel_launch(void* const* d_in, const int* in_sizes, int n_in,
                              void* d_out, int out_size)
{
    const float* x     = (const float*)d_in[0];
    const float* W1    = (const float*)d_in[1];
    const float* b1    = (const float*)d_in[2];
    const float* W2    = (const float*)d_in[3];
    const float* b2    = (const float*)d_in[4];
    const float* W3    = (const float*)d_in[5];
    const float* b3    = (const float*)d_in[6];
    const float* embed = (const float*)d_in[7];
    const float* D1    = (const float*)d_in[8];
    const float* d1    = (const float*)d_in[9];
    const float* D2    = (const float*)d_in[10];
    const float* d2    = (const float*)d_in[11];
    const float* D3    = (const float*)d_in[12];
    const float* d3    = (const float*)d_in[13];
    float* out = (float*)d_out;

    float *h1, *h2, *ze, *zsq, *esq, *pv;
    int *pi;
    uint32_t *zqh, *zql, *d1h, *d1l, *d2h, *d2l, *d3h, *d3l;
    uint32_t *xh, *xl, *w1h, *w1l, *w2h, *w2l, *w3h, *w3l;
    uint32_t *zeh, *zel, *eh, *el;
    cudaGetSymbolAddress((void**)&h1,  g_h1);
    cudaGetSymbolAddress((void**)&h2,  g_h2);
    cudaGetSymbolAddress((void**)&ze,  g_ze);
    cudaGetSymbolAddress((void**)&zsq, g_zsq);
    cudaGetSymbolAddress((void**)&esq, g_esq);
    cudaGetSymbolAddress((void**)&zqh, g_zqh);
    cudaGetSymbolAddress((void**)&zql, g_zql);
    cudaGetSymbolAddress((void**)&d1h, g_d1h);
    cudaGetSymbolAddress((void**)&d1l, g_d1l);
    cudaGetSymbolAddress((void**)&d2h, g_d2h);
    cudaGetSymbolAddress((void**)&d2l, g_d2l);
    cudaGetSymbolAddress((void**)&d3h, g_d3h);
    cudaGetSymbolAddress((void**)&d3l, g_d3l);
    cudaGetSymbolAddress((void**)&xh,  g_xh);
    cudaGetSymbolAddress((void**)&xl,  g_xl);
    cudaGetSymbolAddress((void**)&w1h, g_w1h);
    cudaGetSymbolAddress((void**)&w1l, g_w1l);
    cudaGetSymbolAddress((void**)&w2h, g_w2h);
    cudaGetSymbolAddress((void**)&w2l, g_w2l);
    cudaGetSymbolAddress((void**)&w3h, g_w3h);
    cudaGetSymbolAddress((void**)&w3l, g_w3l);
    cudaGetSymbolAddress((void**)&zeh, g_zeh);
    cudaGetSymbolAddress((void**)&zel, g_zel);
    cudaGetSymbolAddress((void**)&eh,  g_eh);
    cudaGetSymbolAddress((void**)&el,  g_el);
    cudaGetSymbolAddress((void**)&pv,  g_pv);
    cudaGetSymbolAddress((void**)&pi,  g_pi);

    uint32_t* h1h = (uint32_t*)h1;
    uint32_t* h1l = h1h + (size_t)B_ * (HID / 2);
    uint32_t* h2h = (uint32_t*)h2;
    uint32_t* h2l = h2h + (size_t)B_ * (HID / 2);

    const int write_extra =
        ((size_t)out_size >= (size_t)B_ * DIN + 1 + B_) ? 1 : 0;

    // presplit
    xsplit_kernel<<<(B_ * (DIN / 2)) / 256, 256>>>(x, xh, xl, B_ * (DIN / 2));
    wsplit_h_kernel<<<dim3(HID / 32, DIN / 64), 256>>>(W1, DIN, HID, w1h, w1l);
    wsplit_h_kernel<<<dim3(HID / 32, HID / 64), 256>>>(W2, HID, HID, w2h, w2l);
    wsplit_h_kernel<<<dim3(LAT / 32, HID / 64), 256>>>(W3, HID, LAT, w3h, w3l);
    wsplit_kernel<<<dim3(HID / 32, LAT / 64), 256>>>(D1, LAT, HID, d1h, d1l);
    wsplit_kernel<<<dim3(HID / 32, HID / 64), 256>>>(D2, HID, HID, d2h, d2l);
    wsplit_kernel<<<dim3(DIN / 32, HID / 64), 256>>>(D3, HID, DIN, d3h, d3l);
    esplit_kernel<<<(KC * (LAT / 2)) / 256, 256>>>(embed, eh, el, KC * (LAT / 2));
    rowsumsq_kernel<<<(KC * 32) / 256, 256>>>(embed, esq, KC);

    // encoder — fp16 2-way-split 3-term MMA (flip-free, proven R9/R10)
    {
        dim3 g(HID / 128, B_ / 128);
        mmaps_gemm<1, 0><<<g, 256>>>(xh, xl, w1h, w1l, b1, nullptr,
                                     h1h, h1l, B_, HID, DIN);
    }
    {
        dim3 g(HID / 128, B_ / 128);
        mmaps_gemm<1, 0><<<g, 256>>>(h1h, h1l, w2h, w2l, b2, nullptr,
                                     h2h, h2l, B_, HID, HID);
    }
    {
        dim3 g(LAT / 128, B_ / 128);
        mmaps_gemm<2, 0><<<g, 256>>>(h2h, h2l, w3h, w3l, b3, ze,
                                     zeh, zel, B_, LAT, HID);
    }

    // zsq on z_e (needed for the reference-rounded criterion)
    rowsumsq_kernel<<<(B_ * 32) / 256, 256>>>(ze, zsq, B_);

    // dist + argmin — fp16-split MMA, reference criterion (exact 2^-12 rescale)
    {
        dim3 g(KC / 128, B_ / 128);
        dist_mma_kernel<<<g, 256>>>(zeh, zel, eh, el, zsq, esq, pv, pi);
    }
    argmin_final_kernel<<<B_ / 256, 256>>>(pv, pi);

    // gather (+ zq bf16 split) + loss
    gather_loss_kernel<<<(B_ * 32) / 256, 256>>>(embed, out, write_extra);
    loss_final_kernel<<<1, 256>>>(out, write_extra);

    // decoder — bf16 3-term MMA
    {
        dim3 g(HID / 128, B_ / 128);
        mmaps_gemm<1, 1><<<g, 256>>>(zqh, zql, d1h, d1l, d1, nullptr,
                                     h1h, h1l, B_, HID, LAT);
    }
    {
        dim3 g(HID / 128, B_ / 128);
        mmaps_gemm<1, 1><<<g, 256>>>(h1h, h1l, d2h, d2l, d2, nullptr,
                                     h2h, h2l, B_, HID, HID);
    }
    {
        dim3 g(DIN / 128, B_ / 128);
        mmaps_gemm<0, 1><<<g, 256>>>(h2h, h2l, d3h, d3l, d3, out,
                                     nullptr, nullptr, B_, DIN, HID);
    }
}

// round 13
// speedup vs baseline: 1.9919x; 1.1601x over previous
#include <cuda_runtime.h>
#include <cuda_bf16.h>
#include <cuda_fp16.h>
#include <math.h>
#include <stdint.h>

#define B_   8192
#define DIN  1024
#define HID  2048
#define LAT  256
#define KC   4096

typedef unsigned long long ull;

// ---------------- scratch (device globals; no allocation allowed) ----------
__device__ __align__(128) float g_h1[(size_t)B_ * HID];
__device__ __align__(128) float g_h2[(size_t)B_ * HID];
__device__ __align__(128) float g_ze[(size_t)B_ * LAT];
__device__ float g_zsq[B_];
__device__ float g_esq[KC];
__device__ float g_rowloss[B_];
__device__ int   g_idx[B_];
// decoder presplit (bf16x2 k-pairs)
__device__ __align__(128) uint32_t g_zqh[(size_t)B_ * (LAT/2)];
__device__ __align__(128) uint32_t g_zql[(size_t)B_ * (LAT/2)];
__device__ __align__(128) uint32_t g_d1h[(size_t)HID * (LAT/2)];
__device__ __align__(128) uint32_t g_d1l[(size_t)HID * (LAT/2)];
__device__ __align__(128) uint32_t g_d2h[(size_t)HID * (HID/2)];
__device__ __align__(128) uint32_t g_d2l[(size_t)HID * (HID/2)];
__device__ __align__(128) uint32_t g_d3h[(size_t)DIN * (HID/2)];
__device__ __align__(128) uint32_t g_d3l[(size_t)DIN * (HID/2)];
// encoder presplit (fp16x2 k-pairs)
__device__ __align__(128) uint32_t g_xh[(size_t)B_ * (DIN/2)];
__device__ __align__(128) uint32_t g_xl[(size_t)B_ * (DIN/2)];
__device__ __align__(128) uint32_t g_w1h[(size_t)HID * (DIN/2)];
__device__ __align__(128) uint32_t g_w1l[(size_t)HID * (DIN/2)];
__device__ __align__(128) uint32_t g_w2h[(size_t)HID * (HID/2)];
__device__ __align__(128) uint32_t g_w2l[(size_t)HID * (HID/2)];
__device__ __align__(128) uint32_t g_w3h[(size_t)LAT * (HID/2)];
__device__ __align__(128) uint32_t g_w3l[(size_t)LAT * (HID/2)];
// dist path (fp16 splits; embed scaled by 4096)
__device__ __align__(128) uint32_t g_zeh[(size_t)B_ * (LAT/2)];
__device__ __align__(128) uint32_t g_zel[(size_t)B_ * (LAT/2)];
__device__ __align__(128) uint32_t g_eh[(size_t)KC * (LAT/2)];
__device__ __align__(128) uint32_t g_el[(size_t)KC * (LAT/2)];
__device__ float g_pv[(size_t)B_ * 32];
__device__ int   g_pi[(size_t)B_ * 32];

__device__ __forceinline__ float gelu_exact(float x) {
    return 0.5f * x * (1.0f + erff(x * 0.7071067811865476f));
}

// ---- bf16 split ----
__device__ __forceinline__ uint32_t pack2bf(__nv_bfloat16 a, __nv_bfloat16 b) {
    __nv_bfloat162 v(a, b);
    return *reinterpret_cast<uint32_t*>(&v);
}
__device__ __forceinline__ void split_bf(float x, __nv_bfloat16& h, __nv_bfloat16& l) {
    h = __float2bfloat16_rn(x);
    l = __float2bfloat16_rn(x - __bfloat162float(h));
}
__device__ __forceinline__ uint32_t split_pair_hi(float x0, float x1) {
    __nv_bfloat16 h0, l0, h1, l1;
    split_bf(x0, h0, l0); split_bf(x1, h1, l1);
    return pack2bf(h0, h1);
}
__device__ __forceinline__ uint32_t split_pair_lo(float x0, float x1) {
    __nv_bfloat16 h0, l0, h1, l1;
    split_bf(x0, h0, l0); split_bf(x1, h1, l1);
    return pack2bf(l0, l1);
}

// ---- fp16 split ----
__device__ __forceinline__ uint32_t pack2hf(__half a, __half b) {
    __half2 v = __halves2half2(a, b);
    return *reinterpret_cast<uint32_t*>(&v);
}
__device__ __forceinline__ void split_hf(float x, __half& h, __half& l) {
    h = __float2half_rn(x);
    l = __float2half_rn(x - __half2float(h));
}
__device__ __forceinline__ uint32_t split_pair_hi_hf(float x0, float x1) {
    __half h0, l0, h1, l1;
    split_hf(x0, h0, l0); split_hf(x1, h1, l1);
    return pack2hf(h0, h1);
}
__device__ __forceinline__ uint32_t split_pair_lo_hf(float x0, float x1) {
    __half h0, l0, h1, l1;
    split_hf(x0, h0, l0); split_hf(x1, h1, l1);
    return pack2hf(l0, l1);
}

// ---- warp MMAs ----
__device__ __forceinline__ void mma16b(float* d, const uint32_t* a, const uint32_t* b) {
    asm("mma.sync.aligned.m16n8k16.row.col.f32.bf16.bf16.f32 "
        "{%0,%1,%2,%3}, {%4,%5,%6,%7}, {%8,%9}, {%0,%1,%2,%3};"
        : "+f"(d[0]), "+f"(d[1]), "+f"(d[2]), "+f"(d[3])
        : "r"(a[0]), "r"(a[1]), "r"(a[2]), "r"(a[3]), "r"(b[0]), "r"(b[1]));
}
__device__ __forceinline__ void mma16h(float* d, const uint32_t* a, const uint32_t* b) {
    asm("mma.sync.aligned.m16n8k16.row.col.f32.f16.f16.f32 "
        "{%0,%1,%2,%3}, {%4,%5,%6,%7}, {%8,%9}, {%0,%1,%2,%3};"
        : "+f"(d[0]), "+f"(d[1]), "+f"(d[2]), "+f"(d[3])
        : "r"(a[0]), "r"(a[1]), "r"(a[2]), "r"(a[3]), "r"(b[0]), "r"(b[1]));
}

__device__ __forceinline__ void upd_best(float& bv, int& bi, float v, int c) {
    if (v < bv || (v == bv && c < bi)) { bv = v; bi = c; }
}

// ---- cp.async helpers ----
__device__ __forceinline__ void cp16(uint32_t smem_dst, const void* gmem_src) {
    asm volatile("cp.async.cg.shared.global [%0], [%1], 16;"
                 :: "r"(smem_dst), "l"(gmem_src));
}
#define CP_COMMIT() asm volatile("cp.async.commit_group;" ::: "memory")
#define CP_WAIT1()  asm volatile("cp.async.wait_group 1;" ::: "memory")
#define CP_WAIT0()  asm volatile("cp.async.wait_group 0;" ::: "memory")

// ================= pipelined presplit 3-term MMA GEMM (2 CTAs/SM) ==========
// 2-stage cp.async ring in dynamic smem (2 x 40KB). MMA order identical to
// Round 12 (bitwise-identical outputs).
#define LDA 20                       // u32 row stride (16 kp + 4 pad)
#define ST_A_HI 0
#define ST_A_LO 2560
#define ST_B_HI 5120
#define ST_B_LO 7680
#define STAGE_U32 10240              // 40 KB
#define PIPE_SMEM (2 * STAGE_U32 * 4)

// MODE 0: fp32 out. MODE 1: gelu + split out. MODE 2: fp32 out + fp16 split out.
template<int MODE, int BF>
__global__ void __launch_bounds__(256, 2) mmaps_gemm(
    const uint32_t* __restrict__ Ah_g, const uint32_t* __restrict__ Al_g,
    const uint32_t* __restrict__ Bh_g, const uint32_t* __restrict__ Bl_g,
    const float* __restrict__ bias, float* __restrict__ C,
    uint32_t* __restrict__ Oh, uint32_t* __restrict__ Ol,
    int M, int N, int K)
{
    extern __shared__ uint32_t smu[];
    const uint32_t sb = (uint32_t)__cvta_generic_to_shared(smu);

    const int tid  = threadIdx.x;
    const int wid  = tid >> 5;
    const int lane = tid & 31;
    const int g = lane >> 2;
    const int t = lane & 3;
    const int warp_m = wid & 1;
    const int warp_n = wid >> 1;
    const int bm = blockIdx.y * 128;
    const int bn = blockIdx.x * 128;
    const int Kp = K >> 1;

    float acc[4][4][4];
#pragma unroll
    for (int i = 0; i < 4; i++)
#pragma unroll
        for (int j = 0; j < 4; j++)
#pragma unroll
            for (int r = 0; r < 4; r++) acc[i][j][r] = 0.0f;

    const int fr = tid >> 1;
    const int fo = (tid & 1) * 8;
    const uint32_t* pAh = Ah_g + (size_t)(bm + fr) * Kp + fo;
    const uint32_t* pAl = Al_g + (size_t)(bm + fr) * Kp + fo;
    const uint32_t* pBh = Bh_g + (size_t)(bn + fr) * Kp + fo;
    const uint32_t* pBl = Bl_g + (size_t)(bn + fr) * Kp + fo;
    const uint32_t dst0 = sb + (uint32_t)(fr * LDA + fo) * 4;

    const int nt = K / 32;

    // prologue: stage 0
    {
        cp16(dst0,                 pAh);     cp16(dst0 + 16,                 pAh + 4);
        cp16(dst0 + ST_A_LO * 4,   pAl);     cp16(dst0 + ST_A_LO * 4 + 16,   pAl + 4);
        cp16(dst0 + ST_B_HI * 4,   pBh);     cp16(dst0 + ST_B_HI * 4 + 16,   pBh + 4);
        cp16(dst0 + ST_B_LO * 4,   pBl);     cp16(dst0 + ST_B_LO * 4 + 16,   pBl + 4);
        CP_COMMIT();
    }

    for (int kt = 0; kt < nt; kt++) {
        if (kt + 1 < nt) {
            const int off = (kt + 1) * 16;
            const uint32_t d = dst0 + (uint32_t)(((kt + 1) & 1) * STAGE_U32) * 4;
            cp16(d,               pAh + off);   cp16(d + 16,               pAh + off + 4);
            cp16(d + ST_A_LO * 4, pAl + off);   cp16(d + ST_A_LO * 4 + 16, pAl + off + 4);
            cp16(d + ST_B_HI * 4, pBh + off);   cp16(d + ST_B_HI * 4 + 16, pBh + off + 4);
            cp16(d + ST_B_LO * 4, pBl + off);   cp16(d + ST_B_LO * 4 + 16, pBl + off + 4);
            CP_COMMIT();
            CP_WAIT1();
        } else {
            CP_WAIT0();
        }
        __syncthreads();

        const uint32_t* Ah = smu + (kt & 1) * STAGE_U32 + ST_A_HI;
        const uint32_t* Al = smu + (kt & 1) * STAGE_U32 + ST_A_LO;
        const uint32_t* Bh = smu + (kt & 1) * STAGE_U32 + ST_B_HI;
        const uint32_t* Bl = smu + (kt & 1) * STAGE_U32 + ST_B_LO;

#pragma unroll
        for (int kk = 0; kk < 2; kk++) {
            const int ko = kk * 8;
            uint32_t ah[4][4], al[4][4], bh[4][2], bl[4][2];
#pragma unroll
            for (int im = 0; im < 4; im++) {
                int row = warp_m * 64 + im * 16 + g;
                int base = row * LDA + ko;
                ah[im][0] = Ah[base + t];
                ah[im][1] = Ah[base + 8 * LDA + t];
                ah[im][2] = Ah[base + t + 4];
                ah[im][3] = Ah[base + 8 * LDA + t + 4];
                al[im][0] = Al[base + t];
                al[im][1] = Al[base + 8 * LDA + t];
                al[im][2] = Al[base + t + 4];
                al[im][3] = Al[base + 8 * LDA + t + 4];
            }
#pragma unroll
            for (int jn = 0; jn < 4; jn++) {
                int n = warp_n * 32 + jn * 8 + g;
                int base = n * LDA + ko;
                bh[jn][0] = Bh[base + t];
                bh[jn][1] = Bh[base + t + 4];
                bl[jn][0] = Bl[base + t];
                bl[jn][1] = Bl[base + t + 4];
            }
#pragma unroll
            for (int im = 0; im < 4; im++)
#pragma unroll
                for (int jn = 0; jn < 4; jn++) {
                    if (BF) {
                        mma16b(acc[im][jn], al[im], bh[jn]);
                        mma16b(acc[im][jn], ah[im], bl[jn]);
                        mma16b(acc[im][jn], ah[im], bh[jn]);
                    } else {
                        mma16h(acc[im][jn], al[im], bh[jn]);
                        mma16h(acc[im][jn], ah[im], bl[jn]);
                        mma16h(acc[im][jn], ah[im], bh[jn]);
                    }
                }
        }
        __syncthreads();
    }

    // epilogue
#pragma unroll
    for (int im = 0; im < 4; im++) {
#pragma unroll
        for (int jn = 0; jn < 4; jn++) {
            int row = bm + warp_m * 64 + im * 16 + g;
            int col = bn + warp_n * 32 + jn * 8 + 2 * t;
            float bx = bias[col], by = bias[col + 1];
            float2 v0, v1;
            v0.x = acc[im][jn][0] + bx;
            v0.y = acc[im][jn][1] + by;
            v1.x = acc[im][jn][2] + bx;
            v1.y = acc[im][jn][3] + by;
            if (MODE == 1) {
                v0.x = gelu_exact(v0.x); v0.y = gelu_exact(v0.y);
                v1.x = gelu_exact(v1.x); v1.y = gelu_exact(v1.y);
                size_t o0 = (size_t)row * (N >> 1) + (col >> 1);
                size_t o1 = (size_t)(row + 8) * (N >> 1) + (col >> 1);
                if (BF) {
                    Oh[o0] = split_pair_hi(v0.x, v0.y);
                    Ol[o0] = split_pair_lo(v0.x, v0.y);
                    Oh[o1] = split_pair_hi(v1.x, v1.y);
                    Ol[o1] = split_pair_lo(v1.x, v1.y);
                } else {
                    Oh[o0] = split_pair_hi_hf(v0.x, v0.y);
                    Ol[o0] = split_pair_lo_hf(v0.x, v0.y);
                    Oh[o1] = split_pair_hi_hf(v1.x, v1.y);
                    Ol[o1] = split_pair_lo_hf(v1.x, v1.y);
                }
            } else if (MODE == 2) {
                *(float2*)&C[(size_t)row * N + col] = v0;
                *(float2*)&C[(size_t)(row + 8) * N + col] = v1;
                size_t o0 = (size_t)row * (N >> 1) + (col >> 1);
                size_t o1 = (size_t)(row + 8) * (N >> 1) + (col >> 1);
                Oh[o0] = split_pair_hi_hf(v0.x, v0.y);
                Ol[o0] = split_pair_lo_hf(v0.x, v0.y);
                Oh[o1] = split_pair_hi_hf(v1.x, v1.y);
                Ol[o1] = split_pair_lo_hf(v1.x, v1.y);
            } else {
                *(float2*)&C[(size_t)row * N + col] = v0;
                *(float2*)&C[(size_t)(row + 8) * N + col] = v1;
            }
        }
    }
}

// ================= dist MMA + fused argmin (pipelined) ======================
// Criterion identical to Round 12 (reference-rounded). Bitwise-identical.
__global__ void __launch_bounds__(256, 2) dist_mma_kernel(
    const uint32_t* __restrict__ Zh, const uint32_t* __restrict__ Zl,
    const uint32_t* __restrict__ Eh, const uint32_t* __restrict__ El,
    const float* __restrict__ zsq, const float* __restrict__ esq,
    float* __restrict__ pv, int* __restrict__ pi)
{
    extern __shared__ uint32_t smu[];
    const uint32_t sb = (uint32_t)__cvta_generic_to_shared(smu);

    const int tid  = threadIdx.x;
    const int wid  = tid >> 5;
    const int lane = tid & 31;
    const int g = lane >> 2;
    const int t = lane & 3;
    const int warp_m = wid & 1;
    const int warp_n = wid >> 1;
    const int bm = blockIdx.y * 128;   // z rows
    const int bn = blockIdx.x * 128;   // codes
    const int Kp = LAT >> 1;           // 128

    float acc[4][4][4];
#pragma unroll
    for (int i = 0; i < 4; i++)
#pragma unroll
        for (int j = 0; j < 4; j++)
#pragma unroll
            for (int r = 0; r < 4; r++) acc[i][j][r] = 0.0f;

    const int fr = tid >> 1;
    const int fo = (tid & 1) * 8;
    const uint32_t* pAh = Zh + (size_t)(bm + fr) * Kp + fo;
    const uint32_t* pAl = Zl + (size_t)(bm + fr) * Kp + fo;
    const uint32_t* pBh = Eh + (size_t)(bn + fr) * Kp + fo;
    const uint32_t* pBl = El + (size_t)(bn + fr) * Kp + fo;
    const uint32_t dst0 = sb + (uint32_t)(fr * LDA + fo) * 4;

    const int nt = LAT / 32;           // 8

    {
        cp16(dst0,                 pAh);     cp16(dst0 + 16,                 pAh + 4);
        cp16(dst0 + ST_A_LO * 4,   pAl);     cp16(dst0 + ST_A_LO * 4 + 16,   pAl + 4);
        cp16(dst0 + ST_B_HI * 4,   pBh);     cp16(dst0 + ST_B_HI * 4 + 16,   pBh + 4);
        cp16(dst0 + ST_B_LO * 4,   pBl);     cp16(dst0 + ST_B_LO * 4 + 16,   pBl + 4);
        CP_COMMIT();
    }

    for (int kt = 0; kt < nt; kt++) {
        if (kt + 1 < nt) {
            const int off = (kt + 1) * 16;
            const uint32_t d = dst0 + (uint32_t)(((kt + 1) & 1) * STAGE_U32) * 4;
            cp16(d,               pAh + off);   cp16(d + 16,               pAh + off + 4);
            cp16(d + ST_A_LO * 4, pAl + off);   cp16(d + ST_A_LO * 4 + 16, pAl + off + 4);
            cp16(d + ST_B_HI * 4, pBh + off);   cp16(d + ST_B_HI * 4 + 16, pBh + off + 4);
            cp16(d + ST_B_LO * 4, pBl + off);   cp16(d + ST_B_LO * 4 + 16, pBl + off + 4);
            CP_COMMIT();
            CP_WAIT1();
        } else {
            CP_WAIT0();
        }
        __syncthreads();

        const uint32_t* Ah = smu + (kt & 1) * STAGE_U32 + ST_A_HI;
        const uint32_t* Al = smu + (kt & 1) * STAGE_U32 + ST_A_LO;
        const uint32_t* Bh = smu + (kt & 1) * STAGE_U32 + ST_B_HI;
        const uint32_t* Bl = smu + (kt & 1) * STAGE_U32 + ST_B_LO;

#pragma unroll
        for (int kk = 0; kk < 2; kk++) {
            const int ko = kk * 8;
            uint32_t ah[4][4], al[4][4], bh[4][2], bl[4][2];
#pragma unroll
            for (int im = 0; im < 4; im++) {
                int row = warp_m * 64 + im * 16 + g;
                int base = row * LDA + ko;
                ah[im][0] = Ah[base + t];
                ah[im][1] = Ah[base + 8 * LDA + t];
                ah[im][2] = Ah[base + t + 4];
                ah[im][3] = Ah[base + 8 * LDA + t + 4];
                al[im][0] = Al[base + t];
                al[im][1] = Al[base + 8 * LDA + t];
                al[im][2] = Al[base + t + 4];
                al[im][3] = Al[base + 8 * LDA + t + 4];
            }
#pragma unroll
            for (int jn = 0; jn < 4; jn++) {
                int n = warp_n * 32 + jn * 8 + g;
                int base = n * LDA + ko;
                bh[jn][0] = Bh[base + t];
                bh[jn][1] = Bh[base + t + 4];
                bl[jn][0] = Bl[base + t];
                bl[jn][1] = Bl[base + t + 4];
            }
#pragma unroll
            for (int im = 0; im < 4; im++)
#pragma unroll
                for (int jn = 0; jn < 4; jn++) {
                    mma16h(acc[im][jn], al[im], bh[jn]);
                    mma16h(acc[im][jn], ah[im], bl[jn]);
                    mma16h(acc[im][jn], ah[im], bh[jn]);
                }
        }
        __syncthreads();
    }

    // fused argmin epilogue — reference criterion with exact 2^-12 rescale
    const float inv = 0.000244140625f;   // 2^-12
    float bv[4][2];
    int   bi[4][2];
    float zs0[4], zs1[4];
#pragma unroll
    for (int im = 0; im < 4; im++) {
        int r0 = bm + warp_m * 64 + im * 16 + g;
        zs0[im] = zsq[r0];
        zs1[im] = zsq[r0 + 8];
        bv[im][0] = INFINITY; bi[im][0] = 0x7fffffff;
        bv[im][1] = INFINITY; bi[im][1] = 0x7fffffff;
    }

#pragma unroll
    for (int im = 0; im < 4; im++) {
#pragma unroll
        for (int jn = 0; jn < 4; jn++) {
            int c0 = bn + warp_n * 32 + jn * 8 + 2 * t;
            float e0 = esq[c0], e1 = esq[c0 + 1];
            float t00 = zs0[im] + e0, t01 = zs0[im] + e1;
            float t10 = zs1[im] + e0, t11 = zs1[im] + e1;
            float d00 = fmaf(-2.0f, acc[im][jn][0] * inv, t00);
            float d01 = fmaf(-2.0f, acc[im][jn][1] * inv, t01);
            float d10 = fmaf(-2.0f, acc[im][jn][2] * inv, t10);
            float d11 = fmaf(-2.0f, acc[im][jn][3] * inv, t11);
            upd_best(bv[im][0], bi[im][0], d00, c0);
            upd_best(bv[im][0], bi[im][0], d01, c0 + 1);
            upd_best(bv[im][1], bi[im][1], d10, c0);
            upd_best(bv[im][1], bi[im][1], d11, c0 + 1);
        }
    }
#pragma unroll
    for (int im = 0; im < 4; im++)
#pragma unroll
        for (int h = 0; h < 2; h++) {
#pragma unroll
            for (int o = 2; o; o >>= 1) {
                float vv = __shfl_down_sync(0xffffffffu, bv[im][h], o, 4);
                int   cc = __shfl_down_sync(0xffffffffu, bi[im][h], o, 4);
                upd_best(bv[im][h], bi[im][h], vv, cc);
            }
        }

    // reuse stage smem for the cross-warp reduce (all MMA reads done)
    float* sval = (float*)smu;
    int*   sidx = (int*)(smu + 512);
    if (t == 0) {
#pragma unroll
        for (int im = 0; im < 4; im++)
#pragma unroll
            for (int h = 0; h < 2; h++) {
                int r = warp_m * 64 + im * 16 + g + h * 8;
                sval[warp_n * 128 + r] = bv[im][h];
                sidx[warp_n * 128 + r] = bi[im][h];
            }
    }
    __syncthreads();
    if (tid < 128) {
        float v = sval[tid];
        int   c = sidx[tid];
        for (int wn = 1; wn < 4; wn++)
            upd_best(v, c, sval[wn * 128 + tid], sidx[wn * 128 + tid]);
        size_t o = (size_t)(bm + tid) * 32 + blockIdx.x;
        pv[o] = v;
        pi[o] = c;
    }
}

__global__ void argmin_final_kernel(const float* __restrict__ pv,
                                    const int* __restrict__ pi)
{
    int r = blockIdx.x * blockDim.x + threadIdx.x;
    if (r >= B_) return;
    float bv = INFINITY;
    int   bi = 0x7fffffff;
    for (int cb = 0; cb < 32; cb++)
        upd_best(bv, bi, pv[(size_t)r * 32 + cb], pi[(size_t)r * 32 + cb]);
    g_idx[r] = bi;
}

// ================= prep kernels =============================================
__global__ void wsplit_kernel(const float* __restrict__ B, int K, int N,
                              uint32_t* __restrict__ Oh, uint32_t* __restrict__ Ol)
{
    __shared__ float t[64][33];
    const int n0 = blockIdx.x * 32;
    const int k0 = blockIdx.y * 64;
    const int tid = threadIdx.x;
#pragma unroll
    for (int i = 0; i < 8; i++) {
        int idx = tid + i * 256;
        int kk = idx >> 5, nn = idx & 31;
        t[kk][nn] = B[(size_t)(k0 + kk) * N + n0 + nn];
    }
    __syncthreads();
    const int Kp = K >> 1;
#pragma unroll
    for (int i = 0; i < 4; i++) {
        int idx = tid + i * 256;
        int nn = idx >> 5, kp = idx & 31;
        float x0 = t[2 * kp][nn], x1 = t[2 * kp + 1][nn];
        size_t o = (size_t)(n0 + nn) * Kp + (k0 >> 1) + kp;
        Oh[o] = split_pair_hi(x0, x1);
        Ol[o] = split_pair_lo(x0, x1);
    }
}

__global__ void wsplit_h_kernel(const float* __restrict__ B, int K, int N,
                                uint32_t* __restrict__ Oh, uint32_t* __restrict__ Ol)
{
    __shared__ float t[64][33];
    const int n0 = blockIdx.x * 32;
    const int k0 = blockIdx.y * 64;
    const int tid = threadIdx.x;
#pragma unroll
    for (int i = 0; i < 8; i++) {
        int idx = tid + i * 256;
        int kk = idx >> 5, nn = idx & 31;
        t[kk][nn] = B[(size_t)(k0 + kk) * N + n0 + nn];
    }
    __syncthreads();
    const int Kp = K >> 1;
#pragma unroll
    for (int i = 0; i < 4; i++) {
        int idx = tid + i * 256;
        int nn = idx >> 5, kp = idx & 31;
        float x0 = t[2 * kp][nn], x1 = t[2 * kp + 1][nn];
        size_t o = (size_t)(n0 + nn) * Kp + (k0 >> 1) + kp;
        Oh[o] = split_pair_hi_hf(x0, x1);
        Ol[o] = split_pair_lo_hf(x0, x1);
    }
}

__global__ void xsplit_kernel(const float* __restrict__ X,
                              uint32_t* __restrict__ Oh, uint32_t* __restrict__ Ol,
                              int total_pairs)
{
    int idx = blockIdx.x * blockDim.x + threadIdx.x;
    if (idx >= total_pairs) return;
    float2 v = *(const float2*)(X + 2 * (size_t)idx);
    Oh[idx] = split_pair_hi_hf(v.x, v.y);
    Ol[idx] = split_pair_lo_hf(v.x, v.y);
}

__global__ void esplit_kernel(const float* __restrict__ E,
                              uint32_t* __restrict__ Oh, uint32_t* __restrict__ Ol,
                              int total_pairs)
{
    int idx = blockIdx.x * blockDim.x + threadIdx.x;
    if (idx >= total_pairs) return;
    float2 v = *(const float2*)(E + 2 * (size_t)idx);
    float x0 = v.x * 4096.0f, x1 = v.y * 4096.0f;
    Oh[idx] = split_pair_hi_hf(x0, x1);
    Ol[idx] = split_pair_lo_hf(x0, x1);
}

// ---------------- per-row sum of squares (one warp per row) ----------------
__global__ void rowsumsq_kernel(const float* __restrict__ src,
                                float* __restrict__ out, int rows)
{
    int warp = (blockIdx.x * blockDim.x + threadIdx.x) >> 5;
    int lane = threadIdx.x & 31;
    if (warp >= rows) return;
    const float* p = src + (size_t)warp * LAT;
    float s = 0.0f;
#pragma unroll
    for (int i = 0; i < LAT; i += 32) {
        float v = p[i + lane];
        s = fmaf(v, v, s);
    }
#pragma unroll
    for (int o = 16; o; o >>= 1) s += __shfl_down_sync(0xffffffffu, s, o);
    if (lane == 0) out[warp] = s;
}

// ---------------- gather z_q (bf16 split), per-row loss, indices out -------
__global__ void gather_loss_kernel(const float* __restrict__ embed,
                                   float* __restrict__ out_f, int write_extra)
{
    int warp = (blockIdx.x * blockDim.x + threadIdx.x) >> 5;
    int lane = threadIdx.x & 31;
    if (warp >= B_) return;
    int idx = g_idx[warp];
    const float* ze = g_ze + (size_t)warp * LAT;
    const float* eq = embed + (size_t)idx * LAT;
    float s = 0.0f;
#pragma unroll
    for (int i = 0; i < LAT; i += 32) {
        float q = eq[i + lane];
        float z = ze[i + lane];
        float d = z - q;
        s = fmaf(d, d, s);
    }
#pragma unroll
    for (int o = 16; o; o >>= 1) s += __shfl_down_sync(0xffffffffu, s, o);
#pragma unroll
    for (int m = 0; m < LAT / 2; m += 32) {
        int kp = m + lane;
        float q0 = eq[2 * kp], q1 = eq[2 * kp + 1];
        g_zqh[(size_t)warp * (LAT / 2) + kp] = split_pair_hi(q0, q1);
        g_zql[(size_t)warp * (LAT / 2) + kp] = split_pair_lo(q0, q1);
    }
    if (lane == 0) {
        g_rowloss[warp] = s;
        if (write_extra)
            out_f[(size_t)B_ * DIN + 1 + warp] = (float)idx;
    }
}

// ---------------- final loss reduction --------------------------------------
__global__ void loss_final_kernel(float* __restrict__ out_f, int write_extra)
{
    __shared__ float sh[256];
    float s = 0.0f;
    for (int i = threadIdx.x; i < B_; i += 256) s += g_rowloss[i];
    sh[threadIdx.x] = s;
    __syncthreads();
    for (int o = 128; o; o >>= 1) {
        if (threadIdx.x < o) sh[threadIdx.x] += sh[threadIdx.x + o];
        __syncthreads();
    }
    if (threadIdx.x == 0 && write_extra) {
        out_f[(size_t)B_ * DIN] = 1.25f * sh[0] / (float)((size_t)B_ * LAT);
    }
}

// ---------------- launch ----------------------------------------------------
extern "C" void kernel_launch(void* const* d_in, const int* in_sizes, int n_in,
                              void* d_out, int out_size)
{
    const float* x     = (const float*)d_in[0];
    const float* W1    = (const float*)d_in[1];
    const float* b1    = (const float*)d_in[2];
    const float* W2    = (const float*)d_in[3];
    const float* b2    = (const float*)d_in[4];
    const float* W3    = (const float*)d_in[5];
    const float* b3    = (const float*)d_in[6];
    const float* embed = (const float*)d_in[7];
    const float* D1    = (const float*)d_in[8];
    const float* d1    = (const float*)d_in[9];
    const float* D2    = (const float*)d_in[10];
    const float* d2    = (const float*)d_in[11];
    const float* D3    = (const float*)d_in[12];
    const float* d3    = (const float*)d_in[13];
    float* out = (float*)d_out;

    float *h1, *h2, *ze, *zsq, *esq, *pv;
    int *pi;
    uint32_t *zqh, *zql, *d1h, *d1l, *d2h, *d2l, *d3h, *d3l;
    uint32_t *xh, *xl, *w1h, *w1l, *w2h, *w2l, *w3h, *w3l;
    uint32_t *zeh, *zel, *eh, *el;
    cudaGetSymbolAddress((void**)&h1,  g_h1);
    cudaGetSymbolAddress((void**)&h2,  g_h2);
    cudaGetSymbolAddress((void**)&ze,  g_ze);
    cudaGetSymbolAddress((void**)&zsq, g_zsq);
    cudaGetSymbolAddress((void**)&esq, g_esq);
    cudaGetSymbolAddress((void**)&zqh, g_zqh);
    cudaGetSymbolAddress((void**)&zql, g_zql);
    cudaGetSymbolAddress((void**)&d1h, g_d1h);
    cudaGetSymbolAddress((void**)&d1l, g_d1l);
    cudaGetSymbolAddress((void**)&d2h, g_d2h);
    cudaGetSymbolAddress((void**)&d2l, g_d2l);
    cudaGetSymbolAddress((void**)&d3h, g_d3h);
    cudaGetSymbolAddress((void**)&d3l, g_d3l);
    cudaGetSymbolAddress((void**)&xh,  g_xh);
    cudaGetSymbolAddress((void**)&xl,  g_xl);
    cudaGetSymbolAddress((void**)&w1h, g_w1h);
    cudaGetSymbolAddress((void**)&w1l, g_w1l);
    cudaGetSymbolAddress((void**)&w2h, g_w2h);
    cudaGetSymbolAddress((void**)&w2l, g_w2l);
    cudaGetSymbolAddress((void**)&w3h, g_w3h);
    cudaGetSymbolAddress((void**)&w3l, g_w3l);
    cudaGetSymbolAddress((void**)&zeh, g_zeh);
    cudaGetSymbolAddress((void**)&zel, g_zel);
    cudaGetSymbolAddress((void**)&eh,  g_eh);
    cudaGetSymbolAddress((void**)&el,  g_el);
    cudaGetSymbolAddress((void**)&pv,  g_pv);
    cudaGetSymbolAddress((void**)&pi,  g_pi);

    uint32_t* h1h = (uint32_t*)h1;
    uint32_t* h1l = h1h + (size_t)B_ * (HID / 2);
    uint32_t* h2h = (uint32_t*)h2;
    uint32_t* h2l = h2h + (size_t)B_ * (HID / 2);

    const int write_extra =
        ((size_t)out_size >= (size_t)B_ * DIN + 1 + B_) ? 1 : 0;

    cudaFuncSetAttribute(mmaps_gemm<0, 0>,
                         cudaFuncAttributeMaxDynamicSharedMemorySize, PIPE_SMEM);
    cudaFuncSetAttribute(mmaps_gemm<1, 0>,
                         cudaFuncAttributeMaxDynamicSharedMemorySize, PIPE_SMEM);
    cudaFuncSetAttribute(mmaps_gemm<2, 0>,
                         cudaFuncAttributeMaxDynamicSharedMemorySize, PIPE_SMEM);
    cudaFuncSetAttribute(mmaps_gemm<0, 1>,
                         cudaFuncAttributeMaxDynamicSharedMemorySize, PIPE_SMEM);
    cudaFuncSetAttribute(mmaps_gemm<1, 1>,
                         cudaFuncAttributeMaxDynamicSharedMemorySize, PIPE_SMEM);
    cudaFuncSetAttribute(dist_mma_kernel,
                         cudaFuncAttributeMaxDynamicSharedMemorySize, PIPE_SMEM);

    // presplit
    xsplit_kernel<<<(B_ * (DIN / 2)) / 256, 256>>>(x, xh, xl, B_ * (DIN / 2));
    wsplit_h_kernel<<<dim3(HID / 32, DIN / 64), 256>>>(W1, DIN, HID, w1h, w1l);
    wsplit_h_kernel<<<dim3(HID / 32, HID / 64), 256>>>(W2, HID, HID, w2h, w2l);
    wsplit_h_kernel<<<dim3(LAT / 32, HID / 64), 256>>>(W3, HID, LAT, w3h, w3l);
    wsplit_kernel<<<dim3(HID / 32, LAT / 64), 256>>>(D1, LAT, HID, d1h, d1l);
    wsplit_kernel<<<dim3(HID / 32, HID / 64), 256>>>(D2, HID, HID, d2h, d2l);
    wsplit_kernel<<<dim3(DIN / 32, HID / 64), 256>>>(D3, HID, DIN, d3h, d3l);
    esplit_kernel<<<(KC * (LAT / 2)) / 256, 256>>>(embed, eh, el, KC * (LAT / 2));
    rowsumsq_kernel<<<(KC * 32) / 256, 256>>>(embed, esq, KC);

    // encoder — fp16 2-way-split 3-term MMA (flip-free)
    {
        dim3 g(HID / 128, B_ / 128);
        mmaps_gemm<1, 0><<<g, 256, PIPE_SMEM>>>(xh, xl, w1h, w1l, b1, nullptr,
                                                h1h, h1l, B_, HID, DIN);
    }
    {
        dim3 g(HID / 128, B_ / 128);
        mmaps_gemm<1, 0><<<g, 256, PIPE_SMEM>>>(h1h, h1l, w2h, w2l, b2, nullptr,
                                                h2h, h2l, B_, HID, HID);
    }
    {
        dim3 g(LAT / 128, B_ / 128);
        mmaps_gemm<2, 0><<<g, 256, PIPE_SMEM>>>(h2h, h2l, w3h, w3l, b3, ze,
                                                zeh, zel, B_, LAT, HID);
    }

    // zsq on z_e (reference-rounded criterion)
    rowsumsq_kernel<<<(B_ * 32) / 256, 256>>>(ze, zsq, B_);

    // dist + argmin — fp16-split MMA, reference criterion
    {
        dim3 g(KC / 128, B_ / 128);
        dist_mma_kernel<<<g, 256, PIPE_SMEM>>>(zeh, zel, eh, el, zsq, esq, pv, pi);
    }
    argmin_final_kernel<<<B_ / 256, 256>>>(pv, pi);

    // gather (+ zq bf16 split) + loss
    gather_loss_kernel<<<(B_ * 32) / 256, 256>>>(embed, out, write_extra);
    loss_final_kernel<<<1, 256>>>(out, write_extra);

    // decoder — bf16 3-term MMA
    {
        dim3 g(HID / 128, B_ / 128);
        mmaps_gemm<1, 1><<<g, 256, PIPE_SMEM>>>(zqh, zql, d1h, d1l, d1, nullptr,
                                                h1h, h1l, B_, HID, LAT);
    }
    {
        dim3 g(HID / 128, B_ / 128);
        mmaps_gemm<1, 1><<<g, 256, PIPE_SMEM>>>(h1h, h1l, d2h, d2l, d2, nullptr,
                                                h2h, h2l, B_, HID, HID);
    }
    {
        dim3 g(DIN / 128, B_ / 128);
        mmaps_gemm<0, 1><<<g, 256, PIPE_SMEM>>>(h2h, h2l, d3h, d3l, d3, out,
                                                nullptr, nullptr, B_, DIN, HID);
    }
}

// round 15
// speedup vs baseline: 2.2226x; 1.1158x over previous
#include <cuda_runtime.h>
#include <cuda_bf16.h>
#include <cuda_fp16.h>
#include <math.h>
#include <stdint.h>

#define B_   8192
#define DIN  1024
#define HID  2048
#define LAT  256
#define KC   4096

typedef unsigned long long ull;

// ---------------- scratch (device globals; no allocation allowed) ----------
__device__ __align__(128) float g_h1[(size_t)B_ * HID];
__device__ __align__(128) float g_h2[(size_t)B_ * HID];
__device__ __align__(128) float g_ze[(size_t)B_ * LAT];
__device__ float g_zsq[B_];
__device__ float g_esq[KC];
__device__ float g_rowloss[B_];
__device__ int   g_idx[B_];
// decoder presplit (bf16x2 k-pairs)
__device__ __align__(128) uint32_t g_zqh[(size_t)B_ * (LAT/2)];
__device__ __align__(128) uint32_t g_zql[(size_t)B_ * (LAT/2)];
__device__ __align__(128) uint32_t g_d1h[(size_t)HID * (LAT/2)];
__device__ __align__(128) uint32_t g_d1l[(size_t)HID * (LAT/2)];
__device__ __align__(128) uint32_t g_d2h[(size_t)HID * (HID/2)];
__device__ __align__(128) uint32_t g_d2l[(size_t)HID * (HID/2)];
__device__ __align__(128) uint32_t g_d3h[(size_t)DIN * (HID/2)];
__device__ __align__(128) uint32_t g_d3l[(size_t)DIN * (HID/2)];
// encoder presplit (fp16x2 k-pairs)
__device__ __align__(128) uint32_t g_xh[(size_t)B_ * (DIN/2)];
__device__ __align__(128) uint32_t g_xl[(size_t)B_ * (DIN/2)];
__device__ __align__(128) uint32_t g_w1h[(size_t)HID * (DIN/2)];
__device__ __align__(128) uint32_t g_w1l[(size_t)HID * (DIN/2)];
__device__ __align__(128) uint32_t g_w2h[(size_t)HID * (HID/2)];
__device__ __align__(128) uint32_t g_w2l[(size_t)HID * (HID/2)];
__device__ __align__(128) uint32_t g_w3h[(size_t)LAT * (HID/2)];
__device__ __align__(128) uint32_t g_w3l[(size_t)LAT * (HID/2)];
// dist path (fp16 splits; embed scaled by 4096)
__device__ __align__(128) uint32_t g_zeh[(size_t)B_ * (LAT/2)];
__device__ __align__(128) uint32_t g_zel[(size_t)B_ * (LAT/2)];
__device__ __align__(128) uint32_t g_eh[(size_t)KC * (LAT/2)];
__device__ __align__(128) uint32_t g_el[(size_t)KC * (LAT/2)];
__device__ float g_pv[(size_t)B_ * 32];
__device__ int   g_pi[(size_t)B_ * 32];

__device__ __forceinline__ float gelu_exact(float x) {
    return 0.5f * x * (1.0f + erff(x * 0.7071067811865476f));
}

// ---- bf16 split ----
__device__ __forceinline__ uint32_t pack2bf(__nv_bfloat16 a, __nv_bfloat16 b) {
    __nv_bfloat162 v(a, b);
    return *reinterpret_cast<uint32_t*>(&v);
}
__device__ __forceinline__ void split_bf(float x, __nv_bfloat16& h, __nv_bfloat16& l) {
    h = __float2bfloat16_rn(x);
    l = __float2bfloat16_rn(x - __bfloat162float(h));
}
__device__ __forceinline__ uint32_t split_pair_hi(float x0, float x1) {
    __nv_bfloat16 h0, l0, h1, l1;
    split_bf(x0, h0, l0); split_bf(x1, h1, l1);
    return pack2bf(h0, h1);
}
__device__ __forceinline__ uint32_t split_pair_lo(float x0, float x1) {
    __nv_bfloat16 h0, l0, h1, l1;
    split_bf(x0, h0, l0); split_bf(x1, h1, l1);
    return pack2bf(l0, l1);
}

// ---- fp16 split ----
__device__ __forceinline__ uint32_t pack2hf(__half a, __half b) {
    __half2 v = __halves2half2(a, b);
    return *reinterpret_cast<uint32_t*>(&v);
}
__device__ __forceinline__ void split_hf(float x, __half& h, __half& l) {
    h = __float2half_rn(x);
    l = __float2half_rn(x - __half2float(h));
}
__device__ __forceinline__ uint32_t split_pair_hi_hf(float x0, float x1) {
    __half h0, l0, h1, l1;
    split_hf(x0, h0, l0); split_hf(x1, h1, l1);
    return pack2hf(h0, h1);
}
__device__ __forceinline__ uint32_t split_pair_lo_hf(float x0, float x1) {
    __half h0, l0, h1, l1;
    split_hf(x0, h0, l0); split_hf(x1, h1, l1);
    return pack2hf(l0, l1);
}

// ---- warp MMAs ----
__device__ __forceinline__ void mma16b(float* d, const uint32_t* a, const uint32_t* b) {
    asm("mma.sync.aligned.m16n8k16.row.col.f32.bf16.bf16.f32 "
        "{%0,%1,%2,%3}, {%4,%5,%6,%7}, {%8,%9}, {%0,%1,%2,%3};"
        : "+f"(d[0]), "+f"(d[1]), "+f"(d[2]), "+f"(d[3])
        : "r"(a[0]), "r"(a[1]), "r"(a[2]), "r"(a[3]), "r"(b[0]), "r"(b[1]));
}
__device__ __forceinline__ void mma16h(float* d, const uint32_t* a, const uint32_t* b) {
    asm("mma.sync.aligned.m16n8k16.row.col.f32.f16.f16.f32 "
        "{%0,%1,%2,%3}, {%4,%5,%6,%7}, {%8,%9}, {%0,%1,%2,%3};"
        : "+f"(d[0]), "+f"(d[1]), "+f"(d[2]), "+f"(d[3])
        : "r"(a[0]), "r"(a[1]), "r"(a[2]), "r"(a[3]), "r"(b[0]), "r"(b[1]));
}

__device__ __forceinline__ void upd_best(float& bv, int& bi, float v, int c) {
    if (v < bv || (v == bv && c < bi)) { bv = v; bi = c; }
}

// ---- cp.async helpers ----
__device__ __forceinline__ void cp16(uint32_t smem_dst, const void* gmem_src) {
    asm volatile("cp.async.cg.shared.global [%0], [%1], 16;"
                 :: "r"(smem_dst), "l"(gmem_src));
}
#define CP_COMMIT() asm volatile("cp.async.commit_group;" ::: "memory")
#define CP_WAIT1()  asm volatile("cp.async.wait_group 1;" ::: "memory")
#define CP_WAIT0()  asm volatile("cp.async.wait_group 0;" ::: "memory")

// ================= 3-stage pipelined presplit 3-term MMA GEMM ==============
// XOR-swizzled smem layout (row stride 16 u32, no pad):
//   element e of row r -> r*16 + ((e>>2) ^ ((r>>1)&3))*4 + (e&3)
// 16B-aligned cp.async dsts, conflict-free fragment LDS. One sync per k-tile:
// fill for stage kt+2 == stage kt-1 whose readers finished before the barrier.
#define ST_A_HI 0
#define ST_A_LO 2048
#define ST_B_HI 4096
#define ST_B_LO 6144
#define STAGE_U32 8192               // 32 KB
#define PIPE_SMEM (3 * STAGE_U32 * 4)   // 96 KB

// MODE 0: fp32 out. MODE 1: gelu + split out. MODE 2: fp32 out + fp16 split out.
template<int MODE, int BF>
__global__ void __launch_bounds__(256, 2) mmaps_gemm(
    const uint32_t* __restrict__ Ah_g, const uint32_t* __restrict__ Al_g,
    const uint32_t* __restrict__ Bh_g, const uint32_t* __restrict__ Bl_g,
    const float* __restrict__ bias, float* __restrict__ C,
    uint32_t* __restrict__ Oh, uint32_t* __restrict__ Ol,
    int M, int N, int K)
{
    extern __shared__ uint32_t smu[];
    const uint32_t sb = (uint32_t)__cvta_generic_to_shared(smu);

    const int tid  = threadIdx.x;
    const int wid  = tid >> 5;
    const int lane = tid & 31;
    const int g = lane >> 2;
    const int t = lane & 3;
    const int warp_m = wid & 1;
    const int warp_n = wid >> 1;
    const int bm = blockIdx.y * 128;
    const int bn = blockIdx.x * 128;
    const int Kp = K >> 1;

    float acc[4][4][4];
#pragma unroll
    for (int i = 0; i < 4; i++)
#pragma unroll
        for (int j = 0; j < 4; j++)
#pragma unroll
            for (int r = 0; r < 4; r++) acc[i][j][r] = 0.0f;

    const int fr = tid >> 1;              // row 0..127
    const int fo = (tid & 1) * 8;         // source u32 offset 0 or 8
    // swizzled destination chunk offsets (bytes) for this thread's two 16B chunks
    const int swf = (fr >> 1) & 3;
    const int cA  = (tid & 1) * 2;        // chunk 0 or 2
    const uint32_t dchunk0 = (uint32_t)(fr * 64 + ((cA     ^ swf) << 4));
    const uint32_t dchunk1 = (uint32_t)(fr * 64 + (((cA+1) ^ swf) << 4));

    const uint32_t* pAh = Ah_g + (size_t)(bm + fr) * Kp + fo;
    const uint32_t* pAl = Al_g + (size_t)(bm + fr) * Kp + fo;
    const uint32_t* pBh = Bh_g + (size_t)(bn + fr) * Kp + fo;
    const uint32_t* pBl = Bl_g + (size_t)(bn + fr) * Kp + fo;

    const int nt = K / 32;

#define FILL_STAGE(sidx, koff)                                                  \
    do {                                                                        \
        const uint32_t sbase = sb + (uint32_t)((sidx) * STAGE_U32) * 4;         \
        cp16(sbase + ST_A_HI * 4 + dchunk0, pAh + (koff));                      \
        cp16(sbase + ST_A_HI * 4 + dchunk1, pAh + (koff) + 4);                  \
        cp16(sbase + ST_A_LO * 4 + dchunk0, pAl + (koff));                      \
        cp16(sbase + ST_A_LO * 4 + dchunk1, pAl + (koff) + 4);                  \
        cp16(sbase + ST_B_HI * 4 + dchunk0, pBh + (koff));                      \
        cp16(sbase + ST_B_HI * 4 + dchunk1, pBh + (koff) + 4);                  \
        cp16(sbase + ST_B_LO * 4 + dchunk0, pBl + (koff));                      \
        cp16(sbase + ST_B_LO * 4 + dchunk1, pBl + (koff) + 4);                  \
        CP_COMMIT();                                                            \
    } while (0)

    // prologue: stages 0, 1
    FILL_STAGE(0, 0);
    FILL_STAGE(1, 16);

    int stage = 0;
    for (int kt = 0; kt < nt; kt++) {
        if (kt + 1 < nt) CP_WAIT1(); else CP_WAIT0();
        __syncthreads();

        if (kt + 2 < nt) {
            int s2 = stage + 2; if (s2 >= 3) s2 -= 3;
            FILL_STAGE(s2, (kt + 2) * 16);
        }

        const uint32_t* Ah = smu + stage * STAGE_U32 + ST_A_HI;
        const uint32_t* Al = smu + stage * STAGE_U32 + ST_A_LO;
        const uint32_t* Bh = smu + stage * STAGE_U32 + ST_B_HI;
        const uint32_t* Bl = smu + stage * STAGE_U32 + ST_B_LO;

#pragma unroll
        for (int kk = 0; kk < 2; kk++) {
            const int c0 = kk * 2;   // chunk of elements ko..ko+3 (ko = kk*8)
            uint32_t ah[4][4], al[4][4], bh[4][2], bl[4][2];
#pragma unroll
            for (int im = 0; im < 4; im++) {
                int row = warp_m * 64 + im * 16 + g;
                int swr = (row >> 1) & 3;
                int base = row * 16;
                int o0 = ((c0     ^ swr) << 2) + t;
                int o1 = (((c0+1) ^ swr) << 2) + t;
                ah[im][0] = Ah[base + o0];
                ah[im][1] = Ah[base + 128 + o0];
                ah[im][2] = Ah[base + o1];
                ah[im][3] = Ah[base + 128 + o1];
                al[im][0] = Al[base + o0];
                al[im][1] = Al[base + 128 + o0];
                al[im][2] = Al[base + o1];
                al[im][3] = Al[base + 128 + o1];
            }
#pragma unroll
            for (int jn = 0; jn < 4; jn++) {
                int n = warp_n * 32 + jn * 8 + g;
                int swn = (n >> 1) & 3;
                int base = n * 16;
                int o0 = ((c0     ^ swn) << 2) + t;
                int o1 = (((c0+1) ^ swn) << 2) + t;
                bh[jn][0] = Bh[base + o0];
                bh[jn][1] = Bh[base + o1];
                bl[jn][0] = Bl[base + o0];
                bl[jn][1] = Bl[base + o1];
            }
#pragma unroll
            for (int im = 0; im < 4; im++)
#pragma unroll
                for (int jn = 0; jn < 4; jn++) {
                    if (BF) {
                        mma16b(acc[im][jn], al[im], bh[jn]);
                        mma16b(acc[im][jn], ah[im], bl[jn]);
                        mma16b(acc[im][jn], ah[im], bh[jn]);
                    } else {
                        mma16h(acc[im][jn], al[im], bh[jn]);
                        mma16h(acc[im][jn], ah[im], bl[jn]);
                        mma16h(acc[im][jn], ah[im], bh[jn]);
                    }
                }
        }
        stage++; if (stage == 3) stage = 0;
    }

    // epilogue
#pragma unroll
    for (int im = 0; im < 4; im++) {
#pragma unroll
        for (int jn = 0; jn < 4; jn++) {
            int row = bm + warp_m * 64 + im * 16 + g;
            int col = bn + warp_n * 32 + jn * 8 + 2 * t;
            float bx = bias[col], by = bias[col + 1];
            float2 v0, v1;
            v0.x = acc[im][jn][0] + bx;
            v0.y = acc[im][jn][1] + by;
            v1.x = acc[im][jn][2] + bx;
            v1.y = acc[im][jn][3] + by;
            if (MODE == 1) {
                v0.x = gelu_exact(v0.x); v0.y = gelu_exact(v0.y);
                v1.x = gelu_exact(v1.x); v1.y = gelu_exact(v1.y);
                size_t o0 = (size_t)row * (N >> 1) + (col >> 1);
                size_t o1 = (size_t)(row + 8) * (N >> 1) + (col >> 1);
                if (BF) {
                    Oh[o0] = split_pair_hi(v0.x, v0.y);
                    Ol[o0] = split_pair_lo(v0.x, v0.y);
                    Oh[o1] = split_pair_hi(v1.x, v1.y);
                    Ol[o1] = split_pair_lo(v1.x, v1.y);
                } else {
                    Oh[o0] = split_pair_hi_hf(v0.x, v0.y);
                    Ol[o0] = split_pair_lo_hf(v0.x, v0.y);
                    Oh[o1] = split_pair_hi_hf(v1.x, v1.y);
                    Ol[o1] = split_pair_lo_hf(v1.x, v1.y);
                }
            } else if (MODE == 2) {
                *(float2*)&C[(size_t)row * N + col] = v0;
                *(float2*)&C[(size_t)(row + 8) * N + col] = v1;
                size_t o0 = (size_t)row * (N >> 1) + (col >> 1);
                size_t o1 = (size_t)(row + 8) * (N >> 1) + (col >> 1);
                Oh[o0] = split_pair_hi_hf(v0.x, v0.y);
                Ol[o0] = split_pair_lo_hf(v0.x, v0.y);
                Oh[o1] = split_pair_hi_hf(v1.x, v1.y);
                Ol[o1] = split_pair_lo_hf(v1.x, v1.y);
            } else {
                *(float2*)&C[(size_t)row * N + col] = v0;
                *(float2*)&C[(size_t)(row + 8) * N + col] = v1;
            }
        }
    }
#undef FILL_STAGE
}

// ================= dist MMA + fused argmin (3-stage, swizzled) ==============
__global__ void __launch_bounds__(256, 2) dist_mma_kernel(
    const uint32_t* __restrict__ Zh, const uint32_t* __restrict__ Zl,
    const uint32_t* __restrict__ Eh, const uint32_t* __restrict__ El,
    const float* __restrict__ zsq, const float* __restrict__ esq,
    float* __restrict__ pv, int* __restrict__ pi)
{
    extern __shared__ uint32_t smu[];
    const uint32_t sb = (uint32_t)__cvta_generic_to_shared(smu);

    const int tid  = threadIdx.x;
    const int wid  = tid >> 5;
    const int lane = tid & 31;
    const int g = lane >> 2;
    const int t = lane & 3;
    const int warp_m = wid & 1;
    const int warp_n = wid >> 1;
    const int bm = blockIdx.y * 128;
    const int bn = blockIdx.x * 128;
    const int Kp = LAT >> 1;

    float acc[4][4][4];
#pragma unroll
    for (int i = 0; i < 4; i++)
#pragma unroll
        for (int j = 0; j < 4; j++)
#pragma unroll
            for (int r = 0; r < 4; r++) acc[i][j][r] = 0.0f;

    const int fr = tid >> 1;
    const int fo = (tid & 1) * 8;
    const int swf = (fr >> 1) & 3;
    const int cA  = (tid & 1) * 2;
    const uint32_t dchunk0 = (uint32_t)(fr * 64 + ((cA     ^ swf) << 4));
    const uint32_t dchunk1 = (uint32_t)(fr * 64 + (((cA+1) ^ swf) << 4));

    const uint32_t* pAh = Zh + (size_t)(bm + fr) * Kp + fo;
    const uint32_t* pAl = Zl + (size_t)(bm + fr) * Kp + fo;
    const uint32_t* pBh = Eh + (size_t)(bn + fr) * Kp + fo;
    const uint32_t* pBl = El + (size_t)(bn + fr) * Kp + fo;

    const int nt = LAT / 32;   // 8

#define FILL_STAGE_D(sidx, koff)                                                \
    do {                                                                        \
        const uint32_t sbase = sb + (uint32_t)((sidx) * STAGE_U32) * 4;         \
        cp16(sbase + ST_A_HI * 4 + dchunk0, pAh + (koff));                      \
        cp16(sbase + ST_A_HI * 4 + dchunk1, pAh + (koff) + 4);                  \
        cp16(sbase + ST_A_LO * 4 + dchunk0, pAl + (koff));                      \
        cp16(sbase + ST_A_LO * 4 + dchunk1, pAl + (koff) + 4);                  \
        cp16(sbase + ST_B_HI * 4 + dchunk0, pBh + (koff));                      \
        cp16(sbase + ST_B_HI * 4 + dchunk1, pBh + (koff) + 4);                  \
        cp16(sbase + ST_B_LO * 4 + dchunk0, pBl + (koff));                      \
        cp16(sbase + ST_B_LO * 4 + dchunk1, pBl + (koff) + 4);                  \
        CP_COMMIT();                                                            \
    } while (0)

    FILL_STAGE_D(0, 0);
    FILL_STAGE_D(1, 16);

    int stage = 0;
    for (int kt = 0; kt < nt; kt++) {
        if (kt + 1 < nt) CP_WAIT1(); else CP_WAIT0();
        __syncthreads();

        if (kt + 2 < nt) {
            int s2 = stage + 2; if (s2 >= 3) s2 -= 3;
            FILL_STAGE_D(s2, (kt + 2) * 16);
        }

        const uint32_t* Ah = smu + stage * STAGE_U32 + ST_A_HI;
        const uint32_t* Al = smu + stage * STAGE_U32 + ST_A_LO;
        const uint32_t* Bh = smu + stage * STAGE_U32 + ST_B_HI;
        const uint32_t* Bl = smu + stage * STAGE_U32 + ST_B_LO;

#pragma unroll
        for (int kk = 0; kk < 2; kk++) {
            const int c0 = kk * 2;
            uint32_t ah[4][4], al[4][4], bh[4][2], bl[4][2];
#pragma unroll
            for (int im = 0; im < 4; im++) {
                int row = warp_m * 64 + im * 16 + g;
                int swr = (row >> 1) & 3;
                int base = row * 16;
                int o0 = ((c0     ^ swr) << 2) + t;
                int o1 = (((c0+1) ^ swr) << 2) + t;
                ah[im][0] = Ah[base + o0];
                ah[im][1] = Ah[base + 128 + o0];
                ah[im][2] = Ah[base + o1];
                ah[im][3] = Ah[base + 128 + o1];
                al[im][0] = Al[base + o0];
                al[im][1] = Al[base + 128 + o0];
                al[im][2] = Al[base + o1];
                al[im][3] = Al[base + 128 + o1];
            }
#pragma unroll
            for (int jn = 0; jn < 4; jn++) {
                int n = warp_n * 32 + jn * 8 + g;
                int swn = (n >> 1) & 3;
                int base = n * 16;
                int o0 = ((c0     ^ swn) << 2) + t;
                int o1 = (((c0+1) ^ swn) << 2) + t;
                bh[jn][0] = Bh[base + o0];
                bh[jn][1] = Bh[base + o1];
                bl[jn][0] = Bl[base + o0];
                bl[jn][1] = Bl[base + o1];
            }
#pragma unroll
            for (int im = 0; im < 4; im++)
#pragma unroll
                for (int jn = 0; jn < 4; jn++) {
                    mma16h(acc[im][jn], al[im], bh[jn]);
                    mma16h(acc[im][jn], ah[im], bl[jn]);
                    mma16h(acc[im][jn], ah[im], bh[jn]);
                }
        }
        stage++; if (stage == 3) stage = 0;
    }

    // fused argmin epilogue — reference criterion with exact 2^-12 rescale
    const float inv = 0.000244140625f;
    float bv[4][2];
    int   bi[4][2];
    float zs0[4], zs1[4];
#pragma unroll
    for (int im = 0; im < 4; im++) {
        int r0 = bm + warp_m * 64 + im * 16 + g;
        zs0[im] = zsq[r0];
        zs1[im] = zsq[r0 + 8];
        bv[im][0] = INFINITY; bi[im][0] = 0x7fffffff;
        bv[im][1] = INFINITY; bi[im][1] = 0x7fffffff;
    }

#pragma unroll
    for (int im = 0; im < 4; im++) {
#pragma unroll
        for (int jn = 0; jn < 4; jn++) {
            int c0 = bn + warp_n * 32 + jn * 8 + 2 * t;
            float e0 = esq[c0], e1 = esq[c0 + 1];
            float t00 = zs0[im] + e0, t01 = zs0[im] + e1;
            float t10 = zs1[im] + e0, t11 = zs1[im] + e1;
            float d00 = fmaf(-2.0f, acc[im][jn][0] * inv, t00);
            float d01 = fmaf(-2.0f, acc[im][jn][1] * inv, t01);
            float d10 = fmaf(-2.0f, acc[im][jn][2] * inv, t10);
            float d11 = fmaf(-2.0f, acc[im][jn][3] * inv, t11);
            upd_best(bv[im][0], bi[im][0], d00, c0);
            upd_best(bv[im][0], bi[im][0], d01, c0 + 1);
            upd_best(bv[im][1], bi[im][1], d10, c0);
            upd_best(bv[im][1], bi[im][1], d11, c0 + 1);
        }
    }
#pragma unroll
    for (int im = 0; im < 4; im++)
#pragma unroll
        for (int h = 0; h < 2; h++) {
#pragma unroll
            for (int o = 2; o; o >>= 1) {
                float vv = __shfl_down_sync(0xffffffffu, bv[im][h], o, 4);
                int   cc = __shfl_down_sync(0xffffffffu, bi[im][h], o, 4);
                upd_best(bv[im][h], bi[im][h], vv, cc);
            }
        }

    float* sval = (float*)smu;
    int*   sidx = (int*)(smu + 512);
    __syncthreads();
    if (t == 0) {
#pragma unroll
        for (int im = 0; im < 4; im++)
#pragma unroll
            for (int h = 0; h < 2; h++) {
                int r = warp_m * 64 + im * 16 + g + h * 8;
                sval[warp_n * 128 + r] = bv[im][h];
                sidx[warp_n * 128 + r] = bi[im][h];
            }
    }
    __syncthreads();
    if (tid < 128) {
        float v = sval[tid];
        int   c = sidx[tid];
        for (int wn = 1; wn < 4; wn++)
            upd_best(v, c, sval[wn * 128 + tid], sidx[wn * 128 + tid]);
        size_t o = (size_t)(bm + tid) * 32 + blockIdx.x;
        pv[o] = v;
        pi[o] = c;
    }
#undef FILL_STAGE_D
}

__global__ void argmin_final_kernel(const float* __restrict__ pv,
                                    const int* __restrict__ pi)
{
    int r = blockIdx.x * blockDim.x + threadIdx.x;
    if (r >= B_) return;
    float bv = INFINITY;
    int   bi = 0x7fffffff;
    for (int cb = 0; cb < 32; cb++)
        upd_best(bv, bi, pv[(size_t)r * 32 + cb], pi[(size_t)r * 32 + cb]);
    g_idx[r] = bi;
}

// ================= prep kernels =============================================
__global__ void wsplit_kernel(const float* __restrict__ B, int K, int N,
                              uint32_t* __restrict__ Oh, uint32_t* __restrict__ Ol)
{
    __shared__ float t[64][33];
    const int n0 = blockIdx.x * 32;
    const int k0 = blockIdx.y * 64;
    const int tid = threadIdx.x;
#pragma unroll
    for (int i = 0; i < 8; i++) {
        int idx = tid + i * 256;
        int kk = idx >> 5, nn = idx & 31;
        t[kk][nn] = B[(size_t)(k0 + kk) * N + n0 + nn];
    }
    __syncthreads();
    const int Kp = K >> 1;
#pragma unroll
    for (int i = 0; i < 4; i++) {
        int idx = tid + i * 256;
        int nn = idx >> 5, kp = idx & 31;
        float x0 = t[2 * kp][nn], x1 = t[2 * kp + 1][nn];
        size_t o = (size_t)(n0 + nn) * Kp + (k0 >> 1) + kp;
        Oh[o] = split_pair_hi(x0, x1);
        Ol[o] = split_pair_lo(x0, x1);
    }
}

__global__ void wsplit_h_kernel(const float* __restrict__ B, int K, int N,
                                uint32_t* __restrict__ Oh, uint32_t* __restrict__ Ol)
{
    __shared__ float t[64][33];
    const int n0 = blockIdx.x * 32;
    const int k0 = blockIdx.y * 64;
    const int tid = threadIdx.x;
#pragma unroll
    for (int i = 0; i < 8; i++) {
        int idx = tid + i * 256;
        int kk = idx >> 5, nn = idx & 31;
        t[kk][nn] = B[(size_t)(k0 + kk) * N + n0 + nn];
    }
    __syncthreads();
    const int Kp = K >> 1;
#pragma unroll
    for (int i = 0; i < 4; i++) {
        int idx = tid + i * 256;
        int nn = idx >> 5, kp = idx & 31;
        float x0 = t[2 * kp][nn], x1 = t[2 * kp + 1][nn];
        size_t o = (size_t)(n0 + nn) * Kp + (k0 >> 1) + kp;
        Oh[o] = split_pair_hi_hf(x0, x1);
        Ol[o] = split_pair_lo_hf(x0, x1);
    }
}

__global__ void xsplit_kernel(const float* __restrict__ X,
                              uint32_t* __restrict__ Oh, uint32_t* __restrict__ Ol,
                              int total_pairs)
{
    int idx = blockIdx.x * blockDim.x + threadIdx.x;
    if (idx >= total_pairs) return;
    float2 v = *(const float2*)(X + 2 * (size_t)idx);
    Oh[idx] = split_pair_hi_hf(v.x, v.y);
    Ol[idx] = split_pair_lo_hf(v.x, v.y);
}

__global__ void esplit_kernel(const float* __restrict__ E,
                              uint32_t* __restrict__ Oh, uint32_t* __restrict__ Ol,
                              int total_pairs)
{
    int idx = blockIdx.x * blockDim.x + threadIdx.x;
    if (idx >= total_pairs) return;
    float2 v = *(const float2*)(E + 2 * (size_t)idx);
    float x0 = v.x * 4096.0f, x1 = v.y * 4096.0f;
    Oh[idx] = split_pair_hi_hf(x0, x1);
    Ol[idx] = split_pair_lo_hf(x0, x1);
}

// ---------------- per-row sum of squares (one warp per row) ----------------
__global__ void rowsumsq_kernel(const float* __restrict__ src,
                                float* __restrict__ out, int rows)
{
    int warp = (blockIdx.x * blockDim.x + threadIdx.x) >> 5;
    int lane = threadIdx.x & 31;
    if (warp >= rows) return;
    const float* p = src + (size_t)warp * LAT;
    float s = 0.0f;
#pragma unroll
    for (int i = 0; i < LAT; i += 32) {
        float v = p[i + lane];
        s = fmaf(v, v, s);
    }
#pragma unroll
    for (int o = 16; o; o >>= 1) s += __shfl_down_sync(0xffffffffu, s, o);
    if (lane == 0) out[warp] = s;
}

// ---------------- gather z_q (bf16 split), per-row loss, indices out -------
__global__ void gather_loss_kernel(const float* __restrict__ embed,
                                   float* __restrict__ out_f, int write_extra)
{
    int warp = (blockIdx.x * blockDim.x + threadIdx.x) >> 5;
    int lane = threadIdx.x & 31;
    if (warp >= B_) return;
    int idx = g_idx[warp];
    const float* ze = g_ze + (size_t)warp * LAT;
    const float* eq = embed + (size_t)idx * LAT;
    float s = 0.0f;
#pragma unroll
    for (int i = 0; i < LAT; i += 32) {
        float q = eq[i + lane];
        float z = ze[i + lane];
        float d = z - q;
        s = fmaf(d, d, s);
    }
#pragma unroll
    for (int o = 16; o; o >>= 1) s += __shfl_down_sync(0xffffffffu, s, o);
#pragma unroll
    for (int m = 0; m < LAT / 2; m += 32) {
        int kp = m + lane;
        float q0 = eq[2 * kp], q1 = eq[2 * kp + 1];
        g_zqh[(size_t)warp * (LAT / 2) + kp] = split_pair_hi(q0, q1);
        g_zql[(size_t)warp * (LAT / 2) + kp] = split_pair_lo(q0, q1);
    }
    if (lane == 0) {
        g_rowloss[warp] = s;
        if (write_extra)
            out_f[(size_t)B_ * DIN + 1 + warp] = (float)idx;
    }
}

// ---------------- final loss reduction --------------------------------------
__global__ void loss_final_kernel(float* __restrict__ out_f, int write_extra)
{
    __shared__ float sh[256];
    float s = 0.0f;
    for (int i = threadIdx.x; i < B_; i += 256) s += g_rowloss[i];
    sh[threadIdx.x] = s;
    __syncthreads();
    for (int o = 128; o; o >>= 1) {
        if (threadIdx.x < o) sh[threadIdx.x] += sh[threadIdx.x + o];
        __syncthreads();
    }
    if (threadIdx.x == 0 && write_extra) {
        out_f[(size_t)B_ * DIN] = 1.25f * sh[0] / (float)((size_t)B_ * LAT);
    }
}

// ---------------- launch ----------------------------------------------------
extern "C" void kernel_launch(void* const* d_in, const int* in_sizes, int n_in,
                              void* d_out, int out_size)
{
    const float* x     = (const float*)d_in[0];
    const float* W1    = (const float*)d_in[1];
    const float* b1    = (const float*)d_in[2];
    const float* W2    = (const float*)d_in[3];
    const float* b2    = (const float*)d_in[4];
    const float* W3    = (const float*)d_in[5];
    const float* b3    = (const float*)d_in[6];
    const float* embed = (const float*)d_in[7];
    const float* D1    = (const float*)d_in[8];
    const float* d1    = (const float*)d_in[9];
    const float* D2    = (const float*)d_in[10];
    const float* d2    = (const float*)d_in[11];
    const float* D3    = (const float*)d_in[12];
    const float* d3    = (const float*)d_in[13];
    float* out = (float*)d_out;

    float *h1, *h2, *ze, *zsq, *esq, *pv;
    int *pi;
    uint32_t *zqh, *zql, *d1h, *d1l, *d2h, *d2l, *d3h, *d3l;
    uint32_t *xh, *xl, *w1h, *w1l, *w2h, *w2l, *w3h, *w3l;
    uint32_t *zeh, *zel, *eh, *el;
    cudaGetSymbolAddress((void**)&h1,  g_h1);
    cudaGetSymbolAddress((void**)&h2,  g_h2);
    cudaGetSymbolAddress((void**)&ze,  g_ze);
    cudaGetSymbolAddress((void**)&zsq, g_zsq);
    cudaGetSymbolAddress((void**)&esq, g_esq);
    cudaGetSymbolAddress((void**)&zqh, g_zqh);
    cudaGetSymbolAddress((void**)&zql, g_zql);
    cudaGetSymbolAddress((void**)&d1h, g_d1h);
    cudaGetSymbolAddress((void**)&d1l, g_d1l);
    cudaGetSymbolAddress((void**)&d2h, g_d2h);
    cudaGetSymbolAddress((void**)&d2l, g_d2l);
    cudaGetSymbolAddress((void**)&d3h, g_d3h);
    cudaGetSymbolAddress((void**)&d3l, g_d3l);
    cudaGetSymbolAddress((void**)&xh,  g_xh);
    cudaGetSymbolAddress((void**)&xl,  g_xl);
    cudaGetSymbolAddress((void**)&w1h, g_w1h);
    cudaGetSymbolAddress((void**)&w1l, g_w1l);
    cudaGetSymbolAddress((void**)&w2h, g_w2h);
    cudaGetSymbolAddress((void**)&w2l, g_w2l);
    cudaGetSymbolAddress((void**)&w3h, g_w3h);
    cudaGetSymbolAddress((void**)&w3l, g_w3l);
    cudaGetSymbolAddress((void**)&zeh, g_zeh);
    cudaGetSymbolAddress((void**)&zel, g_zel);
    cudaGetSymbolAddress((void**)&eh,  g_eh);
    cudaGetSymbolAddress((void**)&el,  g_el);
    cudaGetSymbolAddress((void**)&pv,  g_pv);
    cudaGetSymbolAddress((void**)&pi,  g_pi);

    uint32_t* h1h = (uint32_t*)h1;
    uint32_t* h1l = h1h + (size_t)B_ * (HID / 2);
    uint32_t* h2h = (uint32_t*)h2;
    uint32_t* h2l = h2h + (size_t)B_ * (HID / 2);

    const int write_extra =
        ((size_t)out_size >= (size_t)B_ * DIN + 1 + B_) ? 1 : 0;

    cudaFuncSetAttribute(mmaps_gemm<0, 0>,
                         cudaFuncAttributeMaxDynamicSharedMemorySize, PIPE_SMEM);
    cudaFuncSetAttribute(mmaps_gemm<1, 0>,
                         cudaFuncAttributeMaxDynamicSharedMemorySize, PIPE_SMEM);
    cudaFuncSetAttribute(mmaps_gemm<2, 0>,
                         cudaFuncAttributeMaxDynamicSharedMemorySize, PIPE_SMEM);
    cudaFuncSetAttribute(mmaps_gemm<0, 1>,
                         cudaFuncAttributeMaxDynamicSharedMemorySize, PIPE_SMEM);
    cudaFuncSetAttribute(mmaps_gemm<1, 1>,
                         cudaFuncAttributeMaxDynamicSharedMemorySize, PIPE_SMEM);
    cudaFuncSetAttribute(dist_mma_kernel,
                         cudaFuncAttributeMaxDynamicSharedMemorySize, PIPE_SMEM);

    // presplit
    xsplit_kernel<<<(B_ * (DIN / 2)) / 256, 256>>>(x, xh, xl, B_ * (DIN / 2));
    wsplit_h_kernel<<<dim3(HID / 32, DIN / 64), 256>>>(W1, DIN, HID, w1h, w1l);
    wsplit_h_kernel<<<dim3(HID / 32, HID / 64), 256>>>(W2, HID, HID, w2h, w2l);
    wsplit_h_kernel<<<dim3(LAT / 32, HID / 64), 256>>>(W3, HID, LAT, w3h, w3l);
    wsplit_kernel<<<dim3(HID / 32, LAT / 64), 256>>>(D1, LAT, HID, d1h, d1l);
    wsplit_kernel<<<dim3(HID / 32, HID / 64), 256>>>(D2, HID, HID, d2h, d2l);
    wsplit_kernel<<<dim3(DIN / 32, HID / 64), 256>>>(D3, HID, DIN, d3h, d3l);
    esplit_kernel<<<(KC * (LAT / 2)) / 256, 256>>>(embed, eh, el, KC * (LAT / 2));
    rowsumsq_kernel<<<(KC * 32) / 256, 256>>>(embed, esq, KC);

    // encoder — fp16 2-way-split 3-term MMA (flip-free)
    {
        dim3 g(HID / 128, B_ / 128);
        mmaps_gemm<1, 0><<<g, 256, PIPE_SMEM>>>(xh, xl, w1h, w1l, b1, nullptr,
                                                h1h, h1l, B_, HID, DIN);
    }
    {
        dim3 g(HID / 128, B_ / 128);
        mmaps_gemm<1, 0><<<g, 256, PIPE_SMEM>>>(h1h, h1l, w2h, w2l, b2, nullptr,
                                                h2h, h2l, B_, HID, HID);
    }
    {
        dim3 g(LAT / 128, B_ / 128);
        mmaps_gemm<2, 0><<<g, 256, PIPE_SMEM>>>(h2h, h2l, w3h, w3l, b3, ze,
                                                zeh, zel, B_, LAT, HID);
    }

    // zsq on z_e (reference-rounded criterion)
    rowsumsq_kernel<<<(B_ * 32) / 256, 256>>>(ze, zsq, B_);

    // dist + argmin — fp16-split MMA, reference criterion
    {
        dim3 g(KC / 128, B_ / 128);
        dist_mma_kernel<<<g, 256, PIPE_SMEM>>>(zeh, zel, eh, el, zsq, esq, pv, pi);
    }
    argmin_final_kernel<<<B_ / 256, 256>>>(pv, pi);

    // gather (+ zq bf16 split) + loss
    gather_loss_kernel<<<(B_ * 32) / 256, 256>>>(embed, out, write_extra);
    loss_final_kernel<<<1, 256>>>(out, write_extra);

    // decoder — bf16 3-term MMA
    {
        dim3 g(HID / 128, B_ / 128);
        mmaps_gemm<1, 1><<<g, 256, PIPE_SMEM>>>(zqh, zql, d1h, d1l, d1, nullptr,
                                                h1h, h1l, B_, HID, LAT);
    }
    {
        dim3 g(HID / 128, B_ / 128);
        mmaps_gemm<1, 1><<<g, 256, PIPE_SMEM>>>(h1h, h1l, d2h, d2l, d2, nullptr,
                                                h2h, h2l, B_, HID, HID);
    }
    {
        dim3 g(DIN / 128, B_ / 128);
        mmaps_gemm<0, 1><<<g, 256, PIPE_SMEM>>>(h2h, h2l, d3h, d3l, d3, out,
                                                nullptr, nullptr, B_, DIN, HID);
    }
}

// round 16
// speedup vs baseline: 2.5477x; 1.1463x over previous
#include <cuda_runtime.h>
#include <cuda_bf16.h>
#include <cuda_fp16.h>
#include <math.h>
#include <stdint.h>

#define B_   8192
#define DIN  1024
#define HID  2048
#define LAT  256
#define KC   4096

typedef unsigned long long ull;

// ---------------- scratch (device globals; no allocation allowed) ----------
__device__ __align__(128) float g_h1[(size_t)B_ * HID];
__device__ __align__(128) float g_h2[(size_t)B_ * HID];
__device__ __align__(128) float g_ze[(size_t)B_ * LAT];
__device__ float g_zsq[B_];
__device__ float g_esq[KC];
__device__ float g_rowloss[B_];
__device__ int   g_idx[B_];
// decoder presplit (fp16x2 k-pairs; zq scaled by 4096)
__device__ __align__(128) uint32_t g_zqh[(size_t)B_ * (LAT/2)];
__device__ __align__(128) uint32_t g_zql[(size_t)B_ * (LAT/2)];
__device__ __align__(128) uint32_t g_d1h[(size_t)HID * (LAT/2)];
__device__ __align__(128) uint32_t g_d1l[(size_t)HID * (LAT/2)];
__device__ __align__(128) uint32_t g_d2h[(size_t)HID * (HID/2)];
__device__ __align__(128) uint32_t g_d2l[(size_t)HID * (HID/2)];
__device__ __align__(128) uint32_t g_d3h[(size_t)DIN * (HID/2)];
__device__ __align__(128) uint32_t g_d3l[(size_t)DIN * (HID/2)];
// encoder presplit (fp16x2 k-pairs)
__device__ __align__(128) uint32_t g_xh[(size_t)B_ * (DIN/2)];
__device__ __align__(128) uint32_t g_xl[(size_t)B_ * (DIN/2)];
__device__ __align__(128) uint32_t g_w1h[(size_t)HID * (DIN/2)];
__device__ __align__(128) uint32_t g_w1l[(size_t)HID * (DIN/2)];
__device__ __align__(128) uint32_t g_w2h[(size_t)HID * (HID/2)];
__device__ __align__(128) uint32_t g_w2l[(size_t)HID * (HID/2)];
__device__ __align__(128) uint32_t g_w3h[(size_t)LAT * (HID/2)];
__device__ __align__(128) uint32_t g_w3l[(size_t)LAT * (HID/2)];
// dist path (fp16 splits; embed scaled by 4096)
__device__ __align__(128) uint32_t g_zeh[(size_t)B_ * (LAT/2)];
__device__ __align__(128) uint32_t g_zel[(size_t)B_ * (LAT/2)];
__device__ __align__(128) uint32_t g_eh[(size_t)KC * (LAT/2)];
__device__ __align__(128) uint32_t g_el[(size_t)KC * (LAT/2)];
__device__ float g_pv[(size_t)B_ * 32];
__device__ int   g_pi[(size_t)B_ * 32];

__device__ __forceinline__ float gelu_exact(float x) {
    return 0.5f * x * (1.0f + erff(x * 0.7071067811865476f));
}

// ---- fp16 split ----
__device__ __forceinline__ uint32_t pack2hf(__half a, __half b) {
    __half2 v = __halves2half2(a, b);
    return *reinterpret_cast<uint32_t*>(&v);
}
__device__ __forceinline__ void split_hf(float x, __half& h, __half& l) {
    h = __float2half_rn(x);
    l = __float2half_rn(x - __half2float(h));
}
__device__ __forceinline__ uint32_t split_pair_hi_hf(float x0, float x1) {
    __half h0, l0, h1, l1;
    split_hf(x0, h0, l0); split_hf(x1, h1, l1);
    return pack2hf(h0, h1);
}
__device__ __forceinline__ uint32_t split_pair_lo_hf(float x0, float x1) {
    __half h0, l0, h1, l1;
    split_hf(x0, h0, l0); split_hf(x1, h1, l1);
    return pack2hf(l0, l1);
}

// ---- warp MMA (fp16) ----
__device__ __forceinline__ void mma16h(float* d, const uint32_t* a, const uint32_t* b) {
    asm("mma.sync.aligned.m16n8k16.row.col.f32.f16.f16.f32 "
        "{%0,%1,%2,%3}, {%4,%5,%6,%7}, {%8,%9}, {%0,%1,%2,%3};"
        : "+f"(d[0]), "+f"(d[1]), "+f"(d[2]), "+f"(d[3])
        : "r"(a[0]), "r"(a[1]), "r"(a[2]), "r"(a[3]), "r"(b[0]), "r"(b[1]));
}

__device__ __forceinline__ void upd_best(float& bv, int& bi, float v, int c) {
    if (v < bv || (v == bv && c < bi)) { bv = v; bi = c; }
}

// ---- cp.async helpers ----
__device__ __forceinline__ void cp16(uint32_t smem_dst, const void* gmem_src) {
    asm volatile("cp.async.cg.shared.global [%0], [%1], 16;"
                 :: "r"(smem_dst), "l"(gmem_src));
}
#define CP_COMMIT() asm volatile("cp.async.commit_group;" ::: "memory")
#define CP_WAIT1()  asm volatile("cp.async.wait_group 1;" ::: "memory")
#define CP_WAIT0()  asm volatile("cp.async.wait_group 0;" ::: "memory")

// ================= 3-stage pipelined presplit fp16 MMA GEMM =================
// XOR-swizzled smem (row stride 16 u32): e of row r -> r*16 + ((e>>2)^((r>>1)&3))*4 + (e&3)
// TERMS=3: al*bh + ah*bl + ah*bh (exact-ish; encoder/dist class)
// TERMS=2: al*bh + ah*bh = a*bh  (decoder; skips Bl buffer entirely)
// MODE 0: fp32 out. MODE 1: gelu + fp16 split out. MODE 2: fp32 + fp16 split out.
// SCALE 1: acc *= 2^-12 before bias (undoes zq 4096 pre-scale; exact).
#define ST_A_HI 0
#define ST_A_LO 2048
#define ST_B_HI 4096
#define ST_B_LO 6144
#define STAGE_U32 8192               // 32 KB
#define PIPE_SMEM (3 * STAGE_U32 * 4)   // 96 KB

template<int MODE, int TERMS, int SCALE>
__global__ void __launch_bounds__(256, 2) mmaps_gemm(
    const uint32_t* __restrict__ Ah_g, const uint32_t* __restrict__ Al_g,
    const uint32_t* __restrict__ Bh_g, const uint32_t* __restrict__ Bl_g,
    const float* __restrict__ bias, float* __restrict__ C,
    uint32_t* __restrict__ Oh, uint32_t* __restrict__ Ol,
    int M, int N, int K)
{
    extern __shared__ uint32_t smu[];
    const uint32_t sb = (uint32_t)__cvta_generic_to_shared(smu);

    const int tid  = threadIdx.x;
    const int wid  = tid >> 5;
    const int lane = tid & 31;
    const int g = lane >> 2;
    const int t = lane & 3;
    const int warp_m = wid & 1;
    const int warp_n = wid >> 1;
    const int bm = blockIdx.y * 128;
    const int bn = blockIdx.x * 128;
    const int Kp = K >> 1;

    float acc[4][4][4];
#pragma unroll
    for (int i = 0; i < 4; i++)
#pragma unroll
        for (int j = 0; j < 4; j++)
#pragma unroll
            for (int r = 0; r < 4; r++) acc[i][j][r] = 0.0f;

    const int fr = tid >> 1;
    const int fo = (tid & 1) * 8;
    const int swf = (fr >> 1) & 3;
    const int cA  = (tid & 1) * 2;
    const uint32_t dchunk0 = (uint32_t)(fr * 64 + ((cA     ^ swf) << 4));
    const uint32_t dchunk1 = (uint32_t)(fr * 64 + (((cA+1) ^ swf) << 4));

    const uint32_t* pAh = Ah_g + (size_t)(bm + fr) * Kp + fo;
    const uint32_t* pAl = Al_g + (size_t)(bm + fr) * Kp + fo;
    const uint32_t* pBh = Bh_g + (size_t)(bn + fr) * Kp + fo;
    const uint32_t* pBl = (TERMS == 3) ? (Bl_g + (size_t)(bn + fr) * Kp + fo) : nullptr;

    const int nt = K / 32;

#define FILL_STAGE(sidx, koff)                                                  \
    do {                                                                        \
        const uint32_t sbase = sb + (uint32_t)((sidx) * STAGE_U32) * 4;         \
        cp16(sbase + ST_A_HI * 4 + dchunk0, pAh + (koff));                      \
        cp16(sbase + ST_A_HI * 4 + dchunk1, pAh + (koff) + 4);                  \
        cp16(sbase + ST_A_LO * 4 + dchunk0, pAl + (koff));                      \
        cp16(sbase + ST_A_LO * 4 + dchunk1, pAl + (koff) + 4);                  \
        cp16(sbase + ST_B_HI * 4 + dchunk0, pBh + (koff));                      \
        cp16(sbase + ST_B_HI * 4 + dchunk1, pBh + (koff) + 4);                  \
        if (TERMS == 3) {                                                       \
            cp16(sbase + ST_B_LO * 4 + dchunk0, pBl + (koff));                  \
            cp16(sbase + ST_B_LO * 4 + dchunk1, pBl + (koff) + 4);              \
        }                                                                       \
        CP_COMMIT();                                                            \
    } while (0)

    FILL_STAGE(0, 0);
    FILL_STAGE(1, 16);

    int stage = 0;
    for (int kt = 0; kt < nt; kt++) {
        if (kt + 1 < nt) CP_WAIT1(); else CP_WAIT0();
        __syncthreads();

        if (kt + 2 < nt) {
            int s2 = stage + 2; if (s2 >= 3) s2 -= 3;
            FILL_STAGE(s2, (kt + 2) * 16);
        }

        const uint32_t* Ah = smu + stage * STAGE_U32 + ST_A_HI;
        const uint32_t* Al = smu + stage * STAGE_U32 + ST_A_LO;
        const uint32_t* Bh = smu + stage * STAGE_U32 + ST_B_HI;
        const uint32_t* Bl = smu + stage * STAGE_U32 + ST_B_LO;

#pragma unroll
        for (int kk = 0; kk < 2; kk++) {
            const int c0 = kk * 2;
            uint32_t ah[4][4], al[4][4], bh[4][2], bl[4][2];
#pragma unroll
            for (int im = 0; im < 4; im++) {
                int row = warp_m * 64 + im * 16 + g;
                int swr = (row >> 1) & 3;
                int base = row * 16;
                int o0 = ((c0     ^ swr) << 2) + t;
                int o1 = (((c0+1) ^ swr) << 2) + t;
                ah[im][0] = Ah[base + o0];
                ah[im][1] = Ah[base + 128 + o0];
                ah[im][2] = Ah[base + o1];
                ah[im][3] = Ah[base + 128 + o1];
                al[im][0] = Al[base + o0];
                al[im][1] = Al[base + 128 + o0];
                al[im][2] = Al[base + o1];
                al[im][3] = Al[base + 128 + o1];
            }
#pragma unroll
            for (int jn = 0; jn < 4; jn++) {
                int n = warp_n * 32 + jn * 8 + g;
                int swn = (n >> 1) & 3;
                int base = n * 16;
                int o0 = ((c0     ^ swn) << 2) + t;
                int o1 = (((c0+1) ^ swn) << 2) + t;
                bh[jn][0] = Bh[base + o0];
                bh[jn][1] = Bh[base + o1];
                if (TERMS == 3) {
                    bl[jn][0] = Bl[base + o0];
                    bl[jn][1] = Bl[base + o1];
                }
            }
#pragma unroll
            for (int im = 0; im < 4; im++)
#pragma unroll
                for (int jn = 0; jn < 4; jn++) {
                    mma16h(acc[im][jn], al[im], bh[jn]);
                    if (TERMS == 3)
                        mma16h(acc[im][jn], ah[im], bl[jn]);
                    mma16h(acc[im][jn], ah[im], bh[jn]);
                }
        }
        stage++; if (stage == 3) stage = 0;
    }

    // epilogue
    const float sc = SCALE ? 0.000244140625f : 1.0f;   // 2^-12 exact
#pragma unroll
    for (int im = 0; im < 4; im++) {
#pragma unroll
        for (int jn = 0; jn < 4; jn++) {
            int row = bm + warp_m * 64 + im * 16 + g;
            int col = bn + warp_n * 32 + jn * 8 + 2 * t;
            float bx = bias[col], by = bias[col + 1];
            float2 v0, v1;
            v0.x = acc[im][jn][0] * sc + bx;
            v0.y = acc[im][jn][1] * sc + by;
            v1.x = acc[im][jn][2] * sc + bx;
            v1.y = acc[im][jn][3] * sc + by;
            if (MODE == 1) {
                v0.x = gelu_exact(v0.x); v0.y = gelu_exact(v0.y);
                v1.x = gelu_exact(v1.x); v1.y = gelu_exact(v1.y);
                size_t o0 = (size_t)row * (N >> 1) + (col >> 1);
                size_t o1 = (size_t)(row + 8) * (N >> 1) + (col >> 1);
                Oh[o0] = split_pair_hi_hf(v0.x, v0.y);
                Ol[o0] = split_pair_lo_hf(v0.x, v0.y);
                Oh[o1] = split_pair_hi_hf(v1.x, v1.y);
                Ol[o1] = split_pair_lo_hf(v1.x, v1.y);
            } else if (MODE == 2) {
                *(float2*)&C[(size_t)row * N + col] = v0;
                *(float2*)&C[(size_t)(row + 8) * N + col] = v1;
                size_t o0 = (size_t)row * (N >> 1) + (col >> 1);
                size_t o1 = (size_t)(row + 8) * (N >> 1) + (col >> 1);
                Oh[o0] = split_pair_hi_hf(v0.x, v0.y);
                Ol[o0] = split_pair_lo_hf(v0.x, v0.y);
                Oh[o1] = split_pair_hi_hf(v1.x, v1.y);
                Ol[o1] = split_pair_lo_hf(v1.x, v1.y);
            } else {
                *(float2*)&C[(size_t)row * N + col] = v0;
                *(float2*)&C[(size_t)(row + 8) * N + col] = v1;
            }
        }
    }
#undef FILL_STAGE
}

// ================= dist MMA + fused argmin (3-stage, swizzled) ==============
__global__ void __launch_bounds__(256, 2) dist_mma_kernel(
    const uint32_t* __restrict__ Zh, const uint32_t* __restrict__ Zl,
    const uint32_t* __restrict__ Eh, const uint32_t* __restrict__ El,
    const float* __restrict__ zsq, const float* __restrict__ esq,
    float* __restrict__ pv, int* __restrict__ pi)
{
    extern __shared__ uint32_t smu[];
    const uint32_t sb = (uint32_t)__cvta_generic_to_shared(smu);

    const int tid  = threadIdx.x;
    const int wid  = tid >> 5;
    const int lane = tid & 31;
    const int g = lane >> 2;
    const int t = lane & 3;
    const int warp_m = wid & 1;
    const int warp_n = wid >> 1;
    const int bm = blockIdx.y * 128;
    const int bn = blockIdx.x * 128;
    const int Kp = LAT >> 1;

    float acc[4][4][4];
#pragma unroll
    for (int i = 0; i < 4; i++)
#pragma unroll
        for (int j = 0; j < 4; j++)
#pragma unroll
            for (int r = 0; r < 4; r++) acc[i][j][r] = 0.0f;

    const int fr = tid >> 1;
    const int fo = (tid & 1) * 8;
    const int swf = (fr >> 1) & 3;
    const int cA  = (tid & 1) * 2;
    const uint32_t dchunk0 = (uint32_t)(fr * 64 + ((cA     ^ swf) << 4));
    const uint32_t dchunk1 = (uint32_t)(fr * 64 + (((cA+1) ^ swf) << 4));

    const uint32_t* pAh = Zh + (size_t)(bm + fr) * Kp + fo;
    const uint32_t* pAl = Zl + (size_t)(bm + fr) * Kp + fo;
    const uint32_t* pBh = Eh + (size_t)(bn + fr) * Kp + fo;
    const uint32_t* pBl = El + (size_t)(bn + fr) * Kp + fo;

    const int nt = LAT / 32;   // 8

#define FILL_STAGE_D(sidx, koff)                                                \
    do {                                                                        \
        const uint32_t sbase = sb + (uint32_t)((sidx) * STAGE_U32) * 4;         \
        cp16(sbase + ST_A_HI * 4 + dchunk0, pAh + (koff));                      \
        cp16(sbase + ST_A_HI * 4 + dchunk1, pAh + (koff) + 4);                  \
        cp16(sbase + ST_A_LO * 4 + dchunk0, pAl + (koff));                      \
        cp16(sbase + ST_A_LO * 4 + dchunk1, pAl + (koff) + 4);                  \
        cp16(sbase + ST_B_HI * 4 + dchunk0, pBh + (koff));                      \
        cp16(sbase + ST_B_HI * 4 + dchunk1, pBh + (koff) + 4);                  \
        cp16(sbase + ST_B_LO * 4 + dchunk0, pBl + (koff));                      \
        cp16(sbase + ST_B_LO * 4 + dchunk1, pBl + (koff) + 4);                  \
        CP_COMMIT();                                                            \
    } while (0)

    FILL_STAGE_D(0, 0);
    FILL_STAGE_D(1, 16);

    int stage = 0;
    for (int kt = 0; kt < nt; kt++) {
        if (kt + 1 < nt) CP_WAIT1(); else CP_WAIT0();
        __syncthreads();

        if (kt + 2 < nt) {
            int s2 = stage + 2; if (s2 >= 3) s2 -= 3;
            FILL_STAGE_D(s2, (kt + 2) * 16);
        }

        const uint32_t* Ah = smu + stage * STAGE_U32 + ST_A_HI;
        const uint32_t* Al = smu + stage * STAGE_U32 + ST_A_LO;
        const uint32_t* Bh = smu + stage * STAGE_U32 + ST_B_HI;
        const uint32_t* Bl = smu + stage * STAGE_U32 + ST_B_LO;

#pragma unroll
        for (int kk = 0; kk < 2; kk++) {
            const int c0 = kk * 2;
            uint32_t ah[4][4], al[4][4], bh[4][2], bl[4][2];
#pragma unroll
            for (int im = 0; im < 4; im++) {
                int row = warp_m * 64 + im * 16 + g;
                int swr = (row >> 1) & 3;
                int base = row * 16;
                int o0 = ((c0     ^ swr) << 2) + t;
                int o1 = (((c0+1) ^ swr) << 2) + t;
                ah[im][0] = Ah[base + o0];
                ah[im][1] = Ah[base + 128 + o0];
                ah[im][2] = Ah[base + o1];
                ah[im][3] = Ah[base + 128 + o1];
                al[im][0] = Al[base + o0];
                al[im][1] = Al[base + 128 + o0];
                al[im][2] = Al[base + o1];
                al[im][3] = Al[base + 128 + o1];
            }
#pragma unroll
            for (int jn = 0; jn < 4; jn++) {
                int n = warp_n * 32 + jn * 8 + g;
                int swn = (n >> 1) & 3;
                int base = n * 16;
                int o0 = ((c0     ^ swn) << 2) + t;
                int o1 = (((c0+1) ^ swn) << 2) + t;
                bh[jn][0] = Bh[base + o0];
                bh[jn][1] = Bh[base + o1];
                bl[jn][0] = Bl[base + o0];
                bl[jn][1] = Bl[base + o1];
            }
#pragma unroll
            for (int im = 0; im < 4; im++)
#pragma unroll
                for (int jn = 0; jn < 4; jn++) {
                    mma16h(acc[im][jn], al[im], bh[jn]);
                    mma16h(acc[im][jn], ah[im], bl[jn]);
                    mma16h(acc[im][jn], ah[im], bh[jn]);
                }
        }
        stage++; if (stage == 3) stage = 0;
    }

    // fused argmin epilogue — reference criterion with exact 2^-12 rescale
    const float inv = 0.000244140625f;
    float bv[4][2];
    int   bi[4][2];
    float zs0[4], zs1[4];
#pragma unroll
    for (int im = 0; im < 4; im++) {
        int r0 = bm + warp_m * 64 + im * 16 + g;
        zs0[im] = zsq[r0];
        zs1[im] = zsq[r0 + 8];
        bv[im][0] = INFINITY; bi[im][0] = 0x7fffffff;
        bv[im][1] = INFINITY; bi[im][1] = 0x7fffffff;
    }

#pragma unroll
    for (int im = 0; im < 4; im++) {
#pragma unroll
        for (int jn = 0; jn < 4; jn++) {
            int c0 = bn + warp_n * 32 + jn * 8 + 2 * t;
            float e0 = esq[c0], e1 = esq[c0 + 1];
            float t00 = zs0[im] + e0, t01 = zs0[im] + e1;
            float t10 = zs1[im] + e0, t11 = zs1[im] + e1;
            float d00 = fmaf(-2.0f, acc[im][jn][0] * inv, t00);
            float d01 = fmaf(-2.0f, acc[im][jn][1] * inv, t01);
            float d10 = fmaf(-2.0f, acc[im][jn][2] * inv, t10);
            float d11 = fmaf(-2.0f, acc[im][jn][3] * inv, t11);
            upd_best(bv[im][0], bi[im][0], d00, c0);
            upd_best(bv[im][0], bi[im][0], d01, c0 + 1);
            upd_best(bv[im][1], bi[im][1], d10, c0);
            upd_best(bv[im][1], bi[im][1], d11, c0 + 1);
        }
    }
#pragma unroll
    for (int im = 0; im < 4; im++)
#pragma unroll
        for (int h = 0; h < 2; h++) {
#pragma unroll
            for (int o = 2; o; o >>= 1) {
                float vv = __shfl_down_sync(0xffffffffu, bv[im][h], o, 4);
                int   cc = __shfl_down_sync(0xffffffffu, bi[im][h], o, 4);
                upd_best(bv[im][h], bi[im][h], vv, cc);
            }
        }

    float* sval = (float*)smu;
    int*   sidx = (int*)(smu + 512);
    __syncthreads();
    if (t == 0) {
#pragma unroll
        for (int im = 0; im < 4; im++)
#pragma unroll
            for (int h = 0; h < 2; h++) {
                int r = warp_m * 64 + im * 16 + g + h * 8;
                sval[warp_n * 128 + r] = bv[im][h];
                sidx[warp_n * 128 + r] = bi[im][h];
            }
    }
    __syncthreads();
    if (tid < 128) {
        float v = sval[tid];
        int   c = sidx[tid];
        for (int wn = 1; wn < 4; wn++)
            upd_best(v, c, sval[wn * 128 + tid], sidx[wn * 128 + tid]);
        size_t o = (size_t)(bm + tid) * 32 + blockIdx.x;
        pv[o] = v;
        pi[o] = c;
    }
#undef FILL_STAGE_D
}

__global__ void argmin_final_kernel(const float* __restrict__ pv,
                                    const int* __restrict__ pi)
{
    int r = blockIdx.x * blockDim.x + threadIdx.x;
    if (r >= B_) return;
    float bv = INFINITY;
    int   bi = 0x7fffffff;
    for (int cb = 0; cb < 32; cb++)
        upd_best(bv, bi, pv[(size_t)r * 32 + cb], pi[(size_t)r * 32 + cb]);
    g_idx[r] = bi;
}

// ================= prep kernels (all fp16 splits now) ========================
__global__ void wsplit_h_kernel(const float* __restrict__ B, int K, int N,
                                uint32_t* __restrict__ Oh, uint32_t* __restrict__ Ol)
{
    __shared__ float t[64][33];
    const int n0 = blockIdx.x * 32;
    const int k0 = blockIdx.y * 64;
    const int tid = threadIdx.x;
#pragma unroll
    for (int i = 0; i < 8; i++) {
        int idx = tid + i * 256;
        int kk = idx >> 5, nn = idx & 31;
        t[kk][nn] = B[(size_t)(k0 + kk) * N + n0 + nn];
    }
    __syncthreads();
    const int Kp = K >> 1;
#pragma unroll
    for (int i = 0; i < 4; i++) {
        int idx = tid + i * 256;
        int nn = idx >> 5, kp = idx & 31;
        float x0 = t[2 * kp][nn], x1 = t[2 * kp + 1][nn];
        size_t o = (size_t)(n0 + nn) * Kp + (k0 >> 1) + kp;
        Oh[o] = split_pair_hi_hf(x0, x1);
        Ol[o] = split_pair_lo_hf(x0, x1);
    }
}

__global__ void xsplit_kernel(const float* __restrict__ X,
                              uint32_t* __restrict__ Oh, uint32_t* __restrict__ Ol,
                              int total_pairs)
{
    int idx = blockIdx.x * blockDim.x + threadIdx.x;
    if (idx >= total_pairs) return;
    float2 v = *(const float2*)(X + 2 * (size_t)idx);
    Oh[idx] = split_pair_hi_hf(v.x, v.y);
    Ol[idx] = split_pair_lo_hf(v.x, v.y);
}

__global__ void esplit_kernel(const float* __restrict__ E,
                              uint32_t* __restrict__ Oh, uint32_t* __restrict__ Ol,
                              int total_pairs)
{
    int idx = blockIdx.x * blockDim.x + threadIdx.x;
    if (idx >= total_pairs) return;
    float2 v = *(const float2*)(E + 2 * (size_t)idx);
    float x0 = v.x * 4096.0f, x1 = v.y * 4096.0f;
    Oh[idx] = split_pair_hi_hf(x0, x1);
    Ol[idx] = split_pair_lo_hf(x0, x1);
}

// ---------------- per-row sum of squares (one warp per row) ----------------
__global__ void rowsumsq_kernel(const float* __restrict__ src,
                                float* __restrict__ out, int rows)
{
    int warp = (blockIdx.x * blockDim.x + threadIdx.x) >> 5;
    int lane = threadIdx.x & 31;
    if (warp >= rows) return;
    const float* p = src + (size_t)warp * LAT;
    float s = 0.0f;
#pragma unroll
    for (int i = 0; i < LAT; i += 32) {
        float v = p[i + lane];
        s = fmaf(v, v, s);
    }
#pragma unroll
    for (int o = 16; o; o >>= 1) s += __shfl_down_sync(0xffffffffu, s, o);
    if (lane == 0) out[warp] = s;
}

// ---------------- gather z_q (fp16 split of 4096*zq), loss, indices --------
__global__ void gather_loss_kernel(const float* __restrict__ embed,
                                   float* __restrict__ out_f, int write_extra)
{
    int warp = (blockIdx.x * blockDim.x + threadIdx.x) >> 5;
    int lane = threadIdx.x & 31;
    if (warp >= B_) return;
    int idx = g_idx[warp];
    const float* ze = g_ze + (size_t)warp * LAT;
    const float* eq = embed + (size_t)idx * LAT;
    float s = 0.0f;
#pragma unroll
    for (int i = 0; i < LAT; i += 32) {
        float q = eq[i + lane];
        float z = ze[i + lane];
        float d = z - q;
        s = fmaf(d, d, s);
    }
#pragma unroll
    for (int o = 16; o; o >>= 1) s += __shfl_down_sync(0xffffffffu, s, o);
#pragma unroll
    for (int m = 0; m < LAT / 2; m += 32) {
        int kp = m + lane;
        float q0 = eq[2 * kp] * 4096.0f, q1 = eq[2 * kp + 1] * 4096.0f;
        g_zqh[(size_t)warp * (LAT / 2) + kp] = split_pair_hi_hf(q0, q1);
        g_zql[(size_t)warp * (LAT / 2) + kp] = split_pair_lo_hf(q0, q1);
    }
    if (lane == 0) {
        g_rowloss[warp] = s;
        if (write_extra)
            out_f[(size_t)B_ * DIN + 1 + warp] = (float)idx;
    }
}

// ---------------- final loss reduction --------------------------------------
__global__ void loss_final_kernel(float* __restrict__ out_f, int write_extra)
{
    __shared__ float sh[256];
    float s = 0.0f;
    for (int i = threadIdx.x; i < B_; i += 256) s += g_rowloss[i];
    sh[threadIdx.x] = s;
    __syncthreads();
    for (int o = 128; o; o >>= 1) {
        if (threadIdx.x < o) sh[threadIdx.x] += sh[threadIdx.x + o];
        __syncthreads();
    }
    if (threadIdx.x == 0 && write_extra) {
        out_f[(size_t)B_ * DIN] = 1.25f * sh[0] / (float)((size_t)B_ * LAT);
    }
}

// ---------------- launch ----------------------------------------------------
extern "C" void kernel_launch(void* const* d_in, const int* in_sizes, int n_in,
                              void* d_out, int out_size)
{
    const float* x     = (const float*)d_in[0];
    const float* W1    = (const float*)d_in[1];
    const float* b1    = (const float*)d_in[2];
    const float* W2    = (const float*)d_in[3];
    const float* b2    = (const float*)d_in[4];
    const float* W3    = (const float*)d_in[5];
    const float* b3    = (const float*)d_in[6];
    const float* embed = (const float*)d_in[7];
    const float* D1    = (const float*)d_in[8];
    const float* d1    = (const float*)d_in[9];
    const float* D2    = (const float*)d_in[10];
    const float* d2    = (const float*)d_in[11];
    const float* D3    = (const float*)d_in[12];
    const float* d3    = (const float*)d_in[13];
    float* out = (float*)d_out;

    float *h1, *h2, *ze, *zsq, *esq, *pv;
    int *pi;
    uint32_t *zqh, *zql, *d1h, *d1l, *d2h, *d2l, *d3h, *d3l;
    uint32_t *xh, *xl, *w1h, *w1l, *w2h, *w2l, *w3h, *w3l;
    uint32_t *zeh, *zel, *eh, *el;
    cudaGetSymbolAddress((void**)&h1,  g_h1);
    cudaGetSymbolAddress((void**)&h2,  g_h2);
    cudaGetSymbolAddress((void**)&ze,  g_ze);
    cudaGetSymbolAddress((void**)&zsq, g_zsq);
    cudaGetSymbolAddress((void**)&esq, g_esq);
    cudaGetSymbolAddress((void**)&zqh, g_zqh);
    cudaGetSymbolAddress((void**)&zql, g_zql);
    cudaGetSymbolAddress((void**)&d1h, g_d1h);
    cudaGetSymbolAddress((void**)&d1l, g_d1l);
    cudaGetSymbolAddress((void**)&d2h, g_d2h);
    cudaGetSymbolAddress((void**)&d2l, g_d2l);
    cudaGetSymbolAddress((void**)&d3h, g_d3h);
    cudaGetSymbolAddress((void**)&d3l, g_d3l);
    cudaGetSymbolAddress((void**)&xh,  g_xh);
    cudaGetSymbolAddress((void**)&xl,  g_xl);
    cudaGetSymbolAddress((void**)&w1h, g_w1h);
    cudaGetSymbolAddress((void**)&w1l, g_w1l);
    cudaGetSymbolAddress((void**)&w2h, g_w2h);
    cudaGetSymbolAddress((void**)&w2l, g_w2l);
    cudaGetSymbolAddress((void**)&w3h, g_w3h);
    cudaGetSymbolAddress((void**)&w3l, g_w3l);
    cudaGetSymbolAddress((void**)&zeh, g_zeh);
    cudaGetSymbolAddress((void**)&zel, g_zel);
    cudaGetSymbolAddress((void**)&eh,  g_eh);
    cudaGetSymbolAddress((void**)&el,  g_el);
    cudaGetSymbolAddress((void**)&pv,  g_pv);
    cudaGetSymbolAddress((void**)&pi,  g_pi);

    uint32_t* h1h = (uint32_t*)h1;
    uint32_t* h1l = h1h + (size_t)B_ * (HID / 2);
    uint32_t* h2h = (uint32_t*)h2;
    uint32_t* h2l = h2h + (size_t)B_ * (HID / 2);

    const int write_extra =
        ((size_t)out_size >= (size_t)B_ * DIN + 1 + B_) ? 1 : 0;

    cudaFuncSetAttribute(mmaps_gemm<1, 3, 0>,
                         cudaFuncAttributeMaxDynamicSharedMemorySize, PIPE_SMEM);
    cudaFuncSetAttribute(mmaps_gemm<2, 3, 0>,
                         cudaFuncAttributeMaxDynamicSharedMemorySize, PIPE_SMEM);
    cudaFuncSetAttribute(mmaps_gemm<1, 2, 1>,
                         cudaFuncAttributeMaxDynamicSharedMemorySize, PIPE_SMEM);
    cudaFuncSetAttribute(mmaps_gemm<1, 2, 0>,
                         cudaFuncAttributeMaxDynamicSharedMemorySize, PIPE_SMEM);
    cudaFuncSetAttribute(mmaps_gemm<0, 2, 0>,
                         cudaFuncAttributeMaxDynamicSharedMemorySize, PIPE_SMEM);
    cudaFuncSetAttribute(dist_mma_kernel,
                         cudaFuncAttributeMaxDynamicSharedMemorySize, PIPE_SMEM);

    // presplit (all fp16)
    xsplit_kernel<<<(B_ * (DIN / 2)) / 256, 256>>>(x, xh, xl, B_ * (DIN / 2));
    wsplit_h_kernel<<<dim3(HID / 32, DIN / 64), 256>>>(W1, DIN, HID, w1h, w1l);
    wsplit_h_kernel<<<dim3(HID / 32, HID / 64), 256>>>(W2, HID, HID, w2h, w2l);
    wsplit_h_kernel<<<dim3(LAT / 32, HID / 64), 256>>>(W3, HID, LAT, w3h, w3l);
    wsplit_h_kernel<<<dim3(HID / 32, LAT / 64), 256>>>(D1, LAT, HID, d1h, d1l);
    wsplit_h_kernel<<<dim3(HID / 32, HID / 64), 256>>>(D2, HID, HID, d2h, d2l);
    wsplit_h_kernel<<<dim3(DIN / 32, HID / 64), 256>>>(D3, HID, DIN, d3h, d3l);
    esplit_kernel<<<(KC * (LAT / 2)) / 256, 256>>>(embed, eh, el, KC * (LAT / 2));
    rowsumsq_kernel<<<(KC * 32) / 256, 256>>>(embed, esq, KC);

    // encoder — fp16 2-way-split 3-term MMA (flip-free)
    {
        dim3 g(HID / 128, B_ / 128);
        mmaps_gemm<1, 3, 0><<<g, 256, PIPE_SMEM>>>(xh, xl, w1h, w1l, b1, nullptr,
                                                   h1h, h1l, B_, HID, DIN);
    }
    {
        dim3 g(HID / 128, B_ / 128);
        mmaps_gemm<1, 3, 0><<<g, 256, PIPE_SMEM>>>(h1h, h1l, w2h, w2l, b2, nullptr,
                                                   h2h, h2l, B_, HID, HID);
    }
    {
        dim3 g(LAT / 128, B_ / 128);
        mmaps_gemm<2, 3, 0><<<g, 256, PIPE_SMEM>>>(h2h, h2l, w3h, w3l, b3, ze,
                                                   zeh, zel, B_, LAT, HID);
    }

    // zsq on z_e (reference-rounded criterion)
    rowsumsq_kernel<<<(B_ * 32) / 256, 256>>>(ze, zsq, B_);

    // dist + argmin — fp16-split 3-term MMA, reference criterion
    {
        dim3 g(KC / 128, B_ / 128);
        dist_mma_kernel<<<g, 256, PIPE_SMEM>>>(zeh, zel, eh, el, zsq, esq, pv, pi);
    }
    argmin_final_kernel<<<B_ / 256, 256>>>(pv, pi);

    // gather (+ zq fp16 split, scaled 4096) + loss
    gather_loss_kernel<<<(B_ * 32) / 256, 256>>>(embed, out, write_extra);
    loss_final_kernel<<<1, 256>>>(out, write_extra);

    // decoder — 2-term fp16 MMA (a exact-split x b-hi; ~1.4e-4 rel err)
    {
        dim3 g(HID / 128, B_ / 128);
        mmaps_gemm<1, 2, 1><<<g, 256, PIPE_SMEM>>>(zqh, zql, d1h, nullptr, d1, nullptr,
                                                   h1h, h1l, B_, HID, LAT);
    }
    {
        dim3 g(HID / 128, B_ / 128);
        mmaps_gemm<1, 2, 0><<<g, 256, PIPE_SMEM>>>(h1h, h1l, d2h, nullptr, d2, nullptr,
                                                   h2h, h2l, B_, HID, HID);
    }
    {
        dim3 g(DIN / 128, B_ / 128);
        mmaps_gemm<0, 2, 0><<<g, 256, PIPE_SMEM>>>(h2h, h2l, d3h, nullptr, d3, out,
                                                   nullptr, nullptr, B_, DIN, HID);
    }
}

// round 17
// speedup vs baseline: 2.8539x; 1.1202x over previous
#include <cuda_runtime.h>
#include <cuda_bf16.h>
#include <cuda_fp16.h>
#include <math.h>
#include <stdint.h>

#define B_   8192
#define DIN  1024
#define HID  2048
#define LAT  256
#define KC   4096

typedef unsigned long long ull;

// ---------------- scratch (device globals; no allocation allowed) ----------
__device__ __align__(128) float g_h1[(size_t)B_ * HID];
__device__ __align__(128) float g_h2[(size_t)B_ * HID];
__device__ __align__(128) float g_ze[(size_t)B_ * LAT];
__device__ float g_zsq[B_];
__device__ float g_esq[KC];
__device__ float g_rowloss[B_];
__device__ int   g_idx[B_];
// decoder presplit (fp16x2 k-pairs; zq scaled by 4096)
__device__ __align__(128) uint32_t g_zqh[(size_t)B_ * (LAT/2)];
__device__ __align__(128) uint32_t g_zql[(size_t)B_ * (LAT/2)];
__device__ __align__(128) uint32_t g_d1h[(size_t)HID * (LAT/2)];
__device__ __align__(128) uint32_t g_d1l[(size_t)HID * (LAT/2)];
__device__ __align__(128) uint32_t g_d2h[(size_t)HID * (HID/2)];
__device__ __align__(128) uint32_t g_d2l[(size_t)HID * (HID/2)];
__device__ __align__(128) uint32_t g_d3h[(size_t)DIN * (HID/2)];
__device__ __align__(128) uint32_t g_d3l[(size_t)DIN * (HID/2)];
// encoder presplit (fp16x2 k-pairs)
__device__ __align__(128) uint32_t g_xh[(size_t)B_ * (DIN/2)];
__device__ __align__(128) uint32_t g_xl[(size_t)B_ * (DIN/2)];
__device__ __align__(128) uint32_t g_w1h[(size_t)HID * (DIN/2)];
__device__ __align__(128) uint32_t g_w1l[(size_t)HID * (DIN/2)];
__device__ __align__(128) uint32_t g_w2h[(size_t)HID * (HID/2)];
__device__ __align__(128) uint32_t g_w2l[(size_t)HID * (HID/2)];
__device__ __align__(128) uint32_t g_w3h[(size_t)LAT * (HID/2)];
__device__ __align__(128) uint32_t g_w3l[(size_t)LAT * (HID/2)];
// dist path (fp16 splits; embed scaled by 4096)
__device__ __align__(128) uint32_t g_zeh[(size_t)B_ * (LAT/2)];
__device__ __align__(128) uint32_t g_zel[(size_t)B_ * (LAT/2)];
__device__ __align__(128) uint32_t g_eh[(size_t)KC * (LAT/2)];
__device__ __align__(128) uint32_t g_el[(size_t)KC * (LAT/2)];
__device__ float g_pv[(size_t)B_ * 32];
__device__ int   g_pi[(size_t)B_ * 32];

__device__ __forceinline__ float gelu_exact(float x) {
    return 0.5f * x * (1.0f + erff(x * 0.7071067811865476f));
}

// ---- fp16 split ----
__device__ __forceinline__ uint32_t pack2hf(__half a, __half b) {
    __half2 v = __halves2half2(a, b);
    return *reinterpret_cast<uint32_t*>(&v);
}
__device__ __forceinline__ void split_hf(float x, __half& h, __half& l) {
    h = __float2half_rn(x);
    l = __float2half_rn(x - __half2float(h));
}
__device__ __forceinline__ uint32_t split_pair_hi_hf(float x0, float x1) {
    __half h0, l0, h1, l1;
    split_hf(x0, h0, l0); split_hf(x1, h1, l1);
    return pack2hf(h0, h1);
}
__device__ __forceinline__ uint32_t split_pair_lo_hf(float x0, float x1) {
    __half h0, l0, h1, l1;
    split_hf(x0, h0, l0); split_hf(x1, h1, l1);
    return pack2hf(l0, l1);
}

// ---- warp MMA (fp16) ----
__device__ __forceinline__ void mma16h(float* d, const uint32_t* a, const uint32_t* b) {
    asm("mma.sync.aligned.m16n8k16.row.col.f32.f16.f16.f32 "
        "{%0,%1,%2,%3}, {%4,%5,%6,%7}, {%8,%9}, {%0,%1,%2,%3};"
        : "+f"(d[0]), "+f"(d[1]), "+f"(d[2]), "+f"(d[3])
        : "r"(a[0]), "r"(a[1]), "r"(a[2]), "r"(a[3]), "r"(b[0]), "r"(b[1]));
}

// ---- ldmatrix x4 (4 fragments / instruction) ----
__device__ __forceinline__ void ldsm4(uint32_t* r, uint32_t addr) {
    asm volatile("ldmatrix.sync.aligned.m8n8.x4.shared.b16 {%0,%1,%2,%3}, [%4];"
        : "=r"(r[0]), "=r"(r[1]), "=r"(r[2]), "=r"(r[3]) : "r"(addr));
}

__device__ __forceinline__ void upd_best(float& bv, int& bi, float v, int c) {
    if (v < bv || (v == bv && c < bi)) { bv = v; bi = c; }
}

// ---- cp.async helpers ----
__device__ __forceinline__ void cp16(uint32_t smem_dst, const void* gmem_src) {
    asm volatile("cp.async.cg.shared.global [%0], [%1], 16;"
                 :: "r"(smem_dst), "l"(gmem_src));
}
#define CP_COMMIT() asm volatile("cp.async.commit_group;" ::: "memory")
#define CP_WAIT1()  asm volatile("cp.async.wait_group 1;" ::: "memory")
#define CP_WAIT0()  asm volatile("cp.async.wait_group 0;" ::: "memory")

// ================= 3-stage pipelined presplit fp16 MMA GEMM =================
// XOR-swizzled smem (row stride 16 u32): e of row r -> r*16 + ((e>>2)^((r>>1)&3))*4 + (e&3)
// Fragment loads via ldmatrix.x4 (lane addrs bake in the swizzle; identical values).
// TERMS=3: al*bh + ah*bl + ah*bh. TERMS=2: a*bh (decoder; skips Bl).
// MODE 0: fp32 out. MODE 1: gelu + fp16 split out. MODE 2: fp32 + fp16 split out.
// SCALE 1: acc *= 2^-12 before bias.
#define ST_A_HI 0
#define ST_A_LO 2048
#define ST_B_HI 4096
#define ST_B_LO 6144
#define STAGE_U32 8192               // 32 KB
#define PIPE_SMEM (3 * STAGE_U32 * 4)   // 96 KB

template<int MODE, int TERMS, int SCALE>
__global__ void __launch_bounds__(256, 2) mmaps_gemm(
    const uint32_t* __restrict__ Ah_g, const uint32_t* __restrict__ Al_g,
    const uint32_t* __restrict__ Bh_g, const uint32_t* __restrict__ Bl_g,
    const float* __restrict__ bias, float* __restrict__ C,
    uint32_t* __restrict__ Oh, uint32_t* __restrict__ Ol,
    int M, int N, int K)
{
    extern __shared__ uint32_t smu[];
    const uint32_t sb = (uint32_t)__cvta_generic_to_shared(smu);

    const int tid  = threadIdx.x;
    const int wid  = tid >> 5;
    const int lane = tid & 31;
    const int g = lane >> 2;
    const int t = lane & 3;
    const int warp_m = wid & 1;
    const int warp_n = wid >> 1;
    const int bm = blockIdx.y * 128;
    const int bn = blockIdx.x * 128;
    const int Kp = K >> 1;

    float acc[4][4][4];
#pragma unroll
    for (int i = 0; i < 4; i++)
#pragma unroll
        for (int j = 0; j < 4; j++)
#pragma unroll
            for (int r = 0; r < 4; r++) acc[i][j][r] = 0.0f;

    // cp.async fill roles
    const int fr = tid >> 1;
    const int fo = (tid & 1) * 8;
    const int swf = (fr >> 1) & 3;
    const int cAc = (tid & 1) * 2;
    const uint32_t dchunk0 = (uint32_t)(fr * 64 + ((cAc     ^ swf) << 4));
    const uint32_t dchunk1 = (uint32_t)(fr * 64 + (((cAc+1) ^ swf) << 4));

    const uint32_t* pAh = Ah_g + (size_t)(bm + fr) * Kp + fo;
    const uint32_t* pAl = Al_g + (size_t)(bm + fr) * Kp + fo;
    const uint32_t* pBh = Bh_g + (size_t)(bn + fr) * Kp + fo;
    const uint32_t* pBl = (TERMS == 3) ? (Bl_g + (size_t)(bn + fr) * Kp + fo) : nullptr;

    // ldmatrix lane roles (addresses reproduce exact fragment values)
    const int lA_row   = (lane & 7) + ((lane >> 3) & 1) * 8;   // 0..15
    const int lA_chunk = lane >> 4;                             // 0..1
    const int lB_row   = (lane >> 4) * 8 + (lane & 7);          // within 16-row pair
    const int lB_chunk = (lane >> 3) & 1;
    int aOff[4], aSw[4];
#pragma unroll
    for (int im = 0; im < 4; im++) {
        int R = warp_m * 64 + im * 16 + lA_row;
        aOff[im] = R * 64;
        aSw[im]  = (R >> 1) & 3;
    }
    int bOff[2], bSw[2];
#pragma unroll
    for (int p = 0; p < 2; p++) {
        int R = warp_n * 32 + p * 16 + lB_row;
        bOff[p] = R * 64;
        bSw[p]  = (R >> 1) & 3;
    }

    const int nt = K / 32;

#define FILL_STAGE(sidx, koff)                                                  \
    do {                                                                        \
        const uint32_t sbase = sb + (uint32_t)((sidx) * STAGE_U32) * 4;         \
        cp16(sbase + ST_A_HI * 4 + dchunk0, pAh + (koff));                      \
        cp16(sbase + ST_A_HI * 4 + dchunk1, pAh + (koff) + 4);                  \
        cp16(sbase + ST_A_LO * 4 + dchunk0, pAl + (koff));                      \
        cp16(sbase + ST_A_LO * 4 + dchunk1, pAl + (koff) + 4);                  \
        cp16(sbase + ST_B_HI * 4 + dchunk0, pBh + (koff));                      \
        cp16(sbase + ST_B_HI * 4 + dchunk1, pBh + (koff) + 4);                  \
        if (TERMS == 3) {                                                       \
            cp16(sbase + ST_B_LO * 4 + dchunk0, pBl + (koff));                  \
            cp16(sbase + ST_B_LO * 4 + dchunk1, pBl + (koff) + 4);              \
        }                                                                       \
        CP_COMMIT();                                                            \
    } while (0)

    FILL_STAGE(0, 0);
    FILL_STAGE(1, 16);

    int stage = 0;
    for (int kt = 0; kt < nt; kt++) {
        if (kt + 1 < nt) CP_WAIT1(); else CP_WAIT0();
        __syncthreads();

        if (kt + 2 < nt) {
            int s2 = stage + 2; if (s2 >= 3) s2 -= 3;
            FILL_STAGE(s2, (kt + 2) * 16);
        }

        const uint32_t stb = sb + (uint32_t)(stage * STAGE_U32) * 4;
        const uint32_t bAh = stb + ST_A_HI * 4;
        const uint32_t bAl = stb + ST_A_LO * 4;
        const uint32_t bBh = stb + ST_B_HI * 4;
        const uint32_t bBl = stb + ST_B_LO * 4;

#pragma unroll
        for (int kk = 0; kk < 2; kk++) {
            const int c0 = kk * 2;
            uint32_t ah[4][4], al[4][4], bh[8], bl[8];
#pragma unroll
            for (int im = 0; im < 4; im++) {
                uint32_t ao = (uint32_t)(aOff[im] + (((c0 + lA_chunk) ^ aSw[im]) << 4));
                ldsm4(ah[im], bAh + ao);
                ldsm4(al[im], bAl + ao);
            }
#pragma unroll
            for (int p = 0; p < 2; p++) {
                uint32_t bo = (uint32_t)(bOff[p] + (((c0 + lB_chunk) ^ bSw[p]) << 4));
                ldsm4(&bh[p * 4], bBh + bo);
                if (TERMS == 3) ldsm4(&bl[p * 4], bBl + bo);
            }
#pragma unroll
            for (int im = 0; im < 4; im++)
#pragma unroll
                for (int jn = 0; jn < 4; jn++) {
                    mma16h(acc[im][jn], al[im], &bh[jn * 2]);
                    if (TERMS == 3)
                        mma16h(acc[im][jn], ah[im], &bl[jn * 2]);
                    mma16h(acc[im][jn], ah[im], &bh[jn * 2]);
                }
        }
        stage++; if (stage == 3) stage = 0;
    }

    // epilogue
    const float sc = SCALE ? 0.000244140625f : 1.0f;   // 2^-12 exact
#pragma unroll
    for (int im = 0; im < 4; im++) {
#pragma unroll
        for (int jn = 0; jn < 4; jn++) {
            int row = bm + warp_m * 64 + im * 16 + g;
            int col = bn + warp_n * 32 + jn * 8 + 2 * t;
            float bx = bias[col], by = bias[col + 1];
            float2 v0, v1;
            v0.x = acc[im][jn][0] * sc + bx;
            v0.y = acc[im][jn][1] * sc + by;
            v1.x = acc[im][jn][2] * sc + bx;
            v1.y = acc[im][jn][3] * sc + by;
            if (MODE == 1) {
                v0.x = gelu_exact(v0.x); v0.y = gelu_exact(v0.y);
                v1.x = gelu_exact(v1.x); v1.y = gelu_exact(v1.y);
                size_t o0 = (size_t)row * (N >> 1) + (col >> 1);
                size_t o1 = (size_t)(row + 8) * (N >> 1) + (col >> 1);
                Oh[o0] = split_pair_hi_hf(v0.x, v0.y);
                Ol[o0] = split_pair_lo_hf(v0.x, v0.y);
                Oh[o1] = split_pair_hi_hf(v1.x, v1.y);
                Ol[o1] = split_pair_lo_hf(v1.x, v1.y);
            } else if (MODE == 2) {
                *(float2*)&C[(size_t)row * N + col] = v0;
                *(float2*)&C[(size_t)(row + 8) * N + col] = v1;
                size_t o0 = (size_t)row * (N >> 1) + (col >> 1);
                size_t o1 = (size_t)(row + 8) * (N >> 1) + (col >> 1);
                Oh[o0] = split_pair_hi_hf(v0.x, v0.y);
                Ol[o0] = split_pair_lo_hf(v0.x, v0.y);
                Oh[o1] = split_pair_hi_hf(v1.x, v1.y);
                Ol[o1] = split_pair_lo_hf(v1.x, v1.y);
            } else {
                *(float2*)&C[(size_t)row * N + col] = v0;
                *(float2*)&C[(size_t)(row + 8) * N + col] = v1;
            }
        }
    }
#undef FILL_STAGE
}

// ================= dist MMA + fused argmin (3-stage, ldmatrix) ==============
__global__ void __launch_bounds__(256, 2) dist_mma_kernel(
    const uint32_t* __restrict__ Zh, const uint32_t* __restrict__ Zl,
    const uint32_t* __restrict__ Eh, const uint32_t* __restrict__ El,
    const float* __restrict__ zsq, const float* __restrict__ esq,
    float* __restrict__ pv, int* __restrict__ pi)
{
    extern __shared__ uint32_t smu[];
    const uint32_t sb = (uint32_t)__cvta_generic_to_shared(smu);

    const int tid  = threadIdx.x;
    const int wid  = tid >> 5;
    const int lane = tid & 31;
    const int g = lane >> 2;
    const int t = lane & 3;
    const int warp_m = wid & 1;
    const int warp_n = wid >> 1;
    const int bm = blockIdx.y * 128;
    const int bn = blockIdx.x * 128;
    const int Kp = LAT >> 1;

    float acc[4][4][4];
#pragma unroll
    for (int i = 0; i < 4; i++)
#pragma unroll
        for (int j = 0; j < 4; j++)
#pragma unroll
            for (int r = 0; r < 4; r++) acc[i][j][r] = 0.0f;

    const int fr = tid >> 1;
    const int fo = (tid & 1) * 8;
    const int swf = (fr >> 1) & 3;
    const int cAc = (tid & 1) * 2;
    const uint32_t dchunk0 = (uint32_t)(fr * 64 + ((cAc     ^ swf) << 4));
    const uint32_t dchunk1 = (uint32_t)(fr * 64 + (((cAc+1) ^ swf) << 4));

    const uint32_t* pAh = Zh + (size_t)(bm + fr) * Kp + fo;
    const uint32_t* pAl = Zl + (size_t)(bm + fr) * Kp + fo;
    const uint32_t* pBh = Eh + (size_t)(bn + fr) * Kp + fo;
    const uint32_t* pBl = El + (size_t)(bn + fr) * Kp + fo;

    const int lA_row   = (lane & 7) + ((lane >> 3) & 1) * 8;
    const int lA_chunk = lane >> 4;
    const int lB_row   = (lane >> 4) * 8 + (lane & 7);
    const int lB_chunk = (lane >> 3) & 1;
    int aOff[4], aSw[4];
#pragma unroll
    for (int im = 0; im < 4; im++) {
        int R = warp_m * 64 + im * 16 + lA_row;
        aOff[im] = R * 64;
        aSw[im]  = (R >> 1) & 3;
    }
    int bOff[2], bSw[2];
#pragma unroll
    for (int p = 0; p < 2; p++) {
        int R = warp_n * 32 + p * 16 + lB_row;
        bOff[p] = R * 64;
        bSw[p]  = (R >> 1) & 3;
    }

    const int nt = LAT / 32;   // 8

#define FILL_STAGE_D(sidx, koff)                                                \
    do {                                                                        \
        const uint32_t sbase = sb + (uint32_t)((sidx) * STAGE_U32) * 4;         \
        cp16(sbase + ST_A_HI * 4 + dchunk0, pAh + (koff));                      \
        cp16(sbase + ST_A_HI * 4 + dchunk1, pAh + (koff) + 4);                  \
        cp16(sbase + ST_A_LO * 4 + dchunk0, pAl + (koff));                      \
        cp16(sbase + ST_A_LO * 4 + dchunk1, pAl + (koff) + 4);                  \
        cp16(sbase + ST_B_HI * 4 + dchunk0, pBh + (koff));                      \
        cp16(sbase + ST_B_HI * 4 + dchunk1, pBh + (koff) + 4);                  \
        cp16(sbase + ST_B_LO * 4 + dchunk0, pBl + (koff));                      \
        cp16(sbase + ST_B_LO * 4 + dchunk1, pBl + (koff) + 4);                  \
        CP_COMMIT();                                                            \
    } while (0)

    FILL_STAGE_D(0, 0);
    FILL_STAGE_D(1, 16);

    int stage = 0;
    for (int kt = 0; kt < nt; kt++) {
        if (kt + 1 < nt) CP_WAIT1(); else CP_WAIT0();
        __syncthreads();

        if (kt + 2 < nt) {
            int s2 = stage + 2; if (s2 >= 3) s2 -= 3;
            FILL_STAGE_D(s2, (kt + 2) * 16);
        }

        const uint32_t stb = sb + (uint32_t)(stage * STAGE_U32) * 4;
        const uint32_t bAh = stb + ST_A_HI * 4;
        const uint32_t bAl = stb + ST_A_LO * 4;
        const uint32_t bBh = stb + ST_B_HI * 4;
        const uint32_t bBl = stb + ST_B_LO * 4;

#pragma unroll
        for (int kk = 0; kk < 2; kk++) {
            const int c0 = kk * 2;
            uint32_t ah[4][4], al[4][4], bh[8], bl[8];
#pragma unroll
            for (int im = 0; im < 4; im++) {
                uint32_t ao = (uint32_t)(aOff[im] + (((c0 + lA_chunk) ^ aSw[im]) << 4));
                ldsm4(ah[im], bAh + ao);
                ldsm4(al[im], bAl + ao);
            }
#pragma unroll
            for (int p = 0; p < 2; p++) {
                uint32_t bo = (uint32_t)(bOff[p] + (((c0 + lB_chunk) ^ bSw[p]) << 4));
                ldsm4(&bh[p * 4], bBh + bo);
                ldsm4(&bl[p * 4], bBl + bo);
            }
#pragma unroll
            for (int im = 0; im < 4; im++)
#pragma unroll
                for (int jn = 0; jn < 4; jn++) {
                    mma16h(acc[im][jn], al[im], &bh[jn * 2]);
                    mma16h(acc[im][jn], ah[im], &bl[jn * 2]);
                    mma16h(acc[im][jn], ah[im], &bh[jn * 2]);
                }
        }
        stage++; if (stage == 3) stage = 0;
    }

    // fused argmin epilogue — reference criterion with exact 2^-12 rescale
    const float inv = 0.000244140625f;
    float bv[4][2];
    int   bi[4][2];
    float zs0[4], zs1[4];
#pragma unroll
    for (int im = 0; im < 4; im++) {
        int r0 = bm + warp_m * 64 + im * 16 + g;
        zs0[im] = zsq[r0];
        zs1[im] = zsq[r0 + 8];
        bv[im][0] = INFINITY; bi[im][0] = 0x7fffffff;
        bv[im][1] = INFINITY; bi[im][1] = 0x7fffffff;
    }

#pragma unroll
    for (int im = 0; im < 4; im++) {
#pragma unroll
        for (int jn = 0; jn < 4; jn++) {
            int c0 = bn + warp_n * 32 + jn * 8 + 2 * t;
            float e0 = esq[c0], e1 = esq[c0 + 1];
            float t00 = zs0[im] + e0, t01 = zs0[im] + e1;
            float t10 = zs1[im] + e0, t11 = zs1[im] + e1;
            float d00 = fmaf(-2.0f, acc[im][jn][0] * inv, t00);
            float d01 = fmaf(-2.0f, acc[im][jn][1] * inv, t01);
            float d10 = fmaf(-2.0f, acc[im][jn][2] * inv, t10);
            float d11 = fmaf(-2.0f, acc[im][jn][3] * inv, t11);
            upd_best(bv[im][0], bi[im][0], d00, c0);
            upd_best(bv[im][0], bi[im][0], d01, c0 + 1);
            upd_best(bv[im][1], bi[im][1], d10, c0);
            upd_best(bv[im][1], bi[im][1], d11, c0 + 1);
        }
    }
#pragma unroll
    for (int im = 0; im < 4; im++)
#pragma unroll
        for (int h = 0; h < 2; h++) {
#pragma unroll
            for (int o = 2; o; o >>= 1) {
                float vv = __shfl_down_sync(0xffffffffu, bv[im][h], o, 4);
                int   cc = __shfl_down_sync(0xffffffffu, bi[im][h], o, 4);
                upd_best(bv[im][h], bi[im][h], vv, cc);
            }
        }

    float* sval = (float*)smu;
    int*   sidx = (int*)(smu + 512);
    __syncthreads();
    if (t == 0) {
#pragma unroll
        for (int im = 0; im < 4; im++)
#pragma unroll
            for (int h = 0; h < 2; h++) {
                int r = warp_m * 64 + im * 16 + g + h * 8;
                sval[warp_n * 128 + r] = bv[im][h];
                sidx[warp_n * 128 + r] = bi[im][h];
            }
    }
    __syncthreads();
    if (tid < 128) {
        float v = sval[tid];
        int   c = sidx[tid];
        for (int wn = 1; wn < 4; wn++)
            upd_best(v, c, sval[wn * 128 + tid], sidx[wn * 128 + tid]);
        size_t o = (size_t)(bm + tid) * 32 + blockIdx.x;
        pv[o] = v;
        pi[o] = c;
    }
#undef FILL_STAGE_D
}

__global__ void argmin_final_kernel(const float* __restrict__ pv,
                                    const int* __restrict__ pi)
{
    int r = blockIdx.x * blockDim.x + threadIdx.x;
    if (r >= B_) return;
    float bv = INFINITY;
    int   bi = 0x7fffffff;
    for (int cb = 0; cb < 32; cb++)
        upd_best(bv, bi, pv[(size_t)r * 32 + cb], pi[(size_t)r * 32 + cb]);
    g_idx[r] = bi;
}

// ================= prep kernels ==============================================
__global__ void wsplit_h_kernel(const float* __restrict__ B, int K, int N,
                                uint32_t* __restrict__ Oh, uint32_t* __restrict__ Ol)
{
    __shared__ float t[64][33];
    const int n0 = blockIdx.x * 32;
    const int k0 = blockIdx.y * 64;
    const int tid = threadIdx.x;
#pragma unroll
    for (int i = 0; i < 8; i++) {
        int idx = tid + i * 256;
        int kk = idx >> 5, nn = idx & 31;
        t[kk][nn] = B[(size_t)(k0 + kk) * N + n0 + nn];
    }
    __syncthreads();
    const int Kp = K >> 1;
#pragma unroll
    for (int i = 0; i < 4; i++) {
        int idx = tid + i * 256;
        int nn = idx >> 5, kp = idx & 31;
        float x0 = t[2 * kp][nn], x1 = t[2 * kp + 1][nn];
        size_t o = (size_t)(n0 + nn) * Kp + (k0 >> 1) + kp;
        Oh[o] = split_pair_hi_hf(x0, x1);
        Ol[o] = split_pair_lo_hf(x0, x1);
    }
}

__global__ void xsplit_kernel(const float* __restrict__ X,
                              uint32_t* __restrict__ Oh, uint32_t* __restrict__ Ol,
                              int total_pairs)
{
    int idx = blockIdx.x * blockDim.x + threadIdx.x;
    if (idx >= total_pairs) return;
    float2 v = *(const float2*)(X + 2 * (size_t)idx);
    Oh[idx] = split_pair_hi_hf(v.x, v.y);
    Ol[idx] = split_pair_lo_hf(v.x, v.y);
}

__global__ void esplit_kernel(const float* __restrict__ E,
                              uint32_t* __restrict__ Oh, uint32_t* __restrict__ Ol,
                              int total_pairs)
{
    int idx = blockIdx.x * blockDim.x + threadIdx.x;
    if (idx >= total_pairs) return;
    float2 v = *(const float2*)(E + 2 * (size_t)idx);
    float x0 = v.x * 4096.0f, x1 = v.y * 4096.0f;
    Oh[idx] = split_pair_hi_hf(x0, x1);
    Ol[idx] = split_pair_lo_hf(x0, x1);
}

// ---------------- per-row sum of squares (one warp per row) ----------------
__global__ void rowsumsq_kernel(const float* __restrict__ src,
                                float* __restrict__ out, int rows)
{
    int warp = (blockIdx.x * blockDim.x + threadIdx.x) >> 5;
    int lane = threadIdx.x & 31;
    if (warp >= rows) return;
    const float* p = src + (size_t)warp * LAT;
    float s = 0.0f;
#pragma unroll
    for (int i = 0; i < LAT; i += 32) {
        float v = p[i + lane];
        s = fmaf(v, v, s);
    }
#pragma unroll
    for (int o = 16; o; o >>= 1) s += __shfl_down_sync(0xffffffffu, s, o);
    if (lane == 0) out[warp] = s;
}

// ---------------- gather z_q (fp16 split of 4096*zq), loss, indices --------
__global__ void gather_loss_kernel(const float* __restrict__ embed,
                                   float* __restrict__ out_f, int write_extra)
{
    int warp = (blockIdx.x * blockDim.x + threadIdx.x) >> 5;
    int lane = threadIdx.x & 31;
    if (warp >= B_) return;
    int idx = g_idx[warp];
    const float* ze = g_ze + (size_t)warp * LAT;
    const float* eq = embed + (size_t)idx * LAT;
    float s = 0.0f;
#pragma unroll
    for (int i = 0; i < LAT; i += 32) {
        float q = eq[i + lane];
        float z = ze[i + lane];
        float d = z - q;
        s = fmaf(d, d, s);
    }
#pragma unroll
    for (int o = 16; o; o >>= 1) s += __shfl_down_sync(0xffffffffu, s, o);
#pragma unroll
    for (int m = 0; m < LAT / 2; m += 32) {
        int kp = m + lane;
        float q0 = eq[2 * kp] * 4096.0f, q1 = eq[2 * kp + 1] * 4096.0f;
        g_zqh[(size_t)warp * (LAT / 2) + kp] = split_pair_hi_hf(q0, q1);
        g_zql[(size_t)warp * (LAT / 2) + kp] = split_pair_lo_hf(q0, q1);
    }
    if (lane == 0) {
        g_rowloss[warp] = s;
        if (write_extra)
            out_f[(size_t)B_ * DIN + 1 + warp] = (float)idx;
    }
}

// ---------------- final loss reduction --------------------------------------
__global__ void loss_final_kernel(float* __restrict__ out_f, int write_extra)
{
    __shared__ float sh[256];
    float s = 0.0f;
    for (int i = threadIdx.x; i < B_; i += 256) s += g_rowloss[i];
    sh[threadIdx.x] = s;
    __syncthreads();
    for (int o = 128; o; o >>= 1) {
        if (threadIdx.x < o) sh[threadIdx.x] += sh[threadIdx.x + o];
        __syncthreads();
    }
    if (threadIdx.x == 0 && write_extra) {
        out_f[(size_t)B_ * DIN] = 1.25f * sh[0] / (float)((size_t)B_ * LAT);
    }
}

// ---------------- launch ----------------------------------------------------
extern "C" void kernel_launch(void* const* d_in, const int* in_sizes, int n_in,
                              void* d_out, int out_size)
{
    const float* x     = (const float*)d_in[0];
    const float* W1    = (const float*)d_in[1];
    const float* b1    = (const float*)d_in[2];
    const float* W2    = (const float*)d_in[3];
    const float* b2    = (const float*)d_in[4];
    const float* W3    = (const float*)d_in[5];
    const float* b3    = (const float*)d_in[6];
    const float* embed = (const float*)d_in[7];
    const float* D1    = (const float*)d_in[8];
    const float* d1    = (const float*)d_in[9];
    const float* D2    = (const float*)d_in[10];
    const float* d2    = (const float*)d_in[11];
    const float* D3    = (const float*)d_in[12];
    const float* d3    = (const float*)d_in[13];
    float* out = (float*)d_out;

    float *h1, *h2, *ze, *zsq, *esq, *pv;
    int *pi;
    uint32_t *zqh, *zql, *d1h, *d1l, *d2h, *d2l, *d3h, *d3l;
    uint32_t *xh, *xl, *w1h, *w1l, *w2h, *w2l, *w3h, *w3l;
    uint32_t *zeh, *zel, *eh, *el;
    cudaGetSymbolAddress((void**)&h1,  g_h1);
    cudaGetSymbolAddress((void**)&h2,  g_h2);
    cudaGetSymbolAddress((void**)&ze,  g_ze);
    cudaGetSymbolAddress((void**)&zsq, g_zsq);
    cudaGetSymbolAddress((void**)&esq, g_esq);
    cudaGetSymbolAddress((void**)&zqh, g_zqh);
    cudaGetSymbolAddress((void**)&zql, g_zql);
    cudaGetSymbolAddress((void**)&d1h, g_d1h);
    cudaGetSymbolAddress((void**)&d1l, g_d1l);
    cudaGetSymbolAddress((void**)&d2h, g_d2h);
    cudaGetSymbolAddress((void**)&d2l, g_d2l);
    cudaGetSymbolAddress((void**)&d3h, g_d3h);
    cudaGetSymbolAddress((void**)&d3l, g_d3l);
    cudaGetSymbolAddress((void**)&xh,  g_xh);
    cudaGetSymbolAddress((void**)&xl,  g_xl);
    cudaGetSymbolAddress((void**)&w1h, g_w1h);
    cudaGetSymbolAddress((void**)&w1l, g_w1l);
    cudaGetSymbolAddress((void**)&w2h, g_w2h);
    cudaGetSymbolAddress((void**)&w2l, g_w2l);
    cudaGetSymbolAddress((void**)&w3h, g_w3h);
    cudaGetSymbolAddress((void**)&w3l, g_w3l);
    cudaGetSymbolAddress((void**)&zeh, g_zeh);
    cudaGetSymbolAddress((void**)&zel, g_zel);
    cudaGetSymbolAddress((void**)&eh,  g_eh);
    cudaGetSymbolAddress((void**)&el,  g_el);
    cudaGetSymbolAddress((void**)&pv,  g_pv);
    cudaGetSymbolAddress((void**)&pi,  g_pi);

    uint32_t* h1h = (uint32_t*)h1;
    uint32_t* h1l = h1h + (size_t)B_ * (HID / 2);
    uint32_t* h2h = (uint32_t*)h2;
    uint32_t* h2l = h2h + (size_t)B_ * (HID / 2);

    const int write_extra =
        ((size_t)out_size >= (size_t)B_ * DIN + 1 + B_) ? 1 : 0;

    cudaFuncSetAttribute(mmaps_gemm<1, 3, 0>,
                         cudaFuncAttributeMaxDynamicSharedMemorySize, PIPE_SMEM);
    cudaFuncSetAttribute(mmaps_gemm<2, 3, 0>,
                         cudaFuncAttributeMaxDynamicSharedMemorySize, PIPE_SMEM);
    cudaFuncSetAttribute(mmaps_gemm<1, 2, 1>,
                         cudaFuncAttributeMaxDynamicSharedMemorySize, PIPE_SMEM);
    cudaFuncSetAttribute(mmaps_gemm<1, 2, 0>,
                         cudaFuncAttributeMaxDynamicSharedMemorySize, PIPE_SMEM);
    cudaFuncSetAttribute(mmaps_gemm<0, 2, 0>,
                         cudaFuncAttributeMaxDynamicSharedMemorySize, PIPE_SMEM);
    cudaFuncSetAttribute(dist_mma_kernel,
                         cudaFuncAttributeMaxDynamicSharedMemorySize, PIPE_SMEM);

    // presplit (all fp16)
    xsplit_kernel<<<(B_ * (DIN / 2)) / 256, 256>>>(x, xh, xl, B_ * (DIN / 2));
    wsplit_h_kernel<<<dim3(HID / 32, DIN / 64), 256>>>(W1, DIN, HID, w1h, w1l);
    wsplit_h_kernel<<<dim3(HID / 32, HID / 64), 256>>>(W2, HID, HID, w2h, w2l);
    wsplit_h_kernel<<<dim3(LAT / 32, HID / 64), 256>>>(W3, HID, LAT, w3h, w3l);
    wsplit_h_kernel<<<dim3(HID / 32, LAT / 64), 256>>>(D1, LAT, HID, d1h, d1l);
    wsplit_h_kernel<<<dim3(HID / 32, HID / 64), 256>>>(D2, HID, HID, d2h, d2l);
    wsplit_h_kernel<<<dim3(DIN / 32, HID / 64), 256>>>(D3, HID, DIN, d3h, d3l);
    esplit_kernel<<<(KC * (LAT / 2)) / 256, 256>>>(embed, eh, el, KC * (LAT / 2));
    rowsumsq_kernel<<<(KC * 32) / 256, 256>>>(embed, esq, KC);

    // encoder — fp16 2-way-split 3-term MMA (flip-free)
    {
        dim3 g(HID / 128, B_ / 128);
        mmaps_gemm<1, 3, 0><<<g, 256, PIPE_SMEM>>>(xh, xl, w1h, w1l, b1, nullptr,
                                                   h1h, h1l, B_, HID, DIN);
    }
    {
        dim3 g(HID / 128, B_ / 128);
        mmaps_gemm<1, 3, 0><<<g, 256, PIPE_SMEM>>>(h1h, h1l, w2h, w2l, b2, nullptr,
                                                   h2h, h2l, B_, HID, HID);
    }
    {
        dim3 g(LAT / 128, B_ / 128);
        mmaps_gemm<2, 3, 0><<<g, 256, PIPE_SMEM>>>(h2h, h2l, w3h, w3l, b3, ze,
                                                   zeh, zel, B_, LAT, HID);
    }

    // zsq on z_e (reference-rounded criterion)
    rowsumsq_kernel<<<(B_ * 32) / 256, 256>>>(ze, zsq, B_);

    // dist + argmin — fp16-split 3-term MMA, reference criterion
    {
        dim3 g(KC / 128, B_ / 128);
        dist_mma_kernel<<<g, 256, PIPE_SMEM>>>(zeh, zel, eh, el, zsq, esq, pv, pi);
    }
    argmin_final_kernel<<<B_ / 256, 256>>>(pv, pi);

    // gather (+ zq fp16 split, scaled 4096) + loss
    gather_loss_kernel<<<(B_ * 32) / 256, 256>>>(embed, out, write_extra);
    loss_final_kernel<<<1, 256>>>(out, write_extra);

    // decoder — 2-term fp16 MMA (a exact-split x b-hi)
    {
        dim3 g(HID / 128, B_ / 128);
        mmaps_gemm<1, 2, 1><<<g, 256, PIPE_SMEM>>>(zqh, zql, d1h, nullptr, d1, nullptr,
                                                   h1h, h1l, B_, HID, LAT);
    }
    {
        dim3 g(HID / 128, B_ / 128);
        mmaps_gemm<1, 2, 0><<<g, 256, PIPE_SMEM>>>(h1h, h1l, d2h, nullptr, d2, nullptr,
                                                   h2h, h2l, B_, HID, HID);
    }
    {
        dim3 g(DIN / 128, B_ / 128);
        mmaps_gemm<0, 2, 0><<<g, 256, PIPE_SMEM>>>(h2h, h2l, d3h, nullptr, d3, out,
                                                   nullptr, nullptr, B_, DIN, HID);
    }
}